// round 1
// baseline (speedup 1.0000x reference)
#include <cuda_runtime.h>
#include <cuda_bf16.h>
#include <cstdint>

#define BB    2
#define LL    4096
#define DM    1024
#define DS    16
#define DC    4
#define DI    2048
#define DTR   64
#define MM    (BB*LL)          // 8192

// ---------------- scratch (device globals; no dynamic alloc allowed) -------
__device__ float g_xn [ (size_t)MM * DM ];        // 8192x1024
__device__ float g_xz [ (size_t)MM * (2*DI) ];    // 8192x4096  (xs | z)
__device__ float g_xc [ (size_t)MM * DI ];        // 8192x2048
__device__ float g_dbl[ (size_t)MM * 96 ];        // 8192x96  (dt_lo64 | B16 | C16)
__device__ float g_dt [ (size_t)MM * DI ];        // 8192x2048
__device__ float g_y  [ (size_t)MM * DI ];        // 8192x2048

// ---------------- layernorm -----------------------------------------------
__global__ void layernorm_kernel(const float* __restrict__ x,
                                 const float* __restrict__ g,
                                 const float* __restrict__ b,
                                 float* __restrict__ o)
{
    __shared__ float red[64];
    int row = blockIdx.x;
    int t = threadIdx.x;                       // 256
    const float4* xr = (const float4*)(x + (size_t)row * DM);
    float4 v = xr[t];
    float s = v.x + v.y + v.z + v.w;
    float q = v.x*v.x + v.y*v.y + v.z*v.z + v.w*v.w;
    #pragma unroll
    for (int off = 16; off; off >>= 1) {
        s += __shfl_xor_sync(0xffffffffu, s, off);
        q += __shfl_xor_sync(0xffffffffu, q, off);
    }
    if ((t & 31) == 0) { red[t >> 5] = s; red[32 + (t >> 5)] = q; }
    __syncthreads();
    if (t < 32) {
        float s2 = (t < 8) ? red[t]      : 0.f;
        float q2 = (t < 8) ? red[32 + t] : 0.f;
        #pragma unroll
        for (int off = 4; off; off >>= 1) {
            s2 += __shfl_xor_sync(0xffffffffu, s2, off);
            q2 += __shfl_xor_sync(0xffffffffu, q2, off);
        }
        if (t == 0) { red[0] = s2; red[1] = q2; }
    }
    __syncthreads();
    float mu  = red[0] * (1.f / DM);
    float var = red[1] * (1.f / DM) - mu * mu;
    float inv = rsqrtf(var + 1e-5f);
    float4 gv = ((const float4*)g)[t];
    float4 bv = ((const float4*)b)[t];
    float4 r;
    r.x = (v.x - mu) * inv * gv.x + bv.x;
    r.y = (v.y - mu) * inv * gv.y + bv.y;
    r.z = (v.z - mu) * inv * gv.z + bv.z;
    r.w = (v.w - mu) * inv * gv.w + bv.w;
    ((float4*)(o + (size_t)row * DM))[t] = r;
}

// ---------------- generic SGEMM:  C[M,N] = A[M,K] * W[N,K]^T  --------------
// 128x128 tile, K-tile 8, 256 threads, 8x8 per thread.
__global__ __launch_bounds__(256)
void sgemm_kernel(const float* __restrict__ A, int lda,
                  const float* __restrict__ W, int ldb,
                  float* __restrict__ C, int ldc,
                  int N, int K,
                  const float* __restrict__ addsrc)
{
    __shared__ float As[8][128];
    __shared__ float Bs[8][128];
    int tid = threadIdx.x;
    int tx = tid & 15, ty = tid >> 4;
    int bm = blockIdx.y * 128, bn = blockIdx.x * 128;

    float acc[8][8];
    #pragma unroll
    for (int i = 0; i < 8; i++)
        #pragma unroll
        for (int j = 0; j < 8; j++) acc[i][j] = 0.f;

    int lrow = tid >> 1;
    int lc4  = (tid & 1) * 4;
    const float* Aptr = A + (size_t)(bm + lrow) * lda + lc4;
    const float* Bptr = W + (size_t)(bn + lrow) * ldb + lc4;
    bool bvalid = (bn + lrow) < N;

    for (int k0 = 0; k0 < K; k0 += 8) {
        float4 av = *(const float4*)(Aptr + k0);
        float4 bv = bvalid ? *(const float4*)(Bptr + k0) : make_float4(0.f,0.f,0.f,0.f);
        As[lc4+0][lrow] = av.x;  As[lc4+1][lrow] = av.y;
        As[lc4+2][lrow] = av.z;  As[lc4+3][lrow] = av.w;
        Bs[lc4+0][lrow] = bv.x;  Bs[lc4+1][lrow] = bv.y;
        Bs[lc4+2][lrow] = bv.z;  Bs[lc4+3][lrow] = bv.w;
        __syncthreads();
        #pragma unroll
        for (int kk = 0; kk < 8; kk++) {
            float a[8], bb[8];
            *(float4*)&a[0]  = *(const float4*)&As[kk][ty * 8];
            *(float4*)&a[4]  = *(const float4*)&As[kk][ty * 8 + 4];
            *(float4*)&bb[0] = *(const float4*)&Bs[kk][tx * 8];
            *(float4*)&bb[4] = *(const float4*)&Bs[kk][tx * 8 + 4];
            #pragma unroll
            for (int i = 0; i < 8; i++)
                #pragma unroll
                for (int j = 0; j < 8; j++)
                    acc[i][j] = fmaf(a[i], bb[j], acc[i][j]);
        }
        __syncthreads();
    }

    #pragma unroll
    for (int i = 0; i < 8; i++) {
        int r = bm + ty * 8 + i;
        #pragma unroll
        for (int j = 0; j < 8; j++) {
            int c = bn + tx * 8 + j;
            if (c < N) {
                float v = acc[i][j];
                if (addsrc) v += addsrc[(size_t)r * ldc + c];
                C[(size_t)r * ldc + c] = v;
            }
        }
    }
}

// ---------------- causal depthwise conv (DC=4) + silu ----------------------
__global__ void conv_silu_kernel(const float* __restrict__ xz,
                                 const float* __restrict__ cw,
                                 const float* __restrict__ cb,
                                 float* __restrict__ xc)
{
    int idx = blockIdx.x * 256 + threadIdx.x;      // over M*DI
    int d = idx & (DI - 1);
    int m = idx >> 11;
    int l = m & (LL - 1);
    const float* p = xz + (size_t)m * (2*DI) + d;  // xs part (cols 0..DI-1)
    float w0 = cw[d*4+0], w1 = cw[d*4+1], w2 = cw[d*4+2], w3 = cw[d*4+3];
    float acc = cb[d] + w3 * p[0];
    if (l >= 1) acc += w2 * p[-(2*DI)];
    if (l >= 2) acc += w1 * p[-2*(2*DI)];
    if (l >= 3) acc += w0 * p[-3*(2*DI)];
    xc[(size_t)m * DI + d] = acc / (1.f + __expf(-acc));
}

// ---------------- softplus(dt + b_dt) --------------------------------------
__global__ void softplus_kernel(float* __restrict__ dt, const float* __restrict__ bdt)
{
    int idx = blockIdx.x * 256 + threadIdx.x;
    int d = idx & (DI - 1);
    float v = dt[idx] + bdt[d];
    dt[idx] = (v > 20.f) ? v : log1pf(__expf(v));
}

// ---------------- selective scan: 16 lanes per (b,d) channel ---------------
__global__ void scan_kernel(const float* __restrict__ dt,
                            const float* __restrict__ xc,
                            const float* __restrict__ dbl,
                            const float* __restrict__ xz,
                            const float* __restrict__ A_log,
                            const float* __restrict__ Dp,
                            float* __restrict__ y)
{
    int gid = blockIdx.x * 256 + threadIdx.x;   // 65536 threads
    int c = gid >> 4;                           // channel 0..4095
    int s = gid & 15;                           // state index
    int b = c >> 11;                            // /DI
    int d = c & (DI - 1);
    float A_s = -__expf(A_log[d * DS + s]);
    float D_d = Dp[d];
    float h = 0.f;
    size_t mbase = (size_t)b * LL;
    for (int l = 0; l < LL; l++) {
        size_t m = mbase + l;
        float dtv = dt[m * DI + d];
        float xv  = xc[m * DI + d];
        float Bv  = dbl[m * 96 + DTR + s];
        float Cv  = dbl[m * 96 + DTR + DS + s];
        float a = __expf(dtv * A_s);
        h = fmaf(a, h, dtv * xv * Bv);
        float p = h * Cv;
        p += __shfl_xor_sync(0xffffffffu, p, 8);
        p += __shfl_xor_sync(0xffffffffu, p, 4);
        p += __shfl_xor_sync(0xffffffffu, p, 2);
        p += __shfl_xor_sync(0xffffffffu, p, 1);
        if (s == 0) {
            float zv = xz[m * (2*DI) + DI + d];
            float yy = p + xv * D_d;
            y[m * DI + d] = yy * (zv / (1.f + __expf(-zv)));
        }
    }
}

// ---------------- launcher -------------------------------------------------
extern "C" void kernel_launch(void* const* d_in, const int* in_sizes, int n_in,
                              void* d_out, int out_size)
{
    const float* x      = (const float*)d_in[0];
    const float* ln_g   = (const float*)d_in[1];
    const float* ln_b   = (const float*)d_in[2];
    const float* W_in   = (const float*)d_in[3];
    const float* conv_w = (const float*)d_in[4];
    const float* conv_b = (const float*)d_in[5];
    const float* W_xp   = (const float*)d_in[6];
    const float* W_dt   = (const float*)d_in[7];
    const float* b_dt   = (const float*)d_in[8];
    const float* A_log  = (const float*)d_in[9];
    const float* Dp     = (const float*)d_in[10];
    const float* W_out  = (const float*)d_in[11];
    float* out = (float*)d_out;

    float *xn, *xz, *xc, *dbl, *dtb, *yb;
    cudaGetSymbolAddress((void**)&xn,  g_xn);
    cudaGetSymbolAddress((void**)&xz,  g_xz);
    cudaGetSymbolAddress((void**)&xc,  g_xc);
    cudaGetSymbolAddress((void**)&dbl, g_dbl);
    cudaGetSymbolAddress((void**)&dtb, g_dt);
    cudaGetSymbolAddress((void**)&yb,  g_y);

    // 1. LayerNorm
    layernorm_kernel<<<MM, 256>>>(x, ln_g, ln_b, xn);
    // 2. xz = xn @ W_in^T   [8192 x 4096], K=1024
    sgemm_kernel<<<dim3(4096/128, MM/128), 256>>>(xn, DM, W_in, DM, xz, 2*DI, 2*DI, DM, nullptr);
    // 3. causal conv + silu -> xc
    conv_silu_kernel<<<(MM*DI)/256, 256>>>(xz, conv_w, conv_b, xc);
    // 4. dbl = xc @ W_xp^T  [8192 x 96], K=2048
    sgemm_kernel<<<dim3(1, MM/128), 256>>>(xc, DI, W_xp, DI, dbl, 96, 96, DI, nullptr);
    // 5. dt_raw = dt_lo @ W_dt^T  [8192 x 2048], K=64  (A = dbl cols 0..63, lda=96)
    sgemm_kernel<<<dim3(DI/128, MM/128), 256>>>(dbl, 96, W_dt, DTR, dtb, DI, DI, DTR, nullptr);
    // 6. dt = softplus(dt_raw + b_dt)
    softplus_kernel<<<(MM*DI)/256, 256>>>(dtb, b_dt);
    // 7. selective scan -> y = (scan + xc*D) * silu(z)
    scan_kernel<<<(BB*DI*DS)/256, 256>>>(dtb, xc, dbl, xz, A_log, Dp, yb);
    // 8. out = x + y @ W_out^T  [8192 x 1024], K=2048
    sgemm_kernel<<<dim3(DM/128, MM/128), 256>>>(yb, DI, W_out, DI, out, DM, DM, DI, x);
}

// round 3
// speedup vs baseline: 1.1991x; 1.1991x over previous
#include <cuda_runtime.h>
#include <cuda_bf16.h>
#include <mma.h>
#include <cstdint>

using namespace nvcuda;

#define BB    2
#define LL    4096
#define DM    1024
#define DS    16
#define DC    4
#define DI    2048
#define DTR   64
#define MM    (BB*LL)          // 8192

// ---------------- scratch (device globals; no dynamic alloc allowed) -------
__device__ float g_xn [ (size_t)MM * DM ];        // 8192x1024
__device__ float g_xz [ (size_t)MM * (2*DI) ];    // 8192x4096  (xs | z)
__device__ float g_xc [ (size_t)MM * DI ];        // 8192x2048
__device__ float g_dbl[ (size_t)MM * 96 ];        // 8192x96  (dt_lo64 | B16 | C16)
__device__ float g_dt [ (size_t)MM * DI ];        // 8192x2048
__device__ float g_y  [ (size_t)MM * DI ];        // 8192x2048

// ---------------- layernorm -----------------------------------------------
__global__ void layernorm_kernel(const float* __restrict__ x,
                                 const float* __restrict__ g,
                                 const float* __restrict__ b,
                                 float* __restrict__ o)
{
    __shared__ float red[64];
    int row = blockIdx.x;
    int t = threadIdx.x;                       // 256
    const float4* xr = (const float4*)(x + (size_t)row * DM);
    float4 v = xr[t];
    float s = v.x + v.y + v.z + v.w;
    float q = v.x*v.x + v.y*v.y + v.z*v.z + v.w*v.w;
    #pragma unroll
    for (int off = 16; off; off >>= 1) {
        s += __shfl_xor_sync(0xffffffffu, s, off);
        q += __shfl_xor_sync(0xffffffffu, q, off);
    }
    if ((t & 31) == 0) { red[t >> 5] = s; red[32 + (t >> 5)] = q; }
    __syncthreads();
    if (t < 32) {
        float s2 = (t < 8) ? red[t]      : 0.f;
        float q2 = (t < 8) ? red[32 + t] : 0.f;
        #pragma unroll
        for (int off = 4; off; off >>= 1) {
            s2 += __shfl_xor_sync(0xffffffffu, s2, off);
            q2 += __shfl_xor_sync(0xffffffffu, q2, off);
        }
        if (t == 0) { red[0] = s2; red[1] = q2; }
    }
    __syncthreads();
    float mu  = red[0] * (1.f / DM);
    float var = red[1] * (1.f / DM) - mu * mu;
    float inv = rsqrtf(var + 1e-5f);
    float4 gv = ((const float4*)g)[t];
    float4 bv = ((const float4*)b)[t];
    float4 r;
    r.x = (v.x - mu) * inv * gv.x + bv.x;
    r.y = (v.y - mu) * inv * gv.y + bv.y;
    r.z = (v.z - mu) * inv * gv.z + bv.z;
    r.w = (v.w - mu) * inv * gv.w + bv.w;
    ((float4*)(o + (size_t)row * DM))[t] = r;
}

// ---------------- TF32 wmma GEMM:  C[M,N] = A[M,K] * W[N,K]^T --------------
// Block tile BM x BN, K-tile 16, cp.async double buffer.
// Warp grid WGM x WGN; warp tile (BM/WGM) x (BN/WGN); frags 16x16x8 tf32.
// EPI: 0 = plain store, 1 = add addsrc (residual).

__device__ __forceinline__ void cp_async16(uint32_t saddr, const void* gptr) {
    asm volatile("cp.async.ca.shared.global [%0], [%1], 16;\n" :: "r"(saddr), "l"(gptr));
}

template<int BM, int BN, int WGM, int WGN, int EPI>
__global__ __launch_bounds__(WGM*WGN*32)
void tf32_gemm_kernel(const float* __restrict__ A, int lda,
                      const float* __restrict__ W, int ldb,
                      float* __restrict__ C, int ldc,
                      int N, int K,
                      const float* __restrict__ addsrc)
{
    constexpr int TM = BM / WGM;          // warp tile M
    constexpr int TN = BN / WGN;          // warp tile N
    constexpr int MF = TM / 16;
    constexpr int NF = TN / 16;
    constexpr int NT = WGM * WGN * 32;    // threads
    constexpr int TILE_FLOATS = (BM + BN) * 16;

    __shared__ alignas(128) float smem[2][TILE_FLOATS];

    int tid  = threadIdx.x;
    int wid  = tid >> 5;
    int wm   = wid / WGN;
    int wn   = wid % WGN;
    int bm   = blockIdx.y * BM;
    int bn   = blockIdx.x * BN;

    // G->S prefetch mapping: e-th float4 covers row e/4, k-quad (e%4)*4
    auto prefetch = [&](int buf, int k0) {
        uint32_t sbase = (uint32_t)__cvta_generic_to_shared(&smem[buf][0]);
        #pragma unroll
        for (int i = 0; i < (BM * 16) / (4 * NT); i++) {
            int e = i * NT + tid;
            int row = e >> 2, kq = (e & 3) * 4;
            cp_async16(sbase + (row * 16 + kq) * 4,
                       A + (size_t)(bm + row) * lda + k0 + kq);
        }
        uint32_t sbase2 = sbase + BM * 16 * 4;
        #pragma unroll
        for (int i = 0; i < (BN * 16) / (4 * NT); i++) {
            int e = i * NT + tid;
            int row = e >> 2, kq = (e & 3) * 4;
            int n = bn + row; if (n >= N) n = N - 1;   // clamp (never stored)
            cp_async16(sbase2 + (row * 16 + kq) * 4,
                       W + (size_t)n * ldb + k0 + kq);
        }
    };

    wmma::fragment<wmma::accumulator, 16, 16, 8, float> acc[MF][NF];
    #pragma unroll
    for (int i = 0; i < MF; i++)
        #pragma unroll
        for (int j = 0; j < NF; j++) wmma::fill_fragment(acc[i][j], 0.f);

    int T = K / 16;
    prefetch(0, 0);
    asm volatile("cp.async.commit_group;\n");

    for (int t = 0; t < T; t++) {
        if (t + 1 < T) {
            prefetch((t + 1) & 1, (t + 1) * 16);
            asm volatile("cp.async.commit_group;\n");
            asm volatile("cp.async.wait_group 1;\n");
        } else {
            asm volatile("cp.async.wait_group 0;\n");
        }
        __syncthreads();

        const float* As = &smem[t & 1][0];
        const float* Ws = &smem[t & 1][BM * 16];
        #pragma unroll
        for (int ks = 0; ks < 16; ks += 8) {
            wmma::fragment<wmma::matrix_a, 16, 16, 8, wmma::precision::tf32, wmma::row_major> af[MF];
            wmma::fragment<wmma::matrix_b, 16, 16, 8, wmma::precision::tf32, wmma::col_major> bf[NF];
            #pragma unroll
            for (int i = 0; i < MF; i++) {
                wmma::load_matrix_sync(af[i], As + (wm * TM + i * 16) * 16 + ks, 16);
                #pragma unroll
                for (int e = 0; e < af[i].num_elements; e++)
                    af[i].x[e] = wmma::__float_to_tf32(af[i].x[e]);
            }
            #pragma unroll
            for (int j = 0; j < NF; j++) {
                wmma::load_matrix_sync(bf[j], Ws + (wn * TN + j * 16) * 16 + ks, 16);
                #pragma unroll
                for (int e = 0; e < bf[j].num_elements; e++)
                    bf[j].x[e] = wmma::__float_to_tf32(bf[j].x[e]);
            }
            #pragma unroll
            for (int i = 0; i < MF; i++)
                #pragma unroll
                for (int j = 0; j < NF; j++)
                    wmma::mma_sync(acc[i][j], af[i], bf[j], acc[i][j]);
        }
        __syncthreads();
    }

    // epilogue
    #pragma unroll
    for (int i = 0; i < MF; i++) {
        int r0 = bm + wm * TM + i * 16;
        #pragma unroll
        for (int j = 0; j < NF; j++) {
            int c0 = bn + wn * TN + j * 16;
            if (c0 < N) {
                if (EPI == 1) {
                    wmma::fragment<wmma::accumulator, 16, 16, 8, float> cf;
                    wmma::load_matrix_sync(cf, addsrc + (size_t)r0 * ldc + c0, ldc, wmma::mem_row_major);
                    #pragma unroll
                    for (int e = 0; e < cf.num_elements; e++)
                        acc[i][j].x[e] += cf.x[e];
                }
                wmma::store_matrix_sync(C + (size_t)r0 * ldc + c0, acc[i][j], ldc, wmma::mem_row_major);
            }
        }
    }
}

// ---------------- causal depthwise conv (DC=4) + silu ----------------------
__global__ void conv_silu_kernel(const float* __restrict__ xz,
                                 const float* __restrict__ cw,
                                 const float* __restrict__ cb,
                                 float* __restrict__ xc)
{
    int idx = blockIdx.x * 256 + threadIdx.x;      // over M*DI
    int d = idx & (DI - 1);
    int m = idx >> 11;
    int l = m & (LL - 1);
    const float* p = xz + (size_t)m * (2*DI) + d;  // xs part (cols 0..DI-1)
    float w0 = cw[d*4+0], w1 = cw[d*4+1], w2 = cw[d*4+2], w3 = cw[d*4+3];
    float acc = cb[d] + w3 * p[0];
    if (l >= 1) acc += w2 * p[-(2*DI)];
    if (l >= 2) acc += w1 * p[-2*(2*DI)];
    if (l >= 3) acc += w0 * p[-3*(2*DI)];
    xc[(size_t)m * DI + d] = acc / (1.f + __expf(-acc));
}

// ---------------- softplus(dt + b_dt) --------------------------------------
__global__ void softplus_kernel(float* __restrict__ dt, const float* __restrict__ bdt)
{
    int idx = blockIdx.x * 256 + threadIdx.x;
    int d = idx & (DI - 1);
    float v = dt[idx] + bdt[d];
    dt[idx] = (v > 20.f) ? v : log1pf(__expf(v));
}

// ---------------- selective scan: 16 lanes per (b,d) channel ---------------
__global__ void scan_kernel(const float* __restrict__ dt,
                            const float* __restrict__ xc,
                            const float* __restrict__ dbl,
                            const float* __restrict__ xz,
                            const float* __restrict__ A_log,
                            const float* __restrict__ Dp,
                            float* __restrict__ y)
{
    int gid = blockIdx.x * 256 + threadIdx.x;   // 65536 threads
    int c = gid >> 4;                           // channel 0..4095
    int s = gid & 15;                           // state index
    int b = c >> 11;                            // /DI
    int d = c & (DI - 1);
    float A_s = -__expf(A_log[d * DS + s]);
    float D_d = Dp[d];
    float h = 0.f;
    size_t mbase = (size_t)b * LL;
    for (int l = 0; l < LL; l++) {
        size_t m = mbase + l;
        float dtv = dt[m * DI + d];
        float xv  = xc[m * DI + d];
        float Bv  = dbl[m * 96 + DTR + s];
        float Cv  = dbl[m * 96 + DTR + DS + s];
        float a = __expf(dtv * A_s);
        h = fmaf(a, h, dtv * xv * Bv);
        float p = h * Cv;
        p += __shfl_xor_sync(0xffffffffu, p, 8);
        p += __shfl_xor_sync(0xffffffffu, p, 4);
        p += __shfl_xor_sync(0xffffffffu, p, 2);
        p += __shfl_xor_sync(0xffffffffu, p, 1);
        if (s == 0) {
            float zv = xz[m * (2*DI) + DI + d];
            float yy = p + xv * D_d;
            y[m * DI + d] = yy * (zv / (1.f + __expf(-zv)));
        }
    }
}

// ---------------- launcher -------------------------------------------------
extern "C" void kernel_launch(void* const* d_in, const int* in_sizes, int n_in,
                              void* d_out, int out_size)
{
    const float* x      = (const float*)d_in[0];
    const float* ln_g   = (const float*)d_in[1];
    const float* ln_b   = (const float*)d_in[2];
    const float* W_in   = (const float*)d_in[3];
    const float* conv_w = (const float*)d_in[4];
    const float* conv_b = (const float*)d_in[5];
    const float* W_xp   = (const float*)d_in[6];
    const float* W_dt   = (const float*)d_in[7];
    const float* b_dt   = (const float*)d_in[8];
    const float* A_log  = (const float*)d_in[9];
    const float* Dp     = (const float*)d_in[10];
    const float* W_out  = (const float*)d_in[11];
    float* out = (float*)d_out;

    float *xn, *xz, *xc, *dbl, *dtb, *yb;
    cudaGetSymbolAddress((void**)&xn,  g_xn);
    cudaGetSymbolAddress((void**)&xz,  g_xz);
    cudaGetSymbolAddress((void**)&xc,  g_xc);
    cudaGetSymbolAddress((void**)&dbl, g_dbl);
    cudaGetSymbolAddress((void**)&dtb, g_dt);
    cudaGetSymbolAddress((void**)&yb,  g_y);

    // 1. LayerNorm
    layernorm_kernel<<<MM, 256>>>(x, ln_g, ln_b, xn);
    // 2. xz = xn @ W_in^T   [8192 x 4096], K=1024
    tf32_gemm_kernel<128,128,4,2,0><<<dim3(4096/128, MM/128), 256>>>(
        xn, DM, W_in, DM, xz, 2*DI, 2*DI, DM, nullptr);
    // 3. causal conv + silu -> xc
    conv_silu_kernel<<<(MM*DI)/256, 256>>>(xz, conv_w, conv_b, xc);
    // 4. dbl = xc @ W_xp^T  [8192 x 96], K=2048  (BM=64 -> 128 CTAs)
    tf32_gemm_kernel<64,128,2,4,0><<<dim3(1, MM/64), 256>>>(
        xc, DI, W_xp, DI, dbl, 96, 96, DI, nullptr);
    // 5. dt_raw = dt_lo @ W_dt^T  [8192 x 2048], K=64  (A = dbl cols 0..63, lda=96)
    tf32_gemm_kernel<128,128,4,2,0><<<dim3(DI/128, MM/128), 256>>>(
        dbl, 96, W_dt, DTR, dtb, DI, DI, DTR, nullptr);
    // 6. dt = softplus(dt_raw + b_dt)
    softplus_kernel<<<(MM*DI)/256, 256>>>(dtb, b_dt);
    // 7. selective scan -> y = (scan + xc*D) * silu(z)
    scan_kernel<<<(BB*DI*DS)/256, 256>>>(dtb, xc, dbl, xz, A_log, Dp, yb);
    // 8. out = x + y @ W_out^T  [8192 x 1024], K=2048
    tf32_gemm_kernel<128,128,4,2,1><<<dim3(DM/128, MM/128), 256>>>(
        yb, DI, W_out, DI, out, DM, DM, DI, x);
}

// round 4
// speedup vs baseline: 1.5359x; 1.2809x over previous
#include <cuda_runtime.h>
#include <cuda_bf16.h>
#include <mma.h>
#include <cstdint>

using namespace nvcuda;
typedef __nv_bfloat16 bf16;

#define BB    2
#define LL    4096
#define DM    1024
#define DS    16
#define DI    2048
#define DTR   64
#define MM    (BB*LL)          // 8192

// ---------------- scratch (device globals) ---------------------------------
__device__ float g_xz [ (size_t)MM * (2*DI) ];    // 8192x4096 (xs | z) fp32
__device__ float g_xc [ (size_t)MM * DI ];        // fp32 (scan)
__device__ float g_dbl[ (size_t)MM * 96 ];        // dt_lo64 | B16 | C16  fp32
__device__ float g_dt [ (size_t)MM * DI ];        // fp32
__device__ bf16  g_xnb [ (size_t)MM * DM ];       // LN out, bf16
__device__ bf16  g_xcb [ (size_t)MM * DI ];       // conv out, bf16
__device__ bf16  g_dtlo[ (size_t)MM * DTR ];      // dt_lo, bf16
__device__ bf16  g_yb  [ (size_t)MM * DI ];       // scan out, bf16
__device__ bf16  g_Winb [ (size_t)(2*DI) * DM ];
__device__ bf16  g_Wxpb [ (size_t)96 * DI ];
__device__ bf16  g_Wdtb [ (size_t)DI * DTR ];
__device__ bf16  g_Woutb[ (size_t)DM * DI ];

// ---------------- fp32 -> bf16 convert -------------------------------------
__global__ void f2bf_kernel(const float* __restrict__ src, bf16* __restrict__ dst, int n)
{
    int i = (blockIdx.x * 256 + threadIdx.x) * 4;
    if (i < n) {
        float4 v = *(const float4*)(src + i);
        __nv_bfloat162* d = (__nv_bfloat162*)(dst + i);
        d[0] = __floats2bfloat162_rn(v.x, v.y);
        d[1] = __floats2bfloat162_rn(v.z, v.w);
    }
}

// extract dt_lo (cols 0..63 of dbl, stride 96) -> bf16 [MM x 64]
__global__ void dtlo_kernel(const float* __restrict__ dbl, bf16* __restrict__ dtlo)
{
    int idx = blockIdx.x * 256 + threadIdx.x;   // over MM*64
    int m = idx >> 6, r = idx & 63;
    dtlo[idx] = __float2bfloat16(dbl[(size_t)m * 96 + r]);
}

// ---------------- layernorm -> bf16 ----------------------------------------
__global__ void layernorm_kernel(const float* __restrict__ x,
                                 const float* __restrict__ g,
                                 const float* __restrict__ b,
                                 bf16* __restrict__ o)
{
    __shared__ float red[64];
    int row = blockIdx.x;
    int t = threadIdx.x;                       // 256
    const float4* xr = (const float4*)(x + (size_t)row * DM);
    float4 v = xr[t];
    float s = v.x + v.y + v.z + v.w;
    float q = v.x*v.x + v.y*v.y + v.z*v.z + v.w*v.w;
    #pragma unroll
    for (int off = 16; off; off >>= 1) {
        s += __shfl_xor_sync(0xffffffffu, s, off);
        q += __shfl_xor_sync(0xffffffffu, q, off);
    }
    if ((t & 31) == 0) { red[t >> 5] = s; red[32 + (t >> 5)] = q; }
    __syncthreads();
    if (t < 32) {
        float s2 = (t < 8) ? red[t]      : 0.f;
        float q2 = (t < 8) ? red[32 + t] : 0.f;
        #pragma unroll
        for (int off = 4; off; off >>= 1) {
            s2 += __shfl_xor_sync(0xffffffffu, s2, off);
            q2 += __shfl_xor_sync(0xffffffffu, q2, off);
        }
        if (t == 0) { red[0] = s2; red[1] = q2; }
    }
    __syncthreads();
    float mu  = red[0] * (1.f / DM);
    float var = red[1] * (1.f / DM) - mu * mu;
    float inv = rsqrtf(var + 1e-5f);
    float4 gv = ((const float4*)g)[t];
    float4 bv = ((const float4*)b)[t];
    __nv_bfloat162* op = (__nv_bfloat162*)(o + (size_t)row * DM + t * 4);
    op[0] = __floats2bfloat162_rn((v.x - mu)*inv*gv.x + bv.x, (v.y - mu)*inv*gv.y + bv.y);
    op[1] = __floats2bfloat162_rn((v.z - mu)*inv*gv.z + bv.z, (v.w - mu)*inv*gv.w + bv.w);
}

// ---------------- bf16 wmma GEMM:  C[M,N] = A[M,K] * W[N,K]^T --------------
// BK=32, 3-stage cp.async pipeline, smem row stride 40 bf16 (conflict-free).
// EPI: 0 plain fp32 store, 1 add addsrc (residual).
__device__ __forceinline__ void cp_async16(uint32_t saddr, const void* gptr) {
    asm volatile("cp.async.cg.shared.global [%0], [%1], 16;\n" :: "r"(saddr), "l"(gptr));
}

#define STAGES 3
#define SPAD   40   // bf16 elems per 32-elem row (80B stride)

template<int BM, int BN, int WGM, int WGN, int EPI>
__global__ __launch_bounds__(WGM*WGN*32)
void hgemm_kernel(const bf16* __restrict__ A, int lda,
                  const bf16* __restrict__ W, int ldb,
                  float* __restrict__ C, int ldc,
                  int N, int K,
                  const float* __restrict__ addsrc)
{
    constexpr int TM = BM / WGM;
    constexpr int TN = BN / WGN;
    constexpr int MF = TM / 16;
    constexpr int NF = TN / 16;
    constexpr int NT = WGM * WGN * 32;
    constexpr int SSZ = (BM + BN) * SPAD;     // bf16 elems per stage

    extern __shared__ bf16 sm[];

    int tid = threadIdx.x;
    int wid = tid >> 5;
    int wm  = wid / WGN;
    int wn  = wid % WGN;
    int bm  = blockIdx.y * BM;
    int bn  = blockIdx.x * BN;

    // prefetch one K-tile (32 wide) into stage p. 16B chunk = 8 bf16.
    auto prefetch = [&](int p, int k0) {
        uint32_t sbase = (uint32_t)__cvta_generic_to_shared(sm + p * SSZ);
        #pragma unroll
        for (int i = 0; i < (BM * 4) / NT; i++) {
            int e = i * NT + tid;
            int row = e >> 2, c8 = (e & 3) * 8;
            cp_async16(sbase + (row * SPAD + c8) * 2,
                       A + (size_t)(bm + row) * lda + k0 + c8);
        }
        uint32_t sbase2 = sbase + BM * SPAD * 2;
        #pragma unroll
        for (int i = 0; i < (BN * 4) / NT; i++) {
            int e = i * NT + tid;
            int row = e >> 2, c8 = (e & 3) * 8;
            int n = bn + row; if (n >= N) n = N - 1;   // clamp (never stored)
            cp_async16(sbase2 + (row * SPAD + c8) * 2,
                       W + (size_t)n * ldb + k0 + c8);
        }
    };

    wmma::fragment<wmma::accumulator, 16, 16, 16, float> acc[MF][NF];
    #pragma unroll
    for (int i = 0; i < MF; i++)
        #pragma unroll
        for (int j = 0; j < NF; j++) wmma::fill_fragment(acc[i][j], 0.f);

    int T = K / 32;
    #pragma unroll
    for (int s = 0; s < STAGES - 1; s++) {
        if (s < T) prefetch(s, s * 32);
        asm volatile("cp.async.commit_group;\n");
    }

    for (int t = 0; t < T; t++) {
        asm volatile("cp.async.wait_group %0;\n" :: "n"(STAGES - 2));
        __syncthreads();

        int pn = t + STAGES - 1;
        if (pn < T) prefetch(pn % STAGES, pn * 32);
        asm volatile("cp.async.commit_group;\n");

        const bf16* As = sm + (t % STAGES) * SSZ;
        const bf16* Ws = As + BM * SPAD;
        #pragma unroll
        for (int ks = 0; ks < 32; ks += 16) {
            wmma::fragment<wmma::matrix_a, 16, 16, 16, bf16, wmma::row_major> af[MF];
            wmma::fragment<wmma::matrix_b, 16, 16, 16, bf16, wmma::col_major> bf[NF];
            #pragma unroll
            for (int i = 0; i < MF; i++)
                wmma::load_matrix_sync(af[i], As + (wm * TM + i * 16) * SPAD + ks, SPAD);
            #pragma unroll
            for (int j = 0; j < NF; j++)
                wmma::load_matrix_sync(bf[j], Ws + (wn * TN + j * 16) * SPAD + ks, SPAD);
            #pragma unroll
            for (int i = 0; i < MF; i++)
                #pragma unroll
                for (int j = 0; j < NF; j++)
                    wmma::mma_sync(acc[i][j], af[i], bf[j], acc[i][j]);
        }
        __syncthreads();
    }

    #pragma unroll
    for (int i = 0; i < MF; i++) {
        int r0 = bm + wm * TM + i * 16;
        #pragma unroll
        for (int j = 0; j < NF; j++) {
            int c0 = bn + wn * TN + j * 16;
            if (c0 < N) {
                if (EPI == 1) {
                    wmma::fragment<wmma::accumulator, 16, 16, 16, float> cf;
                    wmma::load_matrix_sync(cf, addsrc + (size_t)r0 * ldc + c0, ldc, wmma::mem_row_major);
                    #pragma unroll
                    for (int e = 0; e < cf.num_elements; e++)
                        acc[i][j].x[e] += cf.x[e];
                }
                wmma::store_matrix_sync(C + (size_t)r0 * ldc + c0, acc[i][j], ldc, wmma::mem_row_major);
            }
        }
    }
}

// ---------------- causal depthwise conv (DC=4) + silu ----------------------
__global__ void conv_silu_kernel(const float* __restrict__ xz,
                                 const float* __restrict__ cw,
                                 const float* __restrict__ cb,
                                 float* __restrict__ xc,
                                 bf16* __restrict__ xcb)
{
    int idx = blockIdx.x * 256 + threadIdx.x;      // over M*DI
    int d = idx & (DI - 1);
    int m = idx >> 11;
    int l = m & (LL - 1);
    const float* p = xz + (size_t)m * (2*DI) + d;
    float w0 = cw[d*4+0], w1 = cw[d*4+1], w2 = cw[d*4+2], w3 = cw[d*4+3];
    float acc = cb[d] + w3 * p[0];
    if (l >= 1) acc += w2 * p[-(2*DI)];
    if (l >= 2) acc += w1 * p[-2*(2*DI)];
    if (l >= 3) acc += w0 * p[-3*(2*DI)];
    float r = acc / (1.f + __expf(-acc));
    xc[(size_t)m * DI + d] = r;
    xcb[(size_t)m * DI + d] = __float2bfloat16(r);
}

// ---------------- softplus(dt + b_dt) --------------------------------------
__global__ void softplus_kernel(float* __restrict__ dt, const float* __restrict__ bdt)
{
    int idx = blockIdx.x * 256 + threadIdx.x;
    int d = idx & (DI - 1);
    float v = dt[idx] + bdt[d];
    dt[idx] = (v > 20.f) ? v : log1pf(__expf(v));
}

// ---------------- selective scan: 16 lanes per (b,d) channel ---------------
__global__ void scan_kernel(const float* __restrict__ dt,
                            const float* __restrict__ xc,
                            const float* __restrict__ dbl,
                            const float* __restrict__ xz,
                            const float* __restrict__ A_log,
                            const float* __restrict__ Dp,
                            bf16* __restrict__ y)
{
    int gid = blockIdx.x * 256 + threadIdx.x;   // 65536 threads
    int c = gid >> 4;                           // channel 0..4095
    int s = gid & 15;                           // state index
    int b = c >> 11;
    int d = c & (DI - 1);
    float A_s = -__expf(A_log[d * DS + s]);
    float D_d = Dp[d];
    float h = 0.f;
    size_t mbase = (size_t)b * LL;
    for (int l = 0; l < LL; l++) {
        size_t m = mbase + l;
        float dtv = dt[m * DI + d];
        float xv  = xc[m * DI + d];
        float Bv  = dbl[m * 96 + DTR + s];
        float Cv  = dbl[m * 96 + DTR + DS + s];
        float a = __expf(dtv * A_s);
        h = fmaf(a, h, dtv * xv * Bv);
        float p = h * Cv;
        p += __shfl_xor_sync(0xffffffffu, p, 8);
        p += __shfl_xor_sync(0xffffffffu, p, 4);
        p += __shfl_xor_sync(0xffffffffu, p, 2);
        p += __shfl_xor_sync(0xffffffffu, p, 1);
        if (s == 0) {
            float zv = xz[m * (2*DI) + DI + d];
            float yy = p + xv * D_d;
            y[m * DI + d] = __float2bfloat16(yy * (zv / (1.f + __expf(-zv))));
        }
    }
}

// ---------------- launcher -------------------------------------------------
extern "C" void kernel_launch(void* const* d_in, const int* in_sizes, int n_in,
                              void* d_out, int out_size)
{
    const float* x      = (const float*)d_in[0];
    const float* ln_g   = (const float*)d_in[1];
    const float* ln_b   = (const float*)d_in[2];
    const float* W_in   = (const float*)d_in[3];
    const float* conv_w = (const float*)d_in[4];
    const float* conv_b = (const float*)d_in[5];
    const float* W_xp   = (const float*)d_in[6];
    const float* W_dt   = (const float*)d_in[7];
    const float* b_dt   = (const float*)d_in[8];
    const float* A_log  = (const float*)d_in[9];
    const float* Dp     = (const float*)d_in[10];
    const float* W_out  = (const float*)d_in[11];
    float* out = (float*)d_out;

    float *xz, *xc, *dbl, *dtb;
    bf16 *xnb, *xcb, *dtlo, *yb, *Winb, *Wxpb, *Wdtb, *Woutb;
    cudaGetSymbolAddress((void**)&xz,   g_xz);
    cudaGetSymbolAddress((void**)&xc,   g_xc);
    cudaGetSymbolAddress((void**)&dbl,  g_dbl);
    cudaGetSymbolAddress((void**)&dtb,  g_dt);
    cudaGetSymbolAddress((void**)&xnb,  g_xnb);
    cudaGetSymbolAddress((void**)&xcb,  g_xcb);
    cudaGetSymbolAddress((void**)&dtlo, g_dtlo);
    cudaGetSymbolAddress((void**)&yb,   g_yb);
    cudaGetSymbolAddress((void**)&Winb, g_Winb);
    cudaGetSymbolAddress((void**)&Wxpb, g_Wxpb);
    cudaGetSymbolAddress((void**)&Wdtb, g_Wdtb);
    cudaGetSymbolAddress((void**)&Woutb,g_Woutb);

    // opt-in smem (idempotent)
    constexpr int SM_128 = (128 + 128) * SPAD * 2 * STAGES;   // 61440
    constexpr int SM_64  = (64 + 128) * SPAD * 2 * STAGES;    // 46080
    cudaFuncSetAttribute(hgemm_kernel<128,128,4,2,0>, cudaFuncAttributeMaxDynamicSharedMemorySize, SM_128);
    cudaFuncSetAttribute(hgemm_kernel<128,128,4,2,1>, cudaFuncAttributeMaxDynamicSharedMemorySize, SM_128);
    cudaFuncSetAttribute(hgemm_kernel<64,128,2,4,0>,  cudaFuncAttributeMaxDynamicSharedMemorySize, SM_64);

    // 0. weight conversions (fp32 -> bf16)
    f2bf_kernel<<<((2*DI*DM)/4 + 255)/256, 256>>>(W_in,  Winb, 2*DI*DM);
    f2bf_kernel<<<((96*DI)/4 + 255)/256, 256>>>(W_xp,  Wxpb, 96*DI);
    f2bf_kernel<<<((DI*DTR)/4 + 255)/256, 256>>>(W_dt,  Wdtb, DI*DTR);
    f2bf_kernel<<<((DM*DI)/4 + 255)/256, 256>>>(W_out, Woutb, DM*DI);

    // 1. LayerNorm -> bf16
    layernorm_kernel<<<MM, 256>>>(x, ln_g, ln_b, xnb);
    // 2. xz = xn @ W_in^T   [8192 x 4096], K=1024
    hgemm_kernel<128,128,4,2,0><<<dim3(4096/128, MM/128), 256, SM_128>>>(
        xnb, DM, Winb, DM, xz, 2*DI, 2*DI, DM, nullptr);
    // 3. causal conv + silu -> xc (fp32 + bf16)
    conv_silu_kernel<<<(MM*DI)/256, 256>>>(xz, conv_w, conv_b, xc, xcb);
    // 4. dbl = xc @ W_xp^T  [8192 x 96], K=2048
    hgemm_kernel<64,128,2,4,0><<<dim3(1, MM/64), 256, SM_64>>>(
        xcb, DI, Wxpb, DI, dbl, 96, 96, DI, nullptr);
    // 4b. dt_lo -> bf16 compact
    dtlo_kernel<<<(MM*DTR)/256, 256>>>(dbl, dtlo);
    // 5. dt_raw = dt_lo @ W_dt^T  [8192 x 2048], K=64
    hgemm_kernel<128,128,4,2,0><<<dim3(DI/128, MM/128), 256, SM_128>>>(
        dtlo, DTR, Wdtb, DTR, dtb, DI, DI, DTR, nullptr);
    // 6. dt = softplus(dt_raw + b_dt)
    softplus_kernel<<<(MM*DI)/256, 256>>>(dtb, b_dt);
    // 7. selective scan -> y bf16
    scan_kernel<<<(BB*DI*DS)/256, 256>>>(dtb, xc, dbl, xz, A_log, Dp, yb);
    // 8. out = x + y @ W_out^T  [8192 x 1024], K=2048
    hgemm_kernel<128,128,4,2,1><<<dim3(DM/128, MM/128), 256, SM_128>>>(
        yb, DI, Woutb, DI, out, DM, DM, DI, x);
}

// round 6
// speedup vs baseline: 1.5417x; 1.0038x over previous
#include <cuda_runtime.h>
#include <cuda_bf16.h>
#include <mma.h>
#include <cstdint>

using namespace nvcuda;
typedef __nv_bfloat16 bf16;

#define BB    2
#define LL    4096
#define DM    1024
#define DS    16
#define DI    2048
#define DTR   64
#define MM    (BB*LL)          // 8192

// ---------------- scratch (device globals) ---------------------------------
__device__ float g_xz [ (size_t)MM * (2*DI) ];    // 8192x4096 (xs | z) fp32
__device__ float g_xc [ (size_t)MM * DI ];        // fp32 (scan)
__device__ float g_dbl[ (size_t)MM * 96 ];        // dt_lo64 | B16 | C16  fp32
__device__ float g_dt [ (size_t)MM * DI ];        // fp32
__device__ bf16  g_xnb [ (size_t)MM * DM ];       // LN out, bf16
__device__ bf16  g_xcb [ (size_t)MM * DI ];       // conv out, bf16
__device__ bf16  g_dtlo[ (size_t)MM * DTR ];      // dt_lo, bf16
__device__ bf16  g_yb  [ (size_t)MM * DI ];       // scan out, bf16
__device__ bf16  g_Winb [ (size_t)(2*DI) * DM ];
__device__ bf16  g_Wxpb [ (size_t)96 * DI ];
__device__ bf16  g_Wdtb [ (size_t)DI * DTR ];
__device__ bf16  g_Woutb[ (size_t)DM * DI ];

// ======================= helpers ============================================
__device__ __forceinline__ void cp_async16(uint32_t saddr, const void* gptr) {
    asm volatile("cp.async.cg.shared.global [%0], [%1], 16;\n" :: "r"(saddr), "l"(gptr));
}
__device__ __forceinline__ void ldsm_x4(uint32_t* r, uint32_t addr) {
    asm volatile("ldmatrix.sync.aligned.m8n8.x4.shared.b16 {%0,%1,%2,%3}, [%4];"
        : "=r"(r[0]), "=r"(r[1]), "=r"(r[2]), "=r"(r[3]) : "r"(addr));
}
__device__ __forceinline__ void mma16816(float* d, const uint32_t* a, uint32_t b0, uint32_t b1) {
    asm volatile("mma.sync.aligned.m16n8k16.row.col.f32.bf16.bf16.f32 "
        "{%0,%1,%2,%3}, {%4,%5,%6,%7}, {%8,%9}, {%0,%1,%2,%3};"
        : "+f"(d[0]), "+f"(d[1]), "+f"(d[2]), "+f"(d[3])
        : "r"(a[0]), "r"(a[1]), "r"(a[2]), "r"(a[3]), "r"(b0), "r"(b1));
}

// ======================= mma.sync GEMM ======================================
//  C[M,N] = A[M,K] * W[N,K]^T   (bf16 in, fp32 out)
//  CTA 128x256, BK=32, 4-stage cp.async, warp tile 64x64 (2x4 warp grid).
//  EPI: 0 plain, 1 +aux residual (row-major MxN), 2 softplus(v + aux[col]).
template<int EPI>
__global__ __launch_bounds__(256)
void mma_gemm_kernel(const bf16* __restrict__ A, int lda,
                     const bf16* __restrict__ W, int ldb,
                     float* __restrict__ C, int ldc,
                     int K, const float* __restrict__ aux)
{
    constexpr int BM = 128, BN = 256, BK = 32, NS = 4, SP = 40;
    constexpr int ASZ = BM * SP;        // bf16 elems
    constexpr int BSZ = BN * SP;
    constexpr int SSZ = ASZ + BSZ;      // 15360 elems = 30720 B / stage

    extern __shared__ bf16 sm2[];
    const int tid  = threadIdx.x;
    const int lane = tid & 31;
    const int wid  = tid >> 5;
    const int wm   = wid >> 2;          // 0..1
    const int wn   = wid & 3;           // 0..3
    const int bm   = blockIdx.y * BM;
    const int bn   = blockIdx.x * BN;

    auto prefetch = [&](int s, int kt) {
        const int k0 = kt * BK;
        uint32_t base = (uint32_t)__cvta_generic_to_shared(sm2 + s * SSZ);
        #pragma unroll
        for (int i = 0; i < 2; i++) {               // A: 512 x 16B
            int e = i * 256 + tid;
            int r = e >> 2, c = e & 3;
            cp_async16(base + (r * SP + c * 8) * 2,
                       A + (size_t)(bm + r) * lda + k0 + c * 8);
        }
        uint32_t baseB = base + ASZ * 2;
        #pragma unroll
        for (int i = 0; i < 4; i++) {               // B: 1024 x 16B
            int e = i * 256 + tid;
            int r = e >> 2, c = e & 3;
            cp_async16(baseB + (r * SP + c * 8) * 2,
                       W + (size_t)(bn + r) * ldb + k0 + c * 8);
        }
    };

    float acc[4][8][4];
    #pragma unroll
    for (int i = 0; i < 4; i++)
        #pragma unroll
        for (int j = 0; j < 8; j++)
            #pragma unroll
            for (int e = 0; e < 4; e++) acc[i][j][e] = 0.f;

    const int T = K / BK;
    #pragma unroll
    for (int s = 0; s < NS - 1; s++) {
        if (s < T) prefetch(s, s);
        asm volatile("cp.async.commit_group;\n");
    }

    for (int t = 0; t < T; t++) {
        int tn = t + NS - 1;
        if (tn < T) prefetch(tn % NS, tn);
        asm volatile("cp.async.commit_group;\n");
        asm volatile("cp.async.wait_group %0;\n" :: "n"(NS - 1));
        __syncthreads();

        uint32_t abase = (uint32_t)__cvta_generic_to_shared(sm2 + (t % NS) * SSZ);
        uint32_t bbase = abase + ASZ * 2;
        #pragma unroll
        for (int k16 = 0; k16 < 2; k16++) {
            const int half = lane >> 4;
            uint32_t af[4][4], bfr[4][4];
            #pragma unroll
            for (int i = 0; i < 4; i++) {
                int row = wm * 64 + i * 16 + (lane & 15);
                ldsm_x4(af[i], abase + (row * SP + (k16 * 2 + half) * 8) * 2);
            }
            #pragma unroll
            for (int jp = 0; jp < 4; jp++) {
                int row = wn * 64 + jp * 16 + (lane & 15);
                ldsm_x4(bfr[jp], bbase + (row * SP + (k16 * 2 + half) * 8) * 2);
            }
            #pragma unroll
            for (int i = 0; i < 4; i++)
                #pragma unroll
                for (int jp = 0; jp < 4; jp++) {
                    mma16816(acc[i][2*jp],   af[i], bfr[jp][0], bfr[jp][2]);
                    mma16816(acc[i][2*jp+1], af[i], bfr[jp][1], bfr[jp][3]);
                }
        }
        __syncthreads();
    }

    // epilogue: lane holds (r, c), (r, c+1), (r+8, c), (r+8, c+1) per frag
    const int r0 = bm + wm * 64 + (lane >> 2);
    const int c0 = bn + wn * 64 + (lane & 3) * 2;
    #pragma unroll
    for (int i = 0; i < 4; i++) {
        #pragma unroll
        for (int j = 0; j < 8; j++) {
            int r = r0 + i * 16;
            int c = c0 + j * 8;
            float v0 = acc[i][j][0], v1 = acc[i][j][1];
            float v2 = acc[i][j][2], v3 = acc[i][j][3];
            if (EPI == 1) {
                const float2 a0 = *(const float2*)(aux + (size_t)r * ldc + c);
                const float2 a1 = *(const float2*)(aux + (size_t)(r+8) * ldc + c);
                v0 += a0.x; v1 += a0.y; v2 += a1.x; v3 += a1.y;
            } else if (EPI == 2) {
                float b0 = aux[c], b1 = aux[c+1];
                v0 += b0; v1 += b1; v2 += b0; v3 += b1;
                v0 = (v0 > 20.f) ? v0 : log1pf(__expf(v0));
                v1 = (v1 > 20.f) ? v1 : log1pf(__expf(v1));
                v2 = (v2 > 20.f) ? v2 : log1pf(__expf(v2));
                v3 = (v3 > 20.f) ? v3 : log1pf(__expf(v3));
            }
            *(float2*)(C + (size_t)r * ldc + c)     = make_float2(v0, v1);
            *(float2*)(C + (size_t)(r+8) * ldc + c) = make_float2(v2, v3);
        }
    }
}

// ---------------- fp32 -> bf16 convert -------------------------------------
__global__ void f2bf_kernel(const float* __restrict__ src, bf16* __restrict__ dst, int n)
{
    int i = (blockIdx.x * 256 + threadIdx.x) * 4;
    if (i < n) {
        float4 v = *(const float4*)(src + i);
        __nv_bfloat162* d = (__nv_bfloat162*)(dst + i);
        d[0] = __floats2bfloat162_rn(v.x, v.y);
        d[1] = __floats2bfloat162_rn(v.z, v.w);
    }
}

// extract dt_lo (cols 0..63 of dbl, stride 96) -> bf16 [MM x 64]
__global__ void dtlo_kernel(const float* __restrict__ dbl, bf16* __restrict__ dtlo)
{
    int idx = blockIdx.x * 256 + threadIdx.x;   // over MM*64
    int m = idx >> 6, r = idx & 63;
    dtlo[idx] = __float2bfloat16(dbl[(size_t)m * 96 + r]);
}

// ---------------- layernorm -> bf16 ----------------------------------------
__global__ void layernorm_kernel(const float* __restrict__ x,
                                 const float* __restrict__ g,
                                 const float* __restrict__ b,
                                 bf16* __restrict__ o)
{
    __shared__ float red[64];
    int row = blockIdx.x;
    int t = threadIdx.x;                       // 256
    const float4* xr = (const float4*)(x + (size_t)row * DM);
    float4 v = xr[t];
    float s = v.x + v.y + v.z + v.w;
    float q = v.x*v.x + v.y*v.y + v.z*v.z + v.w*v.w;
    #pragma unroll
    for (int off = 16; off; off >>= 1) {
        s += __shfl_xor_sync(0xffffffffu, s, off);
        q += __shfl_xor_sync(0xffffffffu, q, off);
    }
    if ((t & 31) == 0) { red[t >> 5] = s; red[32 + (t >> 5)] = q; }
    __syncthreads();
    if (t < 32) {
        float s2 = (t < 8) ? red[t]      : 0.f;
        float q2 = (t < 8) ? red[32 + t] : 0.f;
        #pragma unroll
        for (int off = 4; off; off >>= 1) {
            s2 += __shfl_xor_sync(0xffffffffu, s2, off);
            q2 += __shfl_xor_sync(0xffffffffu, q2, off);
        }
        if (t == 0) { red[0] = s2; red[1] = q2; }
    }
    __syncthreads();
    float mu  = red[0] * (1.f / DM);
    float var = red[1] * (1.f / DM) - mu * mu;
    float inv = rsqrtf(var + 1e-5f);
    float4 gv = ((const float4*)g)[t];
    float4 bv = ((const float4*)b)[t];
    __nv_bfloat162* op = (__nv_bfloat162*)(o + (size_t)row * DM + t * 4);
    op[0] = __floats2bfloat162_rn((v.x - mu)*inv*gv.x + bv.x, (v.y - mu)*inv*gv.y + bv.y);
    op[1] = __floats2bfloat162_rn((v.z - mu)*inv*gv.z + bv.z, (v.w - mu)*inv*gv.w + bv.w);
}

// ---------------- bf16 wmma GEMM (W_xp only) -------------------------------
#define STAGES 3
#define SPAD   40   // bf16 elems per 32-elem row (80B stride)

template<int BM, int BN, int WGM, int WGN, int EPI>
__global__ __launch_bounds__(WGM*WGN*32)
void hgemm_kernel(const bf16* __restrict__ A, int lda,
                  const bf16* __restrict__ W, int ldb,
                  float* __restrict__ C, int ldc,
                  int N, int K,
                  const float* __restrict__ addsrc)
{
    constexpr int TM = BM / WGM;
    constexpr int TN = BN / WGN;
    constexpr int MF = TM / 16;
    constexpr int NF = TN / 16;
    constexpr int NT = WGM * WGN * 32;
    constexpr int SSZ = (BM + BN) * SPAD;

    extern __shared__ bf16 smh[];

    int tid = threadIdx.x;
    int wid = tid >> 5;
    int wm  = wid / WGN;
    int wn  = wid % WGN;
    int bm  = blockIdx.y * BM;
    int bn  = blockIdx.x * BN;

    auto prefetch = [&](int p, int k0) {
        uint32_t sbase = (uint32_t)__cvta_generic_to_shared(smh + p * SSZ);
        #pragma unroll
        for (int i = 0; i < (BM * 4) / NT; i++) {
            int e = i * NT + tid;
            int row = e >> 2, c8 = (e & 3) * 8;
            cp_async16(sbase + (row * SPAD + c8) * 2,
                       A + (size_t)(bm + row) * lda + k0 + c8);
        }
        uint32_t sbase2 = sbase + BM * SPAD * 2;
        #pragma unroll
        for (int i = 0; i < (BN * 4) / NT; i++) {
            int e = i * NT + tid;
            int row = e >> 2, c8 = (e & 3) * 8;
            int n = bn + row; if (n >= N) n = N - 1;
            cp_async16(sbase2 + (row * SPAD + c8) * 2,
                       W + (size_t)n * ldb + k0 + c8);
        }
    };

    wmma::fragment<wmma::accumulator, 16, 16, 16, float> acc[MF][NF];
    #pragma unroll
    for (int i = 0; i < MF; i++)
        #pragma unroll
        for (int j = 0; j < NF; j++) wmma::fill_fragment(acc[i][j], 0.f);

    int T = K / 32;
    #pragma unroll
    for (int s = 0; s < STAGES - 1; s++) {
        if (s < T) prefetch(s, s * 32);
        asm volatile("cp.async.commit_group;\n");
    }

    for (int t = 0; t < T; t++) {
        asm volatile("cp.async.wait_group %0;\n" :: "n"(STAGES - 2));
        __syncthreads();

        int pn = t + STAGES - 1;
        if (pn < T) prefetch(pn % STAGES, pn * 32);
        asm volatile("cp.async.commit_group;\n");

        const bf16* As = smh + (t % STAGES) * SSZ;
        const bf16* Ws = As + BM * SPAD;
        #pragma unroll
        for (int ks = 0; ks < 32; ks += 16) {
            wmma::fragment<wmma::matrix_a, 16, 16, 16, bf16, wmma::row_major> af[MF];
            wmma::fragment<wmma::matrix_b, 16, 16, 16, bf16, wmma::col_major> bff[NF];
            #pragma unroll
            for (int i = 0; i < MF; i++)
                wmma::load_matrix_sync(af[i], As + (wm * TM + i * 16) * SPAD + ks, SPAD);
            #pragma unroll
            for (int j = 0; j < NF; j++)
                wmma::load_matrix_sync(bff[j], Ws + (wn * TN + j * 16) * SPAD + ks, SPAD);
            #pragma unroll
            for (int i = 0; i < MF; i++)
                #pragma unroll
                for (int j = 0; j < NF; j++)
                    wmma::mma_sync(acc[i][j], af[i], bff[j], acc[i][j]);
        }
        __syncthreads();
    }

    #pragma unroll
    for (int i = 0; i < MF; i++) {
        int r0 = bm + wm * TM + i * 16;
        #pragma unroll
        for (int j = 0; j < NF; j++) {
            int c0 = bn + wn * TN + j * 16;
            if (c0 < N) {
                wmma::store_matrix_sync(C + (size_t)r0 * ldc + c0, acc[i][j], ldc, wmma::mem_row_major);
            }
        }
    }
}

// ---------------- causal depthwise conv (DC=4) + silu ----------------------
__global__ void conv_silu_kernel(const float* __restrict__ xz,
                                 const float* __restrict__ cw,
                                 const float* __restrict__ cb,
                                 float* __restrict__ xc,
                                 bf16* __restrict__ xcb)
{
    int idx = blockIdx.x * 256 + threadIdx.x;      // over M*DI
    int d = idx & (DI - 1);
    int m = idx >> 11;
    int l = m & (LL - 1);
    const float* p = xz + (size_t)m * (2*DI) + d;
    float w0 = cw[d*4+0], w1 = cw[d*4+1], w2 = cw[d*4+2], w3 = cw[d*4+3];
    float acc = cb[d] + w3 * p[0];
    if (l >= 1) acc += w2 * p[-(2*DI)];
    if (l >= 2) acc += w1 * p[-2*(2*DI)];
    if (l >= 3) acc += w0 * p[-3*(2*DI)];
    float r = acc / (1.f + __expf(-acc));
    xc[(size_t)m * DI + d] = r;
    xcb[(size_t)m * DI + d] = __float2bfloat16(r);
}

// ---------------- selective scan: 16 lanes per (b,d) channel ---------------
__global__ void scan_kernel(const float* __restrict__ dt,
                            const float* __restrict__ xc,
                            const float* __restrict__ dbl,
                            const float* __restrict__ xz,
                            const float* __restrict__ A_log,
                            const float* __restrict__ Dp,
                            bf16* __restrict__ y)
{
    int gid = blockIdx.x * 256 + threadIdx.x;   // 65536 threads
    int c = gid >> 4;
    int s = gid & 15;
    int b = c >> 11;
    int d = c & (DI - 1);
    float A_s = -__expf(A_log[d * DS + s]);
    float D_d = Dp[d];
    float h = 0.f;
    size_t mbase = (size_t)b * LL;
    for (int l = 0; l < LL; l++) {
        size_t m = mbase + l;
        float dtv = dt[m * DI + d];
        float xv  = xc[m * DI + d];
        float Bv  = dbl[m * 96 + DTR + s];
        float Cv  = dbl[m * 96 + DTR + DS + s];
        float a = __expf(dtv * A_s);
        h = fmaf(a, h, dtv * xv * Bv);
        float p = h * Cv;
        p += __shfl_xor_sync(0xffffffffu, p, 8);
        p += __shfl_xor_sync(0xffffffffu, p, 4);
        p += __shfl_xor_sync(0xffffffffu, p, 2);
        p += __shfl_xor_sync(0xffffffffu, p, 1);
        if (s == 0) {
            float zv = xz[m * (2*DI) + DI + d];
            float yy = p + xv * D_d;
            y[m * DI + d] = __float2bfloat16(yy * (zv / (1.f + __expf(-zv))));
        }
    }
}

// ---------------- launcher -------------------------------------------------
extern "C" void kernel_launch(void* const* d_in, const int* in_sizes, int n_in,
                              void* d_out, int out_size)
{
    const float* x      = (const float*)d_in[0];
    const float* ln_g   = (const float*)d_in[1];
    const float* ln_b   = (const float*)d_in[2];
    const float* W_in   = (const float*)d_in[3];
    const float* conv_w = (const float*)d_in[4];
    const float* conv_b = (const float*)d_in[5];
    const float* W_xp   = (const float*)d_in[6];
    const float* W_dt   = (const float*)d_in[7];
    const float* b_dt   = (const float*)d_in[8];
    const float* A_log  = (const float*)d_in[9];
    const float* Dp     = (const float*)d_in[10];
    const float* W_out  = (const float*)d_in[11];
    float* out = (float*)d_out;

    float *xz, *xc, *dbl, *dtb;
    bf16 *xnb, *xcb, *dtlo, *yb, *Winb, *Wxpb, *Wdtb, *Woutb;
    cudaGetSymbolAddress((void**)&xz,   g_xz);
    cudaGetSymbolAddress((void**)&xc,   g_xc);
    cudaGetSymbolAddress((void**)&dbl,  g_dbl);
    cudaGetSymbolAddress((void**)&dtb,  g_dt);
    cudaGetSymbolAddress((void**)&xnb,  g_xnb);
    cudaGetSymbolAddress((void**)&xcb,  g_xcb);
    cudaGetSymbolAddress((void**)&dtlo, g_dtlo);
    cudaGetSymbolAddress((void**)&yb,   g_yb);
    cudaGetSymbolAddress((void**)&Winb, g_Winb);
    cudaGetSymbolAddress((void**)&Wxpb, g_Wxpb);
    cudaGetSymbolAddress((void**)&Wdtb, g_Wdtb);
    cudaGetSymbolAddress((void**)&Woutb,g_Woutb);

    constexpr int SM_MMA = 4 * (128 + 256) * 40 * 2;          // 122880
    constexpr int SM_64  = (64 + 128) * SPAD * 2 * STAGES;    // 46080
    cudaFuncSetAttribute(mma_gemm_kernel<0>, cudaFuncAttributeMaxDynamicSharedMemorySize, SM_MMA);
    cudaFuncSetAttribute(mma_gemm_kernel<1>, cudaFuncAttributeMaxDynamicSharedMemorySize, SM_MMA);
    cudaFuncSetAttribute(mma_gemm_kernel<2>, cudaFuncAttributeMaxDynamicSharedMemorySize, SM_MMA);
    cudaFuncSetAttribute(hgemm_kernel<64,128,2,4,0>, cudaFuncAttributeMaxDynamicSharedMemorySize, SM_64);

    // 0. weight conversions
    f2bf_kernel<<<((2*DI*DM)/4 + 255)/256, 256>>>(W_in,  Winb, 2*DI*DM);
    f2bf_kernel<<<((96*DI)/4 + 255)/256, 256>>>(W_xp,  Wxpb, 96*DI);
    f2bf_kernel<<<((DI*DTR)/4 + 255)/256, 256>>>(W_dt,  Wdtb, DI*DTR);
    f2bf_kernel<<<((DM*DI)/4 + 255)/256, 256>>>(W_out, Woutb, DM*DI);

    // 1. LayerNorm -> bf16
    layernorm_kernel<<<MM, 256>>>(x, ln_g, ln_b, xnb);
    // 2. xz = xn @ W_in^T   [8192 x 4096], K=1024
    mma_gemm_kernel<0><<<dim3(4096/256, MM/128), 256, SM_MMA>>>(
        xnb, DM, Winb, DM, xz, 2*DI, DM, nullptr);
    // 3. causal conv + silu -> xc
    conv_silu_kernel<<<(MM*DI)/256, 256>>>(xz, conv_w, conv_b, xc, xcb);
    // 4. dbl = xc @ W_xp^T  [8192 x 96], K=2048  (wmma)
    hgemm_kernel<64,128,2,4,0><<<dim3(1, MM/64), 256, SM_64>>>(
        xcb, DI, Wxpb, DI, dbl, 96, 96, DI, nullptr);
    // 4b. dt_lo -> bf16
    dtlo_kernel<<<(MM*DTR)/256, 256>>>(dbl, dtlo);
    // 5. dt = softplus(dt_lo @ W_dt^T + b_dt)  [8192 x 2048], K=64 (fused epilogue)
    mma_gemm_kernel<2><<<dim3(DI/256, MM/128), 256, SM_MMA>>>(
        dtlo, DTR, Wdtb, DTR, dtb, DI, DTR, b_dt);
    // 6. selective scan
    scan_kernel<<<(BB*DI*DS)/256, 256>>>(dtb, xc, dbl, xz, A_log, Dp, yb);
    // 7. out = x + y @ W_out^T  [8192 x 1024], K=2048
    mma_gemm_kernel<1><<<dim3(DM/256, MM/128), 256, SM_MMA>>>(
        yb, DI, Woutb, DI, out, DM, DI, x);
}

// round 7
// speedup vs baseline: 3.9116x; 2.5371x over previous
#include <cuda_runtime.h>
#include <cuda_bf16.h>
#include <mma.h>
#include <cstdint>

using namespace nvcuda;
typedef __nv_bfloat16 bf16;

#define BB    2
#define LL    4096
#define DM    1024
#define DS    16
#define DI    2048
#define DTR   64
#define MM    (BB*LL)          // 8192
#define CH    256
#define NCH   (LL/CH)          // 16

// ---------------- scratch (device globals) ---------------------------------
__device__ float g_xz [ (size_t)MM * (2*DI) ];    // 8192x4096 (xs | z) fp32
__device__ float g_xc [ (size_t)MM * DI ];        // fp32 (scan)
__device__ float g_dbl[ (size_t)MM * 96 ];        // dt_lo64 | B16 | C16  fp32
__device__ float g_dt [ (size_t)MM * DI ];        // fp32
__device__ bf16  g_xnb [ (size_t)MM * DM ];       // LN out, bf16
__device__ bf16  g_xcb [ (size_t)MM * DI ];       // conv out, bf16
__device__ bf16  g_dtlo[ (size_t)MM * DTR ];      // dt_lo, bf16
__device__ bf16  g_yb  [ (size_t)MM * DI ];       // scan out, bf16
__device__ bf16  g_Winb [ (size_t)(2*DI) * DM ];
__device__ bf16  g_Wxpb [ (size_t)96 * DI ];
__device__ bf16  g_Wdtb [ (size_t)DI * DTR ];
__device__ bf16  g_Woutb[ (size_t)DM * DI ];
// chunked-scan buffers: [b][d][s][ch]
__device__ float g_P [ (size_t)BB * DI * DS * NCH ];
__device__ float g_U [ (size_t)BB * DI * DS * NCH ];
__device__ float g_H [ (size_t)BB * DI * DS * NCH ];

// ======================= helpers ============================================
__device__ __forceinline__ void cp_async16(uint32_t saddr, const void* gptr) {
    asm volatile("cp.async.cg.shared.global [%0], [%1], 16;\n" :: "r"(saddr), "l"(gptr));
}
__device__ __forceinline__ void ldsm_x4(uint32_t* r, uint32_t addr) {
    asm volatile("ldmatrix.sync.aligned.m8n8.x4.shared.b16 {%0,%1,%2,%3}, [%4];"
        : "=r"(r[0]), "=r"(r[1]), "=r"(r[2]), "=r"(r[3]) : "r"(addr));
}
__device__ __forceinline__ void mma16816(float* d, const uint32_t* a, uint32_t b0, uint32_t b1) {
    asm volatile("mma.sync.aligned.m16n8k16.row.col.f32.bf16.bf16.f32 "
        "{%0,%1,%2,%3}, {%4,%5,%6,%7}, {%8,%9}, {%0,%1,%2,%3};"
        : "+f"(d[0]), "+f"(d[1]), "+f"(d[2]), "+f"(d[3])
        : "r"(a[0]), "r"(a[1]), "r"(a[2]), "r"(a[3]), "r"(b0), "r"(b1));
}

// ======================= mma.sync GEMM ======================================
//  C[M,N] = A[M,K] * W[N,K]^T   (bf16 in, fp32 out)
//  CTA 128x256, BK=32, 4-stage cp.async, warp tile 64x64 (2x4 warp grid).
//  EPI: 0 plain, 1 +aux residual (row-major MxN), 2 softplus(v + aux[col]).
template<int EPI>
__global__ __launch_bounds__(256)
void mma_gemm_kernel(const bf16* __restrict__ A, int lda,
                     const bf16* __restrict__ W, int ldb,
                     float* __restrict__ C, int ldc,
                     int K, const float* __restrict__ aux)
{
    constexpr int BM = 128, BN = 256, BK = 32, NS = 4, SP = 40;
    constexpr int ASZ = BM * SP;
    constexpr int BSZ = BN * SP;
    constexpr int SSZ = ASZ + BSZ;

    extern __shared__ bf16 sm2[];
    const int tid  = threadIdx.x;
    const int lane = tid & 31;
    const int wid  = tid >> 5;
    const int wm   = wid >> 2;
    const int wn   = wid & 3;
    const int bm   = blockIdx.y * BM;
    const int bn   = blockIdx.x * BN;

    auto prefetch = [&](int s, int kt) {
        const int k0 = kt * BK;
        uint32_t base = (uint32_t)__cvta_generic_to_shared(sm2 + s * SSZ);
        #pragma unroll
        for (int i = 0; i < 2; i++) {
            int e = i * 256 + tid;
            int r = e >> 2, c = e & 3;
            cp_async16(base + (r * SP + c * 8) * 2,
                       A + (size_t)(bm + r) * lda + k0 + c * 8);
        }
        uint32_t baseB = base + ASZ * 2;
        #pragma unroll
        for (int i = 0; i < 4; i++) {
            int e = i * 256 + tid;
            int r = e >> 2, c = e & 3;
            cp_async16(baseB + (r * SP + c * 8) * 2,
                       W + (size_t)(bn + r) * ldb + k0 + c * 8);
        }
    };

    float acc[4][8][4];
    #pragma unroll
    for (int i = 0; i < 4; i++)
        #pragma unroll
        for (int j = 0; j < 8; j++)
            #pragma unroll
            for (int e = 0; e < 4; e++) acc[i][j][e] = 0.f;

    const int T = K / BK;
    #pragma unroll
    for (int s = 0; s < NS - 1; s++) {
        if (s < T) prefetch(s, s);
        asm volatile("cp.async.commit_group;\n");
    }

    for (int t = 0; t < T; t++) {
        int tn = t + NS - 1;
        if (tn < T) prefetch(tn % NS, tn);
        asm volatile("cp.async.commit_group;\n");
        asm volatile("cp.async.wait_group %0;\n" :: "n"(NS - 1));
        __syncthreads();

        uint32_t abase = (uint32_t)__cvta_generic_to_shared(sm2 + (t % NS) * SSZ);
        uint32_t bbase = abase + ASZ * 2;
        #pragma unroll
        for (int k16 = 0; k16 < 2; k16++) {
            const int half = lane >> 4;
            uint32_t af[4][4], bfr[4][4];
            #pragma unroll
            for (int i = 0; i < 4; i++) {
                int row = wm * 64 + i * 16 + (lane & 15);
                ldsm_x4(af[i], abase + (row * SP + (k16 * 2 + half) * 8) * 2);
            }
            #pragma unroll
            for (int jp = 0; jp < 4; jp++) {
                int row = wn * 64 + jp * 16 + (lane & 15);
                ldsm_x4(bfr[jp], bbase + (row * SP + (k16 * 2 + half) * 8) * 2);
            }
            #pragma unroll
            for (int i = 0; i < 4; i++)
                #pragma unroll
                for (int jp = 0; jp < 4; jp++) {
                    mma16816(acc[i][2*jp],   af[i], bfr[jp][0], bfr[jp][2]);
                    mma16816(acc[i][2*jp+1], af[i], bfr[jp][1], bfr[jp][3]);
                }
        }
        __syncthreads();
    }

    const int r0 = bm + wm * 64 + (lane >> 2);
    const int c0 = bn + wn * 64 + (lane & 3) * 2;
    #pragma unroll
    for (int i = 0; i < 4; i++) {
        #pragma unroll
        for (int j = 0; j < 8; j++) {
            int r = r0 + i * 16;
            int c = c0 + j * 8;
            float v0 = acc[i][j][0], v1 = acc[i][j][1];
            float v2 = acc[i][j][2], v3 = acc[i][j][3];
            if (EPI == 1) {
                const float2 a0 = *(const float2*)(aux + (size_t)r * ldc + c);
                const float2 a1 = *(const float2*)(aux + (size_t)(r+8) * ldc + c);
                v0 += a0.x; v1 += a0.y; v2 += a1.x; v3 += a1.y;
            } else if (EPI == 2) {
                float b0 = aux[c], b1 = aux[c+1];
                v0 += b0; v1 += b1; v2 += b0; v3 += b1;
                v0 = (v0 > 20.f) ? v0 : log1pf(__expf(v0));
                v1 = (v1 > 20.f) ? v1 : log1pf(__expf(v1));
                v2 = (v2 > 20.f) ? v2 : log1pf(__expf(v2));
                v3 = (v3 > 20.f) ? v3 : log1pf(__expf(v3));
            }
            *(float2*)(C + (size_t)r * ldc + c)     = make_float2(v0, v1);
            *(float2*)(C + (size_t)(r+8) * ldc + c) = make_float2(v2, v3);
        }
    }
}

// ---------------- fp32 -> bf16 convert -------------------------------------
__global__ void f2bf_kernel(const float* __restrict__ src, bf16* __restrict__ dst, int n)
{
    int i = (blockIdx.x * 256 + threadIdx.x) * 4;
    if (i < n) {
        float4 v = *(const float4*)(src + i);
        __nv_bfloat162* d = (__nv_bfloat162*)(dst + i);
        d[0] = __floats2bfloat162_rn(v.x, v.y);
        d[1] = __floats2bfloat162_rn(v.z, v.w);
    }
}

// extract dt_lo (cols 0..63 of dbl, stride 96) -> bf16 [MM x 64]
__global__ void dtlo_kernel(const float* __restrict__ dbl, bf16* __restrict__ dtlo)
{
    int idx = blockIdx.x * 256 + threadIdx.x;
    int m = idx >> 6, r = idx & 63;
    dtlo[idx] = __float2bfloat16(dbl[(size_t)m * 96 + r]);
}

// ---------------- layernorm -> bf16 ----------------------------------------
__global__ void layernorm_kernel(const float* __restrict__ x,
                                 const float* __restrict__ g,
                                 const float* __restrict__ b,
                                 bf16* __restrict__ o)
{
    __shared__ float red[64];
    int row = blockIdx.x;
    int t = threadIdx.x;
    const float4* xr = (const float4*)(x + (size_t)row * DM);
    float4 v = xr[t];
    float s = v.x + v.y + v.z + v.w;
    float q = v.x*v.x + v.y*v.y + v.z*v.z + v.w*v.w;
    #pragma unroll
    for (int off = 16; off; off >>= 1) {
        s += __shfl_xor_sync(0xffffffffu, s, off);
        q += __shfl_xor_sync(0xffffffffu, q, off);
    }
    if ((t & 31) == 0) { red[t >> 5] = s; red[32 + (t >> 5)] = q; }
    __syncthreads();
    if (t < 32) {
        float s2 = (t < 8) ? red[t]      : 0.f;
        float q2 = (t < 8) ? red[32 + t] : 0.f;
        #pragma unroll
        for (int off = 4; off; off >>= 1) {
            s2 += __shfl_xor_sync(0xffffffffu, s2, off);
            q2 += __shfl_xor_sync(0xffffffffu, q2, off);
        }
        if (t == 0) { red[0] = s2; red[1] = q2; }
    }
    __syncthreads();
    float mu  = red[0] * (1.f / DM);
    float var = red[1] * (1.f / DM) - mu * mu;
    float inv = rsqrtf(var + 1e-5f);
    float4 gv = ((const float4*)g)[t];
    float4 bv = ((const float4*)b)[t];
    __nv_bfloat162* op = (__nv_bfloat162*)(o + (size_t)row * DM + t * 4);
    op[0] = __floats2bfloat162_rn((v.x - mu)*inv*gv.x + bv.x, (v.y - mu)*inv*gv.y + bv.y);
    op[1] = __floats2bfloat162_rn((v.z - mu)*inv*gv.z + bv.z, (v.w - mu)*inv*gv.w + bv.w);
}

// ---------------- bf16 wmma GEMM (W_xp only) -------------------------------
#define STAGES 3
#define SPAD   40

template<int BM, int BN, int WGM, int WGN, int EPI>
__global__ __launch_bounds__(WGM*WGN*32)
void hgemm_kernel(const bf16* __restrict__ A, int lda,
                  const bf16* __restrict__ W, int ldb,
                  float* __restrict__ C, int ldc,
                  int N, int K,
                  const float* __restrict__ addsrc)
{
    constexpr int TM = BM / WGM;
    constexpr int TN = BN / WGN;
    constexpr int MF = TM / 16;
    constexpr int NF = TN / 16;
    constexpr int NT = WGM * WGN * 32;
    constexpr int SSZ = (BM + BN) * SPAD;

    extern __shared__ bf16 smh[];

    int tid = threadIdx.x;
    int wid = tid >> 5;
    int wm  = wid / WGN;
    int wn  = wid % WGN;
    int bm  = blockIdx.y * BM;
    int bn  = blockIdx.x * BN;

    auto prefetch = [&](int p, int k0) {
        uint32_t sbase = (uint32_t)__cvta_generic_to_shared(smh + p * SSZ);
        #pragma unroll
        for (int i = 0; i < (BM * 4) / NT; i++) {
            int e = i * NT + tid;
            int row = e >> 2, c8 = (e & 3) * 8;
            cp_async16(sbase + (row * SPAD + c8) * 2,
                       A + (size_t)(bm + row) * lda + k0 + c8);
        }
        uint32_t sbase2 = sbase + BM * SPAD * 2;
        #pragma unroll
        for (int i = 0; i < (BN * 4) / NT; i++) {
            int e = i * NT + tid;
            int row = e >> 2, c8 = (e & 3) * 8;
            int n = bn + row; if (n >= N) n = N - 1;
            cp_async16(sbase2 + (row * SPAD + c8) * 2,
                       W + (size_t)n * ldb + k0 + c8);
        }
    };

    wmma::fragment<wmma::accumulator, 16, 16, 16, float> acc[MF][NF];
    #pragma unroll
    for (int i = 0; i < MF; i++)
        #pragma unroll
        for (int j = 0; j < NF; j++) wmma::fill_fragment(acc[i][j], 0.f);

    int T = K / 32;
    #pragma unroll
    for (int s = 0; s < STAGES - 1; s++) {
        if (s < T) prefetch(s, s * 32);
        asm volatile("cp.async.commit_group;\n");
    }

    for (int t = 0; t < T; t++) {
        asm volatile("cp.async.wait_group %0;\n" :: "n"(STAGES - 2));
        __syncthreads();

        int pn = t + STAGES - 1;
        if (pn < T) prefetch(pn % STAGES, pn * 32);
        asm volatile("cp.async.commit_group;\n");

        const bf16* As = smh + (t % STAGES) * SSZ;
        const bf16* Ws = As + BM * SPAD;
        #pragma unroll
        for (int ks = 0; ks < 32; ks += 16) {
            wmma::fragment<wmma::matrix_a, 16, 16, 16, bf16, wmma::row_major> af[MF];
            wmma::fragment<wmma::matrix_b, 16, 16, 16, bf16, wmma::col_major> bff[NF];
            #pragma unroll
            for (int i = 0; i < MF; i++)
                wmma::load_matrix_sync(af[i], As + (wm * TM + i * 16) * SPAD + ks, SPAD);
            #pragma unroll
            for (int j = 0; j < NF; j++)
                wmma::load_matrix_sync(bff[j], Ws + (wn * TN + j * 16) * SPAD + ks, SPAD);
            #pragma unroll
            for (int i = 0; i < MF; i++)
                #pragma unroll
                for (int j = 0; j < NF; j++)
                    wmma::mma_sync(acc[i][j], af[i], bff[j], acc[i][j]);
        }
        __syncthreads();
    }

    #pragma unroll
    for (int i = 0; i < MF; i++) {
        int r0 = bm + wm * TM + i * 16;
        #pragma unroll
        for (int j = 0; j < NF; j++) {
            int c0 = bn + wn * TN + j * 16;
            if (c0 < N) {
                wmma::store_matrix_sync(C + (size_t)r0 * ldc + c0, acc[i][j], ldc, wmma::mem_row_major);
            }
        }
    }
}

// ---------------- causal depthwise conv (DC=4) + silu ----------------------
__global__ void conv_silu_kernel(const float* __restrict__ xz,
                                 const float* __restrict__ cw,
                                 const float* __restrict__ cb,
                                 float* __restrict__ xc,
                                 bf16* __restrict__ xcb)
{
    int idx = blockIdx.x * 256 + threadIdx.x;
    int d = idx & (DI - 1);
    int m = idx >> 11;
    int l = m & (LL - 1);
    const float* p = xz + (size_t)m * (2*DI) + d;
    float w0 = cw[d*4+0], w1 = cw[d*4+1], w2 = cw[d*4+2], w3 = cw[d*4+3];
    float acc = cb[d] + w3 * p[0];
    if (l >= 1) acc += w2 * p[-(2*DI)];
    if (l >= 2) acc += w1 * p[-2*(2*DI)];
    if (l >= 3) acc += w0 * p[-3*(2*DI)];
    float r = acc / (1.f + __expf(-acc));
    xc[(size_t)m * DI + d] = r;
    xcb[(size_t)m * DI + d] = __float2bfloat16(r);
}

// =============== chunked selective scan =====================================
// gid layout: ((b*NCH + ch)*(DI/2) + dpair)*32 + dlo*16 + s
__device__ __forceinline__ void scan_decode(int gid, int& b, int& ch, int& d, int& s)
{
    s = gid & 15;
    int dlo = (gid >> 4) & 1;
    int rest = gid >> 5;                // (b*NCH+ch)*1024 + dpair
    int dpair = rest & 1023;            // DI/2 = 1024
    int rest2 = rest >> 10;             // b*NCH + ch
    ch = rest2 & (NCH - 1);
    b = rest2 >> 4;                     // NCH = 16
    d = dpair * 2 + dlo;
}

// phase 1: per-chunk (P = prod a, U = folded sum), h0 = 0
__global__ void scan_p1_kernel(const float* __restrict__ dt,
                               const float* __restrict__ xc,
                               const float* __restrict__ dbl,
                               const float* __restrict__ A_log,
                               float* __restrict__ P, float* __restrict__ U)
{
    int gid = blockIdx.x * 256 + threadIdx.x;   // BB*NCH*DI*DS = 1M
    int b, ch, d, s;
    scan_decode(gid, b, ch, d, s);
    float A_s = -__expf(A_log[d * DS + s]);
    float Pv = 1.f, Uv = 0.f;
    size_t mbase = (size_t)b * LL + ch * CH;
    #pragma unroll 4
    for (int l = 0; l < CH; l++) {
        size_t m = mbase + l;
        float dtv = dt[m * DI + d];
        float xv  = xc[m * DI + d];
        float Bv  = dbl[m * 96 + DTR + s];
        float a = __expf(dtv * A_s);
        Pv *= a;
        Uv = fmaf(a, Uv, dtv * xv * Bv);
    }
    size_t idx = (((size_t)b * DI + d) * DS + s) * NCH + ch;
    P[idx] = Pv;
    U[idx] = Uv;
}

// phase 2: compose chunk summaries -> h at chunk start
__global__ void scan_p2_kernel(const float* __restrict__ P,
                               const float* __restrict__ U,
                               float* __restrict__ H)
{
    int gid = blockIdx.x * 256 + threadIdx.x;   // BB*DI*DS = 65536
    size_t base = (size_t)gid * NCH;
    float h = 0.f;
    #pragma unroll
    for (int ch = 0; ch < NCH; ch++) {
        H[base + ch] = h;
        h = fmaf(P[base + ch], h, U[base + ch]);
    }
}

// phase 3: replay chunk from h0, project with C, gate with silu(z), write y
__global__ void scan_p3_kernel(const float* __restrict__ dt,
                               const float* __restrict__ xc,
                               const float* __restrict__ dbl,
                               const float* __restrict__ xz,
                               const float* __restrict__ A_log,
                               const float* __restrict__ Dp,
                               const float* __restrict__ H,
                               bf16* __restrict__ y)
{
    int gid = blockIdx.x * 256 + threadIdx.x;   // 1M
    int b, ch, d, s;
    scan_decode(gid, b, ch, d, s);
    float A_s = -__expf(A_log[d * DS + s]);
    float D_d = Dp[d];
    float h = H[(((size_t)b * DI + d) * DS + s) * NCH + ch];
    size_t mbase = (size_t)b * LL + ch * CH;
    #pragma unroll 2
    for (int l = 0; l < CH; l++) {
        size_t m = mbase + l;
        float dtv = dt[m * DI + d];
        float xv  = xc[m * DI + d];
        float Bv  = dbl[m * 96 + DTR + s];
        float Cv  = dbl[m * 96 + DTR + DS + s];
        float a = __expf(dtv * A_s);
        h = fmaf(a, h, dtv * xv * Bv);
        float p = h * Cv;
        p += __shfl_xor_sync(0xffffffffu, p, 8);
        p += __shfl_xor_sync(0xffffffffu, p, 4);
        p += __shfl_xor_sync(0xffffffffu, p, 2);
        p += __shfl_xor_sync(0xffffffffu, p, 1);
        if (s == 0) {
            float zv = xz[m * (2*DI) + DI + d];
            float yy = p + xv * D_d;
            y[m * DI + d] = __float2bfloat16(yy * (zv / (1.f + __expf(-zv))));
        }
    }
}

// ---------------- launcher -------------------------------------------------
extern "C" void kernel_launch(void* const* d_in, const int* in_sizes, int n_in,
                              void* d_out, int out_size)
{
    const float* x      = (const float*)d_in[0];
    const float* ln_g   = (const float*)d_in[1];
    const float* ln_b   = (const float*)d_in[2];
    const float* W_in   = (const float*)d_in[3];
    const float* conv_w = (const float*)d_in[4];
    const float* conv_b = (const float*)d_in[5];
    const float* W_xp   = (const float*)d_in[6];
    const float* W_dt   = (const float*)d_in[7];
    const float* b_dt   = (const float*)d_in[8];
    const float* A_log  = (const float*)d_in[9];
    const float* Dp     = (const float*)d_in[10];
    const float* W_out  = (const float*)d_in[11];
    float* out = (float*)d_out;

    float *xz, *xc, *dbl, *dtb, *Pb, *Ub, *Hb;
    bf16 *xnb, *xcb, *dtlo, *yb, *Winb, *Wxpb, *Wdtb, *Woutb;
    cudaGetSymbolAddress((void**)&xz,   g_xz);
    cudaGetSymbolAddress((void**)&xc,   g_xc);
    cudaGetSymbolAddress((void**)&dbl,  g_dbl);
    cudaGetSymbolAddress((void**)&dtb,  g_dt);
    cudaGetSymbolAddress((void**)&xnb,  g_xnb);
    cudaGetSymbolAddress((void**)&xcb,  g_xcb);
    cudaGetSymbolAddress((void**)&dtlo, g_dtlo);
    cudaGetSymbolAddress((void**)&yb,   g_yb);
    cudaGetSymbolAddress((void**)&Winb, g_Winb);
    cudaGetSymbolAddress((void**)&Wxpb, g_Wxpb);
    cudaGetSymbolAddress((void**)&Wdtb, g_Wdtb);
    cudaGetSymbolAddress((void**)&Woutb,g_Woutb);
    cudaGetSymbolAddress((void**)&Pb,   g_P);
    cudaGetSymbolAddress((void**)&Ub,   g_U);
    cudaGetSymbolAddress((void**)&Hb,   g_H);

    constexpr int SM_MMA = 4 * (128 + 256) * 40 * 2;          // 122880
    constexpr int SM_64  = (64 + 128) * SPAD * 2 * STAGES;    // 46080
    cudaFuncSetAttribute(mma_gemm_kernel<0>, cudaFuncAttributeMaxDynamicSharedMemorySize, SM_MMA);
    cudaFuncSetAttribute(mma_gemm_kernel<1>, cudaFuncAttributeMaxDynamicSharedMemorySize, SM_MMA);
    cudaFuncSetAttribute(mma_gemm_kernel<2>, cudaFuncAttributeMaxDynamicSharedMemorySize, SM_MMA);
    cudaFuncSetAttribute(hgemm_kernel<64,128,2,4,0>, cudaFuncAttributeMaxDynamicSharedMemorySize, SM_64);

    // 0. weight conversions
    f2bf_kernel<<<((2*DI*DM)/4 + 255)/256, 256>>>(W_in,  Winb, 2*DI*DM);
    f2bf_kernel<<<((96*DI)/4 + 255)/256, 256>>>(W_xp,  Wxpb, 96*DI);
    f2bf_kernel<<<((DI*DTR)/4 + 255)/256, 256>>>(W_dt,  Wdtb, DI*DTR);
    f2bf_kernel<<<((DM*DI)/4 + 255)/256, 256>>>(W_out, Woutb, DM*DI);

    // 1. LayerNorm -> bf16
    layernorm_kernel<<<MM, 256>>>(x, ln_g, ln_b, xnb);
    // 2. xz = xn @ W_in^T   [8192 x 4096], K=1024
    mma_gemm_kernel<0><<<dim3(4096/256, MM/128), 256, SM_MMA>>>(
        xnb, DM, Winb, DM, xz, 2*DI, DM, nullptr);
    // 3. causal conv + silu -> xc
    conv_silu_kernel<<<(MM*DI)/256, 256>>>(xz, conv_w, conv_b, xc, xcb);
    // 4. dbl = xc @ W_xp^T  [8192 x 96], K=2048  (wmma)
    hgemm_kernel<64,128,2,4,0><<<dim3(1, MM/64), 256, SM_64>>>(
        xcb, DI, Wxpb, DI, dbl, 96, 96, DI, nullptr);
    // 4b. dt_lo -> bf16
    dtlo_kernel<<<(MM*DTR)/256, 256>>>(dbl, dtlo);
    // 5. dt = softplus(dt_lo @ W_dt^T + b_dt)  (fused epilogue)
    mma_gemm_kernel<2><<<dim3(DI/256, MM/128), 256, SM_MMA>>>(
        dtlo, DTR, Wdtb, DTR, dtb, DI, DTR, b_dt);
    // 6. chunked selective scan (3 phases)
    scan_p1_kernel<<<(BB*NCH*DI*DS)/256, 256>>>(dtb, xc, dbl, A_log, Pb, Ub);
    scan_p2_kernel<<<(BB*DI*DS)/256, 256>>>(Pb, Ub, Hb);
    scan_p3_kernel<<<(BB*NCH*DI*DS)/256, 256>>>(dtb, xc, dbl, xz, A_log, Dp, Hb, yb);
    // 7. out = x + y @ W_out^T  [8192 x 1024], K=2048
    mma_gemm_kernel<1><<<dim3(DM/256, MM/128), 256, SM_MMA>>>(
        yb, DI, Woutb, DI, out, DM, DI, x);
}

// round 8
// speedup vs baseline: 3.9713x; 1.0153x over previous
#include <cuda_runtime.h>
#include <cuda_bf16.h>
#include <mma.h>
#include <cstdint>

using namespace nvcuda;
typedef __nv_bfloat16 bf16;

#define BB    2
#define LL    4096
#define DM    1024
#define DS    16
#define DI    2048
#define DTR   64
#define MM    (BB*LL)          // 8192
#define CH    256
#define NCH   (LL/CH)          // 16

// ---------------- scratch (device globals) ---------------------------------
__device__ float g_xz [ (size_t)MM * (2*DI) ];    // 8192x4096 (xs | z) fp32
__device__ float g_xc [ (size_t)MM * DI ];        // fp32 (scan)
__device__ float g_dbl[ (size_t)MM * 96 ];        // dt_lo64 | B16 | C16  fp32
__device__ float g_dt [ (size_t)MM * DI ];        // fp32
__device__ bf16  g_xnb [ (size_t)MM * DM ];
__device__ bf16  g_xcb [ (size_t)MM * DI ];
__device__ bf16  g_dtlo[ (size_t)MM * DTR ];
__device__ bf16  g_yb  [ (size_t)MM * DI ];
__device__ bf16  g_Winb [ (size_t)(2*DI) * DM ];
__device__ bf16  g_Wxpb [ (size_t)96 * DI ];
__device__ bf16  g_Wdtb [ (size_t)DI * DTR ];
__device__ bf16  g_Woutb[ (size_t)DM * DI ];
__device__ float g_P [ (size_t)BB * DI * DS * NCH ];
__device__ float g_U [ (size_t)BB * DI * DS * NCH ];
__device__ float g_H [ (size_t)BB * DI * DS * NCH ];

// ======================= helpers ============================================
__device__ __forceinline__ void cp_async16(uint32_t saddr, const void* gptr) {
    asm volatile("cp.async.cg.shared.global [%0], [%1], 16;\n" :: "r"(saddr), "l"(gptr));
}
__device__ __forceinline__ void ldsm_x4(uint32_t* r, uint32_t addr) {
    asm volatile("ldmatrix.sync.aligned.m8n8.x4.shared.b16 {%0,%1,%2,%3}, [%4];"
        : "=r"(r[0]), "=r"(r[1]), "=r"(r[2]), "=r"(r[3]) : "r"(addr));
}
__device__ __forceinline__ void mma16816(float* d, const uint32_t* a, uint32_t b0, uint32_t b1) {
    asm volatile("mma.sync.aligned.m16n8k16.row.col.f32.bf16.bf16.f32 "
        "{%0,%1,%2,%3}, {%4,%5,%6,%7}, {%8,%9}, {%0,%1,%2,%3};"
        : "+f"(d[0]), "+f"(d[1]), "+f"(d[2]), "+f"(d[3])
        : "r"(a[0]), "r"(a[1]), "r"(a[2]), "r"(a[3]), "r"(b0), "r"(b1));
}
__device__ __forceinline__ float fast_softplus(float v) {
    return (v > 15.f) ? v : __logf(1.f + __expf(v));
}

// ======================= mma.sync GEMM (2 CTAs/SM) ==========================
//  C[M,N] = A[M,K] * W[N,K]^T   (bf16 in, fp32 out)
//  CTA 128x128, BK=32, 4-stage cp.async, warp tile 64x32 (2x4 warp grid).
//  EPI: 0 plain, 1 +aux residual (row-major MxN), 2 softplus(v + aux[col]).
template<int EPI>
__global__ __launch_bounds__(256, 2)
void mma_gemm_kernel(const bf16* __restrict__ A, int lda,
                     const bf16* __restrict__ W, int ldb,
                     float* __restrict__ C, int ldc,
                     int K, const float* __restrict__ aux)
{
    constexpr int BM = 128, BN = 128, BK = 32, NS = 4, SP = 40;
    constexpr int ASZ = BM * SP;
    constexpr int SSZ = (BM + BN) * SP;         // 10240 elems = 20480 B/stage

    extern __shared__ bf16 sm2[];
    const int tid  = threadIdx.x;
    const int lane = tid & 31;
    const int wid  = tid >> 5;
    const int wm   = wid >> 2;          // 0..1 -> 64 rows
    const int wn   = wid & 3;           // 0..3 -> 32 cols
    const int bm   = blockIdx.y * BM;
    const int bn   = blockIdx.x * BN;

    auto prefetch = [&](int s, int kt) {
        const int k0 = kt * BK;
        uint32_t base = (uint32_t)__cvta_generic_to_shared(sm2 + s * SSZ);
        #pragma unroll
        for (int i = 0; i < 2; i++) {               // A: 512 x 16B
            int e = i * 256 + tid;
            int r = e >> 2, c = e & 3;
            cp_async16(base + (r * SP + c * 8) * 2,
                       A + (size_t)(bm + r) * lda + k0 + c * 8);
        }
        uint32_t baseB = base + ASZ * 2;
        #pragma unroll
        for (int i = 0; i < 2; i++) {               // B: 512 x 16B
            int e = i * 256 + tid;
            int r = e >> 2, c = e & 3;
            cp_async16(baseB + (r * SP + c * 8) * 2,
                       W + (size_t)(bn + r) * ldb + k0 + c * 8);
        }
    };

    float acc[4][4][4];
    #pragma unroll
    for (int i = 0; i < 4; i++)
        #pragma unroll
        for (int j = 0; j < 4; j++)
            #pragma unroll
            for (int e = 0; e < 4; e++) acc[i][j][e] = 0.f;

    const int T = K / BK;
    #pragma unroll
    for (int s = 0; s < NS - 1; s++) {
        if (s < T) prefetch(s, s);
        asm volatile("cp.async.commit_group;\n");
    }

    for (int t = 0; t < T; t++) {
        int tn = t + NS - 1;
        if (tn < T) prefetch(tn % NS, tn);
        asm volatile("cp.async.commit_group;\n");
        asm volatile("cp.async.wait_group %0;\n" :: "n"(NS - 1));
        __syncthreads();

        uint32_t abase = (uint32_t)__cvta_generic_to_shared(sm2 + (t % NS) * SSZ);
        uint32_t bbase = abase + ASZ * 2;
        #pragma unroll
        for (int k16 = 0; k16 < 2; k16++) {
            const int half = lane >> 4;
            uint32_t af[4][4], bfr[2][4];
            #pragma unroll
            for (int i = 0; i < 4; i++) {
                int row = wm * 64 + i * 16 + (lane & 15);
                ldsm_x4(af[i], abase + (row * SP + (k16 * 2 + half) * 8) * 2);
            }
            #pragma unroll
            for (int jp = 0; jp < 2; jp++) {
                int row = wn * 32 + jp * 16 + (lane & 15);
                ldsm_x4(bfr[jp], bbase + (row * SP + (k16 * 2 + half) * 8) * 2);
            }
            #pragma unroll
            for (int i = 0; i < 4; i++)
                #pragma unroll
                for (int jp = 0; jp < 2; jp++) {
                    mma16816(acc[i][2*jp],   af[i], bfr[jp][0], bfr[jp][2]);
                    mma16816(acc[i][2*jp+1], af[i], bfr[jp][1], bfr[jp][3]);
                }
        }
        __syncthreads();
    }

    const int r0 = bm + wm * 64 + (lane >> 2);
    const int c0 = bn + wn * 32 + (lane & 3) * 2;
    #pragma unroll
    for (int i = 0; i < 4; i++) {
        #pragma unroll
        for (int j = 0; j < 4; j++) {
            int r = r0 + i * 16;
            int c = c0 + j * 8;
            float v0 = acc[i][j][0], v1 = acc[i][j][1];
            float v2 = acc[i][j][2], v3 = acc[i][j][3];
            if (EPI == 1) {
                const float2 a0 = *(const float2*)(aux + (size_t)r * ldc + c);
                const float2 a1 = *(const float2*)(aux + (size_t)(r+8) * ldc + c);
                v0 += a0.x; v1 += a0.y; v2 += a1.x; v3 += a1.y;
            } else if (EPI == 2) {
                float b0 = aux[c], b1 = aux[c+1];
                v0 = fast_softplus(v0 + b0);
                v1 = fast_softplus(v1 + b1);
                v2 = fast_softplus(v2 + b0);
                v3 = fast_softplus(v3 + b1);
            }
            *(float2*)(C + (size_t)r * ldc + c)     = make_float2(v0, v1);
            *(float2*)(C + (size_t)(r+8) * ldc + c) = make_float2(v2, v3);
        }
    }
}

// ---------------- fp32 -> bf16 convert -------------------------------------
__global__ void f2bf_kernel(const float* __restrict__ src, bf16* __restrict__ dst, int n)
{
    int i = (blockIdx.x * 256 + threadIdx.x) * 4;
    if (i < n) {
        float4 v = *(const float4*)(src + i);
        __nv_bfloat162* d = (__nv_bfloat162*)(dst + i);
        d[0] = __floats2bfloat162_rn(v.x, v.y);
        d[1] = __floats2bfloat162_rn(v.z, v.w);
    }
}

// extract dt_lo (cols 0..63 of dbl, stride 96) -> bf16 [MM x 64]
__global__ void dtlo_kernel(const float* __restrict__ dbl, bf16* __restrict__ dtlo)
{
    int idx = blockIdx.x * 256 + threadIdx.x;
    int m = idx >> 6, r = idx & 63;
    dtlo[idx] = __float2bfloat16(dbl[(size_t)m * 96 + r]);
}

// ---------------- layernorm -> bf16 ----------------------------------------
__global__ void layernorm_kernel(const float* __restrict__ x,
                                 const float* __restrict__ g,
                                 const float* __restrict__ b,
                                 bf16* __restrict__ o)
{
    __shared__ float red[64];
    int row = blockIdx.x;
    int t = threadIdx.x;
    const float4* xr = (const float4*)(x + (size_t)row * DM);
    float4 v = xr[t];
    float s = v.x + v.y + v.z + v.w;
    float q = v.x*v.x + v.y*v.y + v.z*v.z + v.w*v.w;
    #pragma unroll
    for (int off = 16; off; off >>= 1) {
        s += __shfl_xor_sync(0xffffffffu, s, off);
        q += __shfl_xor_sync(0xffffffffu, q, off);
    }
    if ((t & 31) == 0) { red[t >> 5] = s; red[32 + (t >> 5)] = q; }
    __syncthreads();
    if (t < 32) {
        float s2 = (t < 8) ? red[t]      : 0.f;
        float q2 = (t < 8) ? red[32 + t] : 0.f;
        #pragma unroll
        for (int off = 4; off; off >>= 1) {
            s2 += __shfl_xor_sync(0xffffffffu, s2, off);
            q2 += __shfl_xor_sync(0xffffffffu, q2, off);
        }
        if (t == 0) { red[0] = s2; red[1] = q2; }
    }
    __syncthreads();
    float mu  = red[0] * (1.f / DM);
    float var = red[1] * (1.f / DM) - mu * mu;
    float inv = rsqrtf(var + 1e-5f);
    float4 gv = ((const float4*)g)[t];
    float4 bv = ((const float4*)b)[t];
    __nv_bfloat162* op = (__nv_bfloat162*)(o + (size_t)row * DM + t * 4);
    op[0] = __floats2bfloat162_rn((v.x - mu)*inv*gv.x + bv.x, (v.y - mu)*inv*gv.y + bv.y);
    op[1] = __floats2bfloat162_rn((v.z - mu)*inv*gv.z + bv.z, (v.w - mu)*inv*gv.w + bv.w);
}

// ---------------- bf16 wmma GEMM (W_xp only) -------------------------------
#define STAGES 3
#define SPAD   40

template<int BM, int BN, int WGM, int WGN, int EPI>
__global__ __launch_bounds__(WGM*WGN*32)
void hgemm_kernel(const bf16* __restrict__ A, int lda,
                  const bf16* __restrict__ W, int ldb,
                  float* __restrict__ C, int ldc,
                  int N, int K,
                  const float* __restrict__ addsrc)
{
    constexpr int TM = BM / WGM;
    constexpr int TN = BN / WGN;
    constexpr int MF = TM / 16;
    constexpr int NF = TN / 16;
    constexpr int NT = WGM * WGN * 32;
    constexpr int SSZ = (BM + BN) * SPAD;

    extern __shared__ bf16 smh[];

    int tid = threadIdx.x;
    int wid = tid >> 5;
    int wm  = wid / WGN;
    int wn  = wid % WGN;
    int bm  = blockIdx.y * BM;
    int bn  = blockIdx.x * BN;

    auto prefetch = [&](int p, int k0) {
        uint32_t sbase = (uint32_t)__cvta_generic_to_shared(smh + p * SSZ);
        #pragma unroll
        for (int i = 0; i < (BM * 4) / NT; i++) {
            int e = i * NT + tid;
            int row = e >> 2, c8 = (e & 3) * 8;
            cp_async16(sbase + (row * SPAD + c8) * 2,
                       A + (size_t)(bm + row) * lda + k0 + c8);
        }
        uint32_t sbase2 = sbase + BM * SPAD * 2;
        #pragma unroll
        for (int i = 0; i < (BN * 4) / NT; i++) {
            int e = i * NT + tid;
            int row = e >> 2, c8 = (e & 3) * 8;
            int n = bn + row; if (n >= N) n = N - 1;
            cp_async16(sbase2 + (row * SPAD + c8) * 2,
                       W + (size_t)n * ldb + k0 + c8);
        }
    };

    wmma::fragment<wmma::accumulator, 16, 16, 16, float> acc[MF][NF];
    #pragma unroll
    for (int i = 0; i < MF; i++)
        #pragma unroll
        for (int j = 0; j < NF; j++) wmma::fill_fragment(acc[i][j], 0.f);

    int T = K / 32;
    #pragma unroll
    for (int s = 0; s < STAGES - 1; s++) {
        if (s < T) prefetch(s, s * 32);
        asm volatile("cp.async.commit_group;\n");
    }

    for (int t = 0; t < T; t++) {
        asm volatile("cp.async.wait_group %0;\n" :: "n"(STAGES - 2));
        __syncthreads();

        int pn = t + STAGES - 1;
        if (pn < T) prefetch(pn % STAGES, pn * 32);
        asm volatile("cp.async.commit_group;\n");

        const bf16* As = smh + (t % STAGES) * SSZ;
        const bf16* Ws = As + BM * SPAD;
        #pragma unroll
        for (int ks = 0; ks < 32; ks += 16) {
            wmma::fragment<wmma::matrix_a, 16, 16, 16, bf16, wmma::row_major> af[MF];
            wmma::fragment<wmma::matrix_b, 16, 16, 16, bf16, wmma::col_major> bff[NF];
            #pragma unroll
            for (int i = 0; i < MF; i++)
                wmma::load_matrix_sync(af[i], As + (wm * TM + i * 16) * SPAD + ks, SPAD);
            #pragma unroll
            for (int j = 0; j < NF; j++)
                wmma::load_matrix_sync(bff[j], Ws + (wn * TN + j * 16) * SPAD + ks, SPAD);
            #pragma unroll
            for (int i = 0; i < MF; i++)
                #pragma unroll
                for (int j = 0; j < NF; j++)
                    wmma::mma_sync(acc[i][j], af[i], bff[j], acc[i][j]);
        }
        __syncthreads();
    }

    #pragma unroll
    for (int i = 0; i < MF; i++) {
        int r0 = bm + wm * TM + i * 16;
        #pragma unroll
        for (int j = 0; j < NF; j++) {
            int c0 = bn + wn * TN + j * 16;
            if (c0 < N) {
                wmma::store_matrix_sync(C + (size_t)r0 * ldc + c0, acc[i][j], ldc, wmma::mem_row_major);
            }
        }
    }
}

// ---------------- causal depthwise conv (DC=4) + silu ----------------------
__global__ void conv_silu_kernel(const float* __restrict__ xz,
                                 const float* __restrict__ cw,
                                 const float* __restrict__ cb,
                                 float* __restrict__ xc,
                                 bf16* __restrict__ xcb)
{
    int idx = blockIdx.x * 256 + threadIdx.x;
    int d = idx & (DI - 1);
    int m = idx >> 11;
    int l = m & (LL - 1);
    const float* p = xz + (size_t)m * (2*DI) + d;
    float w0 = cw[d*4+0], w1 = cw[d*4+1], w2 = cw[d*4+2], w3 = cw[d*4+3];
    float acc = cb[d] + w3 * p[0];
    if (l >= 1) acc += w2 * p[-(2*DI)];
    if (l >= 2) acc += w1 * p[-2*(2*DI)];
    if (l >= 3) acc += w0 * p[-3*(2*DI)];
    float r = acc / (1.f + __expf(-acc));
    xc[(size_t)m * DI + d] = r;
    xcb[(size_t)m * DI + d] = __float2bfloat16(r);
}

// =============== chunked selective scan =====================================
__device__ __forceinline__ void scan_decode(int gid, int& b, int& ch, int& d, int& s)
{
    s = gid & 15;
    int dlo = (gid >> 4) & 1;
    int rest = gid >> 5;
    int dpair = rest & 1023;
    int rest2 = rest >> 10;
    ch = rest2 & (NCH - 1);
    b = rest2 >> 4;
    d = dpair * 2 + dlo;
}

// phase 1: per-chunk (P = prod a, U = folded sum), h0 = 0
__global__ void scan_p1_kernel(const float* __restrict__ dt,
                               const float* __restrict__ xc,
                               const float* __restrict__ dbl,
                               const float* __restrict__ A_log,
                               float* __restrict__ P, float* __restrict__ U)
{
    int gid = blockIdx.x * 256 + threadIdx.x;
    int b, ch, d, s;
    scan_decode(gid, b, ch, d, s);
    float A_s2 = -__expf(A_log[d * DS + s]) * 1.4426950408889634f;  // log2e folded
    float Pv = 1.f, Uv = 0.f;
    size_t mbase = (size_t)b * LL + ch * CH;
    #pragma unroll 4
    for (int l = 0; l < CH; l++) {
        size_t m = mbase + l;
        float dtv = dt[m * DI + d];
        float xv  = xc[m * DI + d];
        float Bv  = dbl[m * 96 + DTR + s];
        float a = exp2f(dtv * A_s2);
        Pv *= a;
        Uv = fmaf(a, Uv, dtv * xv * Bv);
    }
    size_t idx = (((size_t)b * DI + d) * DS + s) * NCH + ch;
    P[idx] = Pv;
    U[idx] = Uv;
}

// phase 2: compose chunk summaries -> h at chunk start
__global__ void scan_p2_kernel(const float* __restrict__ P,
                               const float* __restrict__ U,
                               float* __restrict__ H)
{
    int gid = blockIdx.x * 256 + threadIdx.x;
    size_t base = (size_t)gid * NCH;
    float h = 0.f;
    #pragma unroll
    for (int ch = 0; ch < NCH; ch++) {
        H[base + ch] = h;
        h = fmaf(P[base + ch], h, U[base + ch]);
    }
}

// phase 3: replay chunk from h0, project with C, gate with silu(z), write y
__global__ void scan_p3_kernel(const float* __restrict__ dt,
                               const float* __restrict__ xc,
                               const float* __restrict__ dbl,
                               const float* __restrict__ xz,
                               const float* __restrict__ A_log,
                               const float* __restrict__ Dp,
                               const float* __restrict__ H,
                               bf16* __restrict__ y)
{
    int gid = blockIdx.x * 256 + threadIdx.x;
    int b, ch, d, s;
    scan_decode(gid, b, ch, d, s);
    float A_s2 = -__expf(A_log[d * DS + s]) * 1.4426950408889634f;
    float D_d = Dp[d];
    float h = H[(((size_t)b * DI + d) * DS + s) * NCH + ch];
    size_t mbase = (size_t)b * LL + ch * CH;
    #pragma unroll 2
    for (int l = 0; l < CH; l++) {
        size_t m = mbase + l;
        float dtv = dt[m * DI + d];
        float xv  = xc[m * DI + d];
        float Bv  = dbl[m * 96 + DTR + s];
        float Cv  = dbl[m * 96 + DTR + DS + s];
        float a = exp2f(dtv * A_s2);
        h = fmaf(a, h, dtv * xv * Bv);
        float p = h * Cv;
        p += __shfl_xor_sync(0xffffffffu, p, 8);
        p += __shfl_xor_sync(0xffffffffu, p, 4);
        p += __shfl_xor_sync(0xffffffffu, p, 2);
        p += __shfl_xor_sync(0xffffffffu, p, 1);
        if (s == 0) {
            float zv = xz[m * (2*DI) + DI + d];
            float yy = p + xv * D_d;
            y[m * DI + d] = __float2bfloat16(yy * (zv / (1.f + __expf(-zv))));
        }
    }
}

// ---------------- launcher -------------------------------------------------
extern "C" void kernel_launch(void* const* d_in, const int* in_sizes, int n_in,
                              void* d_out, int out_size)
{
    const float* x      = (const float*)d_in[0];
    const float* ln_g   = (const float*)d_in[1];
    const float* ln_b   = (const float*)d_in[2];
    const float* W_in   = (const float*)d_in[3];
    const float* conv_w = (const float*)d_in[4];
    const float* conv_b = (const float*)d_in[5];
    const float* W_xp   = (const float*)d_in[6];
    const float* W_dt   = (const float*)d_in[7];
    const float* b_dt   = (const float*)d_in[8];
    const float* A_log  = (const float*)d_in[9];
    const float* Dp     = (const float*)d_in[10];
    const float* W_out  = (const float*)d_in[11];
    float* out = (float*)d_out;

    float *xz, *xc, *dbl, *dtb, *Pb, *Ub, *Hb;
    bf16 *xnb, *xcb, *dtlo, *yb, *Winb, *Wxpb, *Wdtb, *Woutb;
    cudaGetSymbolAddress((void**)&xz,   g_xz);
    cudaGetSymbolAddress((void**)&xc,   g_xc);
    cudaGetSymbolAddress((void**)&dbl,  g_dbl);
    cudaGetSymbolAddress((void**)&dtb,  g_dt);
    cudaGetSymbolAddress((void**)&xnb,  g_xnb);
    cudaGetSymbolAddress((void**)&xcb,  g_xcb);
    cudaGetSymbolAddress((void**)&dtlo, g_dtlo);
    cudaGetSymbolAddress((void**)&yb,   g_yb);
    cudaGetSymbolAddress((void**)&Winb, g_Winb);
    cudaGetSymbolAddress((void**)&Wxpb, g_Wxpb);
    cudaGetSymbolAddress((void**)&Wdtb, g_Wdtb);
    cudaGetSymbolAddress((void**)&Woutb,g_Woutb);
    cudaGetSymbolAddress((void**)&Pb,   g_P);
    cudaGetSymbolAddress((void**)&Ub,   g_U);
    cudaGetSymbolAddress((void**)&Hb,   g_H);

    constexpr int SM_MMA = 4 * (128 + 128) * 40 * 2;          // 81920
    constexpr int SM_64  = (64 + 128) * SPAD * 2 * STAGES;    // 46080
    cudaFuncSetAttribute(mma_gemm_kernel<0>, cudaFuncAttributeMaxDynamicSharedMemorySize, SM_MMA);
    cudaFuncSetAttribute(mma_gemm_kernel<1>, cudaFuncAttributeMaxDynamicSharedMemorySize, SM_MMA);
    cudaFuncSetAttribute(mma_gemm_kernel<2>, cudaFuncAttributeMaxDynamicSharedMemorySize, SM_MMA);
    cudaFuncSetAttribute(hgemm_kernel<64,128,2,4,0>, cudaFuncAttributeMaxDynamicSharedMemorySize, SM_64);

    // Launch order arranged so GEMM1 is launch #4 (ncu captures launch #4).
    // 1. W_in -> bf16
    f2bf_kernel<<<((2*DI*DM)/4 + 255)/256, 256>>>(W_in,  Winb, 2*DI*DM);
    // 2. LayerNorm -> bf16
    layernorm_kernel<<<MM, 256>>>(x, ln_g, ln_b, xnb);
    // 3. W_xp -> bf16 (independent filler)
    f2bf_kernel<<<((96*DI)/4 + 255)/256, 256>>>(W_xp,  Wxpb, 96*DI);
    // 4. xz = xn @ W_in^T   [8192 x 4096], K=1024   <-- PROFILED
    mma_gemm_kernel<0><<<dim3(4096/128, MM/128), 256, SM_MMA>>>(
        xnb, DM, Winb, DM, xz, 2*DI, DM, nullptr);
    // 5. causal conv + silu -> xc
    conv_silu_kernel<<<(MM*DI)/256, 256>>>(xz, conv_w, conv_b, xc, xcb);
    // 6. W_dt -> bf16
    f2bf_kernel<<<((DI*DTR)/4 + 255)/256, 256>>>(W_dt,  Wdtb, DI*DTR);
    // 7. dbl = xc @ W_xp^T  [8192 x 96], K=2048  (wmma)
    hgemm_kernel<64,128,2,4,0><<<dim3(1, MM/64), 256, SM_64>>>(
        xcb, DI, Wxpb, DI, dbl, 96, 96, DI, nullptr);
    // 8. dt_lo -> bf16
    dtlo_kernel<<<(MM*DTR)/256, 256>>>(dbl, dtlo);
    // 9. W_out -> bf16
    f2bf_kernel<<<((DM*DI)/4 + 255)/256, 256>>>(W_out, Woutb, DM*DI);
    // 10. dt = softplus(dt_lo @ W_dt^T + b_dt)  (fused fast-softplus epilogue)
    mma_gemm_kernel<2><<<dim3(DI/128, MM/128), 256, SM_MMA>>>(
        dtlo, DTR, Wdtb, DTR, dtb, DI, DTR, b_dt);
    // 11-13. chunked selective scan
    scan_p1_kernel<<<(BB*NCH*DI*DS)/256, 256>>>(dtb, xc, dbl, A_log, Pb, Ub);
    scan_p2_kernel<<<(BB*DI*DS)/256, 256>>>(Pb, Ub, Hb);
    scan_p3_kernel<<<(BB*NCH*DI*DS)/256, 256>>>(dtb, xc, dbl, xz, A_log, Dp, Hb, yb);
    // 14. out = x + y @ W_out^T  [8192 x 1024], K=2048
    mma_gemm_kernel<1><<<dim3(DM/128, MM/128), 256, SM_MMA>>>(
        yb, DI, Woutb, DI, out, DM, DI, x);
}

// round 9
// speedup vs baseline: 6.7658x; 1.7037x over previous
#include <cuda_runtime.h>
#include <cuda_bf16.h>
#include <mma.h>
#include <cstdint>

using namespace nvcuda;
typedef __nv_bfloat16 bf16;

#define BB    2
#define LL    4096
#define DM    1024
#define DS    16
#define DI    2048
#define DTR   64
#define MM    (BB*LL)          // 8192
#define CH    128
#define NCH   (LL/CH)          // 32

// ---------------- scratch (device globals) ---------------------------------
__device__ float g_xz [ (size_t)MM * (2*DI) ];    // 8192x4096 (xs | z) fp32
__device__ float g_xc [ (size_t)MM * DI ];        // fp32 (scan)
__device__ float g_dbl[ (size_t)MM * 96 ];        // dt_lo64 | B16 | C16  fp32
__device__ float g_dt [ (size_t)MM * DI ];        // fp32
__device__ bf16  g_xnb [ (size_t)MM * DM ];
__device__ bf16  g_xcb [ (size_t)MM * DI ];
__device__ bf16  g_dtlo[ (size_t)MM * DTR ];
__device__ bf16  g_yb  [ (size_t)MM * DI ];
__device__ bf16  g_Winb [ (size_t)(2*DI) * DM ];
__device__ bf16  g_Wxpb [ (size_t)96 * DI ];
__device__ bf16  g_Wdtb [ (size_t)DI * DTR ];
__device__ bf16  g_Woutb[ (size_t)DM * DI ];
// scan chunk buffers, layout idx(b,ch,s,d) = ((b*NCH+ch)*DS+s)*DI + d
__device__ float g_P [ (size_t)BB * NCH * DS * DI ];
__device__ float g_U [ (size_t)BB * NCH * DS * DI ];
__device__ float g_H [ (size_t)BB * NCH * DS * DI ];

#define LOG2E 1.4426950408889634f

// ======================= helpers ============================================
__device__ __forceinline__ void cp_async16(uint32_t saddr, const void* gptr) {
    asm volatile("cp.async.cg.shared.global [%0], [%1], 16;\n" :: "r"(saddr), "l"(gptr));
}
__device__ __forceinline__ void ldsm_x4(uint32_t* r, uint32_t addr) {
    asm volatile("ldmatrix.sync.aligned.m8n8.x4.shared.b16 {%0,%1,%2,%3}, [%4];"
        : "=r"(r[0]), "=r"(r[1]), "=r"(r[2]), "=r"(r[3]) : "r"(addr));
}
__device__ __forceinline__ void mma16816(float* d, const uint32_t* a, uint32_t b0, uint32_t b1) {
    asm volatile("mma.sync.aligned.m16n8k16.row.col.f32.bf16.bf16.f32 "
        "{%0,%1,%2,%3}, {%4,%5,%6,%7}, {%8,%9}, {%0,%1,%2,%3};"
        : "+f"(d[0]), "+f"(d[1]), "+f"(d[2]), "+f"(d[3])
        : "r"(a[0]), "r"(a[1]), "r"(a[2]), "r"(a[3]), "r"(b0), "r"(b1));
}
__device__ __forceinline__ float fast_softplus(float v) {
    return (v > 15.f) ? v : __logf(1.f + __expf(v));
}

// ======================= mma.sync GEMM (2 CTAs/SM) ==========================
template<int EPI>
__global__ __launch_bounds__(256, 2)
void mma_gemm_kernel(const bf16* __restrict__ A, int lda,
                     const bf16* __restrict__ W, int ldb,
                     float* __restrict__ C, int ldc,
                     int K, const float* __restrict__ aux)
{
    constexpr int BM = 128, BN = 128, BK = 32, NS = 4, SP = 40;
    constexpr int ASZ = BM * SP;
    constexpr int SSZ = (BM + BN) * SP;

    extern __shared__ bf16 sm2[];
    const int tid  = threadIdx.x;
    const int lane = tid & 31;
    const int wid  = tid >> 5;
    const int wm   = wid >> 2;
    const int wn   = wid & 3;
    const int bm   = blockIdx.y * BM;
    const int bn   = blockIdx.x * BN;

    auto prefetch = [&](int s, int kt) {
        const int k0 = kt * BK;
        uint32_t base = (uint32_t)__cvta_generic_to_shared(sm2 + s * SSZ);
        #pragma unroll
        for (int i = 0; i < 2; i++) {
            int e = i * 256 + tid;
            int r = e >> 2, c = e & 3;
            cp_async16(base + (r * SP + c * 8) * 2,
                       A + (size_t)(bm + r) * lda + k0 + c * 8);
        }
        uint32_t baseB = base + ASZ * 2;
        #pragma unroll
        for (int i = 0; i < 2; i++) {
            int e = i * 256 + tid;
            int r = e >> 2, c = e & 3;
            cp_async16(baseB + (r * SP + c * 8) * 2,
                       W + (size_t)(bn + r) * ldb + k0 + c * 8);
        }
    };

    float acc[4][4][4];
    #pragma unroll
    for (int i = 0; i < 4; i++)
        #pragma unroll
        for (int j = 0; j < 4; j++)
            #pragma unroll
            for (int e = 0; e < 4; e++) acc[i][j][e] = 0.f;

    const int T = K / BK;
    #pragma unroll
    for (int s = 0; s < NS - 1; s++) {
        if (s < T) prefetch(s, s);
        asm volatile("cp.async.commit_group;\n");
    }

    for (int t = 0; t < T; t++) {
        int tn = t + NS - 1;
        if (tn < T) prefetch(tn % NS, tn);
        asm volatile("cp.async.commit_group;\n");
        asm volatile("cp.async.wait_group %0;\n" :: "n"(NS - 1));
        __syncthreads();

        uint32_t abase = (uint32_t)__cvta_generic_to_shared(sm2 + (t % NS) * SSZ);
        uint32_t bbase = abase + ASZ * 2;
        #pragma unroll
        for (int k16 = 0; k16 < 2; k16++) {
            const int half = lane >> 4;
            uint32_t af[4][4], bfr[2][4];
            #pragma unroll
            for (int i = 0; i < 4; i++) {
                int row = wm * 64 + i * 16 + (lane & 15);
                ldsm_x4(af[i], abase + (row * SP + (k16 * 2 + half) * 8) * 2);
            }
            #pragma unroll
            for (int jp = 0; jp < 2; jp++) {
                int row = wn * 32 + jp * 16 + (lane & 15);
                ldsm_x4(bfr[jp], bbase + (row * SP + (k16 * 2 + half) * 8) * 2);
            }
            #pragma unroll
            for (int i = 0; i < 4; i++)
                #pragma unroll
                for (int jp = 0; jp < 2; jp++) {
                    mma16816(acc[i][2*jp],   af[i], bfr[jp][0], bfr[jp][2]);
                    mma16816(acc[i][2*jp+1], af[i], bfr[jp][1], bfr[jp][3]);
                }
        }
        __syncthreads();
    }

    const int r0 = bm + wm * 64 + (lane >> 2);
    const int c0 = bn + wn * 32 + (lane & 3) * 2;
    #pragma unroll
    for (int i = 0; i < 4; i++) {
        #pragma unroll
        for (int j = 0; j < 4; j++) {
            int r = r0 + i * 16;
            int c = c0 + j * 8;
            float v0 = acc[i][j][0], v1 = acc[i][j][1];
            float v2 = acc[i][j][2], v3 = acc[i][j][3];
            if (EPI == 1) {
                const float2 a0 = *(const float2*)(aux + (size_t)r * ldc + c);
                const float2 a1 = *(const float2*)(aux + (size_t)(r+8) * ldc + c);
                v0 += a0.x; v1 += a0.y; v2 += a1.x; v3 += a1.y;
            } else if (EPI == 2) {
                float b0 = aux[c], b1 = aux[c+1];
                v0 = fast_softplus(v0 + b0);
                v1 = fast_softplus(v1 + b1);
                v2 = fast_softplus(v2 + b0);
                v3 = fast_softplus(v3 + b1);
            }
            *(float2*)(C + (size_t)r * ldc + c)     = make_float2(v0, v1);
            *(float2*)(C + (size_t)(r+8) * ldc + c) = make_float2(v2, v3);
        }
    }
}

// ---------------- fp32 -> bf16 convert -------------------------------------
__global__ void f2bf_kernel(const float* __restrict__ src, bf16* __restrict__ dst, int n)
{
    int i = (blockIdx.x * 256 + threadIdx.x) * 4;
    if (i < n) {
        float4 v = *(const float4*)(src + i);
        __nv_bfloat162* d = (__nv_bfloat162*)(dst + i);
        d[0] = __floats2bfloat162_rn(v.x, v.y);
        d[1] = __floats2bfloat162_rn(v.z, v.w);
    }
}

__global__ void dtlo_kernel(const float* __restrict__ dbl, bf16* __restrict__ dtlo)
{
    int idx = blockIdx.x * 256 + threadIdx.x;
    int m = idx >> 6, r = idx & 63;
    dtlo[idx] = __float2bfloat16(dbl[(size_t)m * 96 + r]);
}

// ---------------- layernorm -> bf16 ----------------------------------------
__global__ void layernorm_kernel(const float* __restrict__ x,
                                 const float* __restrict__ g,
                                 const float* __restrict__ b,
                                 bf16* __restrict__ o)
{
    __shared__ float red[64];
    int row = blockIdx.x;
    int t = threadIdx.x;
    const float4* xr = (const float4*)(x + (size_t)row * DM);
    float4 v = xr[t];
    float s = v.x + v.y + v.z + v.w;
    float q = v.x*v.x + v.y*v.y + v.z*v.z + v.w*v.w;
    #pragma unroll
    for (int off = 16; off; off >>= 1) {
        s += __shfl_xor_sync(0xffffffffu, s, off);
        q += __shfl_xor_sync(0xffffffffu, q, off);
    }
    if ((t & 31) == 0) { red[t >> 5] = s; red[32 + (t >> 5)] = q; }
    __syncthreads();
    if (t < 32) {
        float s2 = (t < 8) ? red[t]      : 0.f;
        float q2 = (t < 8) ? red[32 + t] : 0.f;
        #pragma unroll
        for (int off = 4; off; off >>= 1) {
            s2 += __shfl_xor_sync(0xffffffffu, s2, off);
            q2 += __shfl_xor_sync(0xffffffffu, q2, off);
        }
        if (t == 0) { red[0] = s2; red[1] = q2; }
    }
    __syncthreads();
    float mu  = red[0] * (1.f / DM);
    float var = red[1] * (1.f / DM) - mu * mu;
    float inv = rsqrtf(var + 1e-5f);
    float4 gv = ((const float4*)g)[t];
    float4 bv = ((const float4*)b)[t];
    __nv_bfloat162* op = (__nv_bfloat162*)(o + (size_t)row * DM + t * 4);
    op[0] = __floats2bfloat162_rn((v.x - mu)*inv*gv.x + bv.x, (v.y - mu)*inv*gv.y + bv.y);
    op[1] = __floats2bfloat162_rn((v.z - mu)*inv*gv.z + bv.z, (v.w - mu)*inv*gv.w + bv.w);
}

// ---------------- bf16 wmma GEMM (W_xp only) -------------------------------
#define STAGES 3
#define SPAD   40

template<int BM, int BN, int WGM, int WGN, int EPI>
__global__ __launch_bounds__(WGM*WGN*32)
void hgemm_kernel(const bf16* __restrict__ A, int lda,
                  const bf16* __restrict__ W, int ldb,
                  float* __restrict__ C, int ldc,
                  int N, int K,
                  const float* __restrict__ addsrc)
{
    constexpr int TM = BM / WGM;
    constexpr int TN = BN / WGN;
    constexpr int MF = TM / 16;
    constexpr int NF = TN / 16;
    constexpr int NT = WGM * WGN * 32;
    constexpr int SSZ = (BM + BN) * SPAD;

    extern __shared__ bf16 smh[];

    int tid = threadIdx.x;
    int wid = tid >> 5;
    int wm  = wid / WGN;
    int wn  = wid % WGN;
    int bm  = blockIdx.y * BM;
    int bn  = blockIdx.x * BN;

    auto prefetch = [&](int p, int k0) {
        uint32_t sbase = (uint32_t)__cvta_generic_to_shared(smh + p * SSZ);
        #pragma unroll
        for (int i = 0; i < (BM * 4) / NT; i++) {
            int e = i * NT + tid;
            int row = e >> 2, c8 = (e & 3) * 8;
            cp_async16(sbase + (row * SPAD + c8) * 2,
                       A + (size_t)(bm + row) * lda + k0 + c8);
        }
        uint32_t sbase2 = sbase + BM * SPAD * 2;
        #pragma unroll
        for (int i = 0; i < (BN * 4) / NT; i++) {
            int e = i * NT + tid;
            int row = e >> 2, c8 = (e & 3) * 8;
            int n = bn + row; if (n >= N) n = N - 1;
            cp_async16(sbase2 + (row * SPAD + c8) * 2,
                       W + (size_t)n * ldb + k0 + c8);
        }
    };

    wmma::fragment<wmma::accumulator, 16, 16, 16, float> acc[MF][NF];
    #pragma unroll
    for (int i = 0; i < MF; i++)
        #pragma unroll
        for (int j = 0; j < NF; j++) wmma::fill_fragment(acc[i][j], 0.f);

    int T = K / 32;
    #pragma unroll
    for (int s = 0; s < STAGES - 1; s++) {
        if (s < T) prefetch(s, s * 32);
        asm volatile("cp.async.commit_group;\n");
    }

    for (int t = 0; t < T; t++) {
        asm volatile("cp.async.wait_group %0;\n" :: "n"(STAGES - 2));
        __syncthreads();

        int pn = t + STAGES - 1;
        if (pn < T) prefetch(pn % STAGES, pn * 32);
        asm volatile("cp.async.commit_group;\n");

        const bf16* As = smh + (t % STAGES) * SSZ;
        const bf16* Ws = As + BM * SPAD;
        #pragma unroll
        for (int ks = 0; ks < 32; ks += 16) {
            wmma::fragment<wmma::matrix_a, 16, 16, 16, bf16, wmma::row_major> af[MF];
            wmma::fragment<wmma::matrix_b, 16, 16, 16, bf16, wmma::col_major> bff[NF];
            #pragma unroll
            for (int i = 0; i < MF; i++)
                wmma::load_matrix_sync(af[i], As + (wm * TM + i * 16) * SPAD + ks, SPAD);
            #pragma unroll
            for (int j = 0; j < NF; j++)
                wmma::load_matrix_sync(bff[j], Ws + (wn * TN + j * 16) * SPAD + ks, SPAD);
            #pragma unroll
            for (int i = 0; i < MF; i++)
                #pragma unroll
                for (int j = 0; j < NF; j++)
                    wmma::mma_sync(acc[i][j], af[i], bff[j], acc[i][j]);
        }
        __syncthreads();
    }

    #pragma unroll
    for (int i = 0; i < MF; i++) {
        int r0 = bm + wm * TM + i * 16;
        #pragma unroll
        for (int j = 0; j < NF; j++) {
            int c0 = bn + wn * TN + j * 16;
            if (c0 < N) {
                wmma::store_matrix_sync(C + (size_t)r0 * ldc + c0, acc[i][j], ldc, wmma::mem_row_major);
            }
        }
    }
}

// ---------------- causal depthwise conv (DC=4) + silu, 2 channels/thread ---
__global__ void conv_silu_kernel(const float* __restrict__ xz,
                                 const float* __restrict__ cw,
                                 const float* __restrict__ cb,
                                 float* __restrict__ xc,
                                 bf16* __restrict__ xcb)
{
    int idx = blockIdx.x * 256 + threadIdx.x;      // over M*DI/2
    int dp = idx & (DI/2 - 1);
    int m  = idx >> 10;
    int l  = m & (LL - 1);
    int d  = dp * 2;
    const float* p = xz + (size_t)m * (2*DI) + d;
    float4 wa = *(const float4*)(cw + d * 4);
    float4 wb = *(const float4*)(cw + d * 4 + 4);
    float2 bias = *(const float2*)(cb + d);
    float2 v0 = *(const float2*)p;
    float ax = fmaf(wa.w, v0.x, bias.x);
    float ay = fmaf(wb.w, v0.y, bias.y);
    if (l >= 1) { float2 v = *(const float2*)(p - 2*DI);  ax = fmaf(wa.z, v.x, ax); ay = fmaf(wb.z, v.y, ay); }
    if (l >= 2) { float2 v = *(const float2*)(p - 4*DI);  ax = fmaf(wa.y, v.x, ax); ay = fmaf(wb.y, v.y, ay); }
    if (l >= 3) { float2 v = *(const float2*)(p - 6*DI);  ax = fmaf(wa.x, v.x, ax); ay = fmaf(wb.x, v.y, ay); }
    float rx = ax / (1.f + __expf(-ax));
    float ry = ay / (1.f + __expf(-ay));
    *(float2*)(xc + (size_t)m * DI + d) = make_float2(rx, ry);
    *(__nv_bfloat162*)(xcb + (size_t)m * DI + d) = __floats2bfloat162_rn(rx, ry);
}

// =============== chunked selective scan (16 states per thread) ==============
// buffers laid out idx(b,ch,s,d) = ((b*NCH+ch)*DS+s)*DI + d

// phase 1: per-chunk P = prod(a), U = fold; thread owns (b,ch,d), 16 states.
__global__ __launch_bounds__(256)
void scan_p1_kernel(const float* __restrict__ dt,
                    const float* __restrict__ xc,
                    const float* __restrict__ dbl,
                    const float* __restrict__ A_log,
                    float* __restrict__ P, float* __restrict__ U)
{
    int gid = blockIdx.x * 256 + threadIdx.x;   // BB*NCH*DI = 131072
    int d  = gid & (DI - 1);
    int ch = (gid >> 11) & (NCH - 1);
    int b  = gid >> 16;

    float A2[DS], Pv[DS], Uv[DS];
    #pragma unroll
    for (int s = 0; s < DS; s++) {
        A2[s] = -__expf(A_log[d * DS + s]) * LOG2E;
        Pv[s] = 1.f; Uv[s] = 0.f;
    }
    size_t mbase = (size_t)b * LL + ch * CH;
    for (int l = 0; l < CH; l++) {
        size_t m = mbase + l;
        float dtv = dt[m * DI + d];
        float xv  = xc[m * DI + d];
        float dx  = dtv * xv;
        const float4* Bp = (const float4*)(dbl + m * 96 + DTR);
        float4 B0 = Bp[0], B1 = Bp[1], B2 = Bp[2], B3 = Bp[3];
        float Bv[DS] = {B0.x,B0.y,B0.z,B0.w, B1.x,B1.y,B1.z,B1.w,
                        B2.x,B2.y,B2.z,B2.w, B3.x,B3.y,B3.z,B3.w};
        #pragma unroll
        for (int s = 0; s < DS; s++) {
            float a = exp2f(dtv * A2[s]);
            Pv[s] *= a;
            Uv[s] = fmaf(a, Uv[s], dx * Bv[s]);
        }
    }
    size_t base = ((size_t)(b * NCH + ch) * DS) * DI + d;
    #pragma unroll
    for (int s = 0; s < DS; s++) {
        P[base + (size_t)s * DI] = Pv[s];
        U[base + (size_t)s * DI] = Uv[s];
    }
}

// phase 2: compose chunk summaries -> h at chunk start; thread owns (b,s,d)
__global__ void scan_p2_kernel(const float* __restrict__ P,
                               const float* __restrict__ U,
                               float* __restrict__ H)
{
    int gid = blockIdx.x * 256 + threadIdx.x;   // BB*DS*DI = 65536
    int d = gid & (DI - 1);
    int s = (gid >> 11) & (DS - 1);
    int b = gid >> 15;
    float h = 0.f;
    #pragma unroll
    for (int ch = 0; ch < NCH; ch++) {
        size_t idx = ((size_t)((b * NCH + ch) * DS + s)) * DI + d;
        H[idx] = h;
        h = fmaf(P[idx], h, U[idx]);
    }
}

// phase 3: replay chunk from h0, project with C, gate with silu(z)
__global__ __launch_bounds__(256)
void scan_p3_kernel(const float* __restrict__ dt,
                    const float* __restrict__ xc,
                    const float* __restrict__ dbl,
                    const float* __restrict__ xz,
                    const float* __restrict__ A_log,
                    const float* __restrict__ Dp,
                    const float* __restrict__ H,
                    bf16* __restrict__ y)
{
    int gid = blockIdx.x * 256 + threadIdx.x;   // 131072
    int d  = gid & (DI - 1);
    int ch = (gid >> 11) & (NCH - 1);
    int b  = gid >> 16;

    float A2[DS], h[DS];
    size_t hbase = ((size_t)(b * NCH + ch) * DS) * DI + d;
    #pragma unroll
    for (int s = 0; s < DS; s++) {
        A2[s] = -__expf(A_log[d * DS + s]) * LOG2E;
        h[s] = H[hbase + (size_t)s * DI];
    }
    float D_d = Dp[d];
    size_t mbase = (size_t)b * LL + ch * CH;
    for (int l = 0; l < CH; l++) {
        size_t m = mbase + l;
        float dtv = dt[m * DI + d];
        float xv  = xc[m * DI + d];
        float dx  = dtv * xv;
        const float4* Bp = (const float4*)(dbl + m * 96 + DTR);
        float4 B0 = Bp[0], B1 = Bp[1], B2 = Bp[2], B3 = Bp[3];
        const float4* Cp = (const float4*)(dbl + m * 96 + DTR + DS);
        float4 C0 = Cp[0], C1 = Cp[1], C2 = Cp[2], C3 = Cp[3];
        float Bv[DS] = {B0.x,B0.y,B0.z,B0.w, B1.x,B1.y,B1.z,B1.w,
                        B2.x,B2.y,B2.z,B2.w, B3.x,B3.y,B3.z,B3.w};
        float Cv[DS] = {C0.x,C0.y,C0.z,C0.w, C1.x,C1.y,C1.z,C1.w,
                        C2.x,C2.y,C2.z,C2.w, C3.x,C3.y,C3.z,C3.w};
        float acc = 0.f;
        #pragma unroll
        for (int s = 0; s < DS; s++) {
            float a = exp2f(dtv * A2[s]);
            h[s] = fmaf(a, h[s], dx * Bv[s]);
            acc = fmaf(h[s], Cv[s], acc);
        }
        float zv = xz[m * (2*DI) + DI + d];
        float yy = fmaf(xv, D_d, acc);
        y[m * DI + d] = __float2bfloat16(yy * (zv / (1.f + __expf(-zv))));
    }
}

// ---------------- launcher -------------------------------------------------
extern "C" void kernel_launch(void* const* d_in, const int* in_sizes, int n_in,
                              void* d_out, int out_size)
{
    const float* x      = (const float*)d_in[0];
    const float* ln_g   = (const float*)d_in[1];
    const float* ln_b   = (const float*)d_in[2];
    const float* W_in   = (const float*)d_in[3];
    const float* conv_w = (const float*)d_in[4];
    const float* conv_b = (const float*)d_in[5];
    const float* W_xp   = (const float*)d_in[6];
    const float* W_dt   = (const float*)d_in[7];
    const float* b_dt   = (const float*)d_in[8];
    const float* A_log  = (const float*)d_in[9];
    const float* Dp     = (const float*)d_in[10];
    const float* W_out  = (const float*)d_in[11];
    float* out = (float*)d_out;

    float *xz, *xc, *dbl, *dtb, *Pb, *Ub, *Hb;
    bf16 *xnb, *xcb, *dtlo, *yb, *Winb, *Wxpb, *Wdtb, *Woutb;
    cudaGetSymbolAddress((void**)&xz,   g_xz);
    cudaGetSymbolAddress((void**)&xc,   g_xc);
    cudaGetSymbolAddress((void**)&dbl,  g_dbl);
    cudaGetSymbolAddress((void**)&dtb,  g_dt);
    cudaGetSymbolAddress((void**)&xnb,  g_xnb);
    cudaGetSymbolAddress((void**)&xcb,  g_xcb);
    cudaGetSymbolAddress((void**)&dtlo, g_dtlo);
    cudaGetSymbolAddress((void**)&yb,   g_yb);
    cudaGetSymbolAddress((void**)&Winb, g_Winb);
    cudaGetSymbolAddress((void**)&Wxpb, g_Wxpb);
    cudaGetSymbolAddress((void**)&Wdtb, g_Wdtb);
    cudaGetSymbolAddress((void**)&Woutb,g_Woutb);
    cudaGetSymbolAddress((void**)&Pb,   g_P);
    cudaGetSymbolAddress((void**)&Ub,   g_U);
    cudaGetSymbolAddress((void**)&Hb,   g_H);

    constexpr int SM_MMA = 4 * (128 + 128) * 40 * 2;          // 81920
    constexpr int SM_64  = (64 + 128) * SPAD * 2 * STAGES;    // 46080
    cudaFuncSetAttribute(mma_gemm_kernel<0>, cudaFuncAttributeMaxDynamicSharedMemorySize, SM_MMA);
    cudaFuncSetAttribute(mma_gemm_kernel<1>, cudaFuncAttributeMaxDynamicSharedMemorySize, SM_MMA);
    cudaFuncSetAttribute(mma_gemm_kernel<2>, cudaFuncAttributeMaxDynamicSharedMemorySize, SM_MMA);
    cudaFuncSetAttribute(hgemm_kernel<64,128,2,4,0>, cudaFuncAttributeMaxDynamicSharedMemorySize, SM_64);

    // 1. W_in -> bf16
    f2bf_kernel<<<((2*DI*DM)/4 + 255)/256, 256>>>(W_in,  Winb, 2*DI*DM);
    // 2. LayerNorm -> bf16
    layernorm_kernel<<<MM, 256>>>(x, ln_g, ln_b, xnb);
    // 3. W_xp -> bf16
    f2bf_kernel<<<((96*DI)/4 + 255)/256, 256>>>(W_xp,  Wxpb, 96*DI);
    // 4. xz = xn @ W_in^T   [8192 x 4096], K=1024   <-- PROFILED (launch #4)
    mma_gemm_kernel<0><<<dim3(4096/128, MM/128), 256, SM_MMA>>>(
        xnb, DM, Winb, DM, xz, 2*DI, DM, nullptr);
    // 5. causal conv + silu -> xc (2 ch/thread)
    conv_silu_kernel<<<(MM*DI/2)/256, 256>>>(xz, conv_w, conv_b, xc, xcb);
    // 6. W_dt -> bf16
    f2bf_kernel<<<((DI*DTR)/4 + 255)/256, 256>>>(W_dt,  Wdtb, DI*DTR);
    // 7. dbl = xc @ W_xp^T  [8192 x 96], K=2048
    hgemm_kernel<64,128,2,4,0><<<dim3(1, MM/64), 256, SM_64>>>(
        xcb, DI, Wxpb, DI, dbl, 96, 96, DI, nullptr);
    // 8. dt_lo -> bf16
    dtlo_kernel<<<(MM*DTR)/256, 256>>>(dbl, dtlo);
    // 9. W_out -> bf16
    f2bf_kernel<<<((DM*DI)/4 + 255)/256, 256>>>(W_out, Woutb, DM*DI);
    // 10. dt = softplus(dt_lo @ W_dt^T + b_dt)
    mma_gemm_kernel<2><<<dim3(DI/128, MM/128), 256, SM_MMA>>>(
        dtlo, DTR, Wdtb, DTR, dtb, DI, DTR, b_dt);
    // 11-13. chunked selective scan (16 states/thread)
    scan_p1_kernel<<<(BB*NCH*DI)/256, 256>>>(dtb, xc, dbl, A_log, Pb, Ub);
    scan_p2_kernel<<<(BB*DS*DI)/256, 256>>>(Pb, Ub, Hb);
    scan_p3_kernel<<<(BB*NCH*DI)/256, 256>>>(dtb, xc, dbl, xz, A_log, Dp, Hb, yb);
    // 14. out = x + y @ W_out^T  [8192 x 1024], K=2048
    mma_gemm_kernel<1><<<dim3(DM/128, MM/128), 256, SM_MMA>>>(
        yb, DI, Woutb, DI, out, DM, DI, x);
}

// round 10
// speedup vs baseline: 7.3331x; 1.0838x over previous
#include <cuda_runtime.h>
#include <cuda_bf16.h>
#include <mma.h>
#include <cstdint>

using namespace nvcuda;
typedef __nv_bfloat16 bf16;

#define BB    2
#define LL    4096
#define DM    1024
#define DS    16
#define DI    2048
#define DTR   64
#define MM    (BB*LL)          // 8192
#define CH    128
#define NCH   (LL/CH)          // 32

// ---------------- scratch (device globals) ---------------------------------
__device__ float g_xz [ (size_t)MM * (2*DI) ];    // 8192x4096 (xs | z) fp32
__device__ float g_xc [ (size_t)MM * DI ];        // fp32 (scan)
__device__ float g_dbl[ (size_t)MM * 96 ];        // dt_lo64 | B16 | C16  fp32
__device__ float g_dblp[ (size_t)4 * MM * 96 ];   // split-K partials
__device__ float g_dt [ (size_t)MM * DI ];        // fp32
__device__ bf16  g_xnb [ (size_t)MM * DM ];
__device__ bf16  g_xcb [ (size_t)MM * DI ];
__device__ bf16  g_dtlo[ (size_t)MM * DTR ];
__device__ bf16  g_yb  [ (size_t)MM * DI ];
__device__ bf16  g_Winb [ (size_t)(2*DI) * DM ];
__device__ bf16  g_Wxpb [ (size_t)96 * DI ];
__device__ bf16  g_Wdtb [ (size_t)DI * DTR ];
__device__ bf16  g_Woutb[ (size_t)DM * DI ];
// scan chunk buffers, layout idx(b,ch,s,d) = ((b*NCH+ch)*DS+s)*DI + d
__device__ float g_P [ (size_t)BB * NCH * DS * DI ];
__device__ float g_U [ (size_t)BB * NCH * DS * DI ];
__device__ float g_H [ (size_t)BB * NCH * DS * DI ];

#define LOG2E 1.4426950408889634f

// ======================= helpers ============================================
__device__ __forceinline__ void cp_async16(uint32_t saddr, const void* gptr) {
    asm volatile("cp.async.cg.shared.global [%0], [%1], 16;\n" :: "r"(saddr), "l"(gptr));
}
__device__ __forceinline__ void ldsm_x4(uint32_t* r, uint32_t addr) {
    asm volatile("ldmatrix.sync.aligned.m8n8.x4.shared.b16 {%0,%1,%2,%3}, [%4];"
        : "=r"(r[0]), "=r"(r[1]), "=r"(r[2]), "=r"(r[3]) : "r"(addr));
}
__device__ __forceinline__ void mma16816(float* d, const uint32_t* a, uint32_t b0, uint32_t b1) {
    asm volatile("mma.sync.aligned.m16n8k16.row.col.f32.bf16.bf16.f32 "
        "{%0,%1,%2,%3}, {%4,%5,%6,%7}, {%8,%9}, {%0,%1,%2,%3};"
        : "+f"(d[0]), "+f"(d[1]), "+f"(d[2]), "+f"(d[3])
        : "r"(a[0]), "r"(a[1]), "r"(a[2]), "r"(a[3]), "r"(b0), "r"(b1));
}
__device__ __forceinline__ float fast_softplus(float v) {
    return (v > 15.f) ? v : __logf(1.f + __expf(v));
}

// ======================= mma.sync GEMM (BK=64, 2-stage, 2 CTAs/SM) =========
//  C[M,N] = A[M,K] * W[N,K]^T   (bf16 in, fp32 out)
//  CTA 128x128, BK=64, 2-stage cp.async, warp tile 64x32 (2x4 warp grid).
//  EPI: 0 plain, 1 +aux residual, 2 softplus(v + aux[col]).
template<int EPI>
__global__ __launch_bounds__(256, 2)
void mma_gemm_kernel(const bf16* __restrict__ A, int lda,
                     const bf16* __restrict__ W, int ldb,
                     float* __restrict__ C, int ldc,
                     int K, const float* __restrict__ aux)
{
    constexpr int BM = 128, BN = 128, BK = 64, SP = 72;
    constexpr int ASZ = BM * SP;                // elems
    constexpr int SSZ = (BM + BN) * SP;         // 18432 elems = 36864 B/stage

    extern __shared__ bf16 sm2[];
    const int tid  = threadIdx.x;
    const int lane = tid & 31;
    const int wid  = tid >> 5;
    const int wm   = wid >> 2;
    const int wn   = wid & 3;
    const int bm   = blockIdx.y * BM;
    const int bn   = blockIdx.x * BN;

    auto prefetch = [&](int s, int kt) {
        const int k0 = kt * BK;
        uint32_t base = (uint32_t)__cvta_generic_to_shared(sm2 + s * SSZ);
        #pragma unroll
        for (int i = 0; i < 4; i++) {               // A: 1024 x 16B chunks
            int e = i * 256 + tid;
            int r = e >> 3, c = e & 7;
            cp_async16(base + (r * SP + c * 8) * 2,
                       A + (size_t)(bm + r) * lda + k0 + c * 8);
        }
        uint32_t baseB = base + ASZ * 2;
        #pragma unroll
        for (int i = 0; i < 4; i++) {               // B: 1024 x 16B chunks
            int e = i * 256 + tid;
            int r = e >> 3, c = e & 7;
            cp_async16(baseB + (r * SP + c * 8) * 2,
                       W + (size_t)(bn + r) * ldb + k0 + c * 8);
        }
    };

    float acc[4][4][4];
    #pragma unroll
    for (int i = 0; i < 4; i++)
        #pragma unroll
        for (int j = 0; j < 4; j++)
            #pragma unroll
            for (int e = 0; e < 4; e++) acc[i][j][e] = 0.f;

    const int T = K / BK;
    prefetch(0, 0);
    asm volatile("cp.async.commit_group;\n");

    for (int t = 0; t < T; t++) {
        if (t + 1 < T) {
            prefetch((t + 1) & 1, t + 1);
            asm volatile("cp.async.commit_group;\n");
            asm volatile("cp.async.wait_group 1;\n");
        } else {
            asm volatile("cp.async.wait_group 0;\n");
        }
        __syncthreads();

        uint32_t abase = (uint32_t)__cvta_generic_to_shared(sm2 + (t & 1) * SSZ);
        uint32_t bbase = abase + ASZ * 2;
        const int half = lane >> 4;
        #pragma unroll
        for (int k16 = 0; k16 < 4; k16++) {
            uint32_t af[4][4], bfr[2][4];
            #pragma unroll
            for (int i = 0; i < 4; i++) {
                int row = wm * 64 + i * 16 + (lane & 15);
                ldsm_x4(af[i], abase + (row * SP + (k16 * 2 + half) * 8) * 2);
            }
            #pragma unroll
            for (int jp = 0; jp < 2; jp++) {
                int row = wn * 32 + jp * 16 + (lane & 15);
                ldsm_x4(bfr[jp], bbase + (row * SP + (k16 * 2 + half) * 8) * 2);
            }
            #pragma unroll
            for (int i = 0; i < 4; i++)
                #pragma unroll
                for (int jp = 0; jp < 2; jp++) {
                    mma16816(acc[i][2*jp],   af[i], bfr[jp][0], bfr[jp][2]);
                    mma16816(acc[i][2*jp+1], af[i], bfr[jp][1], bfr[jp][3]);
                }
        }
        __syncthreads();
    }

    const int r0 = bm + wm * 64 + (lane >> 2);
    const int c0 = bn + wn * 32 + (lane & 3) * 2;
    #pragma unroll
    for (int i = 0; i < 4; i++) {
        #pragma unroll
        for (int j = 0; j < 4; j++) {
            int r = r0 + i * 16;
            int c = c0 + j * 8;
            float v0 = acc[i][j][0], v1 = acc[i][j][1];
            float v2 = acc[i][j][2], v3 = acc[i][j][3];
            if (EPI == 1) {
                const float2 a0 = *(const float2*)(aux + (size_t)r * ldc + c);
                const float2 a1 = *(const float2*)(aux + (size_t)(r+8) * ldc + c);
                v0 += a0.x; v1 += a0.y; v2 += a1.x; v3 += a1.y;
            } else if (EPI == 2) {
                float b0 = aux[c], b1 = aux[c+1];
                v0 = fast_softplus(v0 + b0);
                v1 = fast_softplus(v1 + b1);
                v2 = fast_softplus(v2 + b0);
                v3 = fast_softplus(v3 + b1);
            }
            *(float2*)(C + (size_t)r * ldc + c)     = make_float2(v0, v1);
            *(float2*)(C + (size_t)(r+8) * ldc + c) = make_float2(v2, v3);
        }
    }
}

// ---------------- fp32 -> bf16 convert -------------------------------------
__global__ void f2bf_kernel(const float* __restrict__ src, bf16* __restrict__ dst, int n)
{
    int i = (blockIdx.x * 256 + threadIdx.x) * 4;
    if (i < n) {
        float4 v = *(const float4*)(src + i);
        __nv_bfloat162* d = (__nv_bfloat162*)(dst + i);
        d[0] = __floats2bfloat162_rn(v.x, v.y);
        d[1] = __floats2bfloat162_rn(v.z, v.w);
    }
}

// ---------------- layernorm -> bf16 ----------------------------------------
__global__ void layernorm_kernel(const float* __restrict__ x,
                                 const float* __restrict__ g,
                                 const float* __restrict__ b,
                                 bf16* __restrict__ o)
{
    __shared__ float red[64];
    int row = blockIdx.x;
    int t = threadIdx.x;
    const float4* xr = (const float4*)(x + (size_t)row * DM);
    float4 v = xr[t];
    float s = v.x + v.y + v.z + v.w;
    float q = v.x*v.x + v.y*v.y + v.z*v.z + v.w*v.w;
    #pragma unroll
    for (int off = 16; off; off >>= 1) {
        s += __shfl_xor_sync(0xffffffffu, s, off);
        q += __shfl_xor_sync(0xffffffffu, q, off);
    }
    if ((t & 31) == 0) { red[t >> 5] = s; red[32 + (t >> 5)] = q; }
    __syncthreads();
    if (t < 32) {
        float s2 = (t < 8) ? red[t]      : 0.f;
        float q2 = (t < 8) ? red[32 + t] : 0.f;
        #pragma unroll
        for (int off = 4; off; off >>= 1) {
            s2 += __shfl_xor_sync(0xffffffffu, s2, off);
            q2 += __shfl_xor_sync(0xffffffffu, q2, off);
        }
        if (t == 0) { red[0] = s2; red[1] = q2; }
    }
    __syncthreads();
    float mu  = red[0] * (1.f / DM);
    float var = red[1] * (1.f / DM) - mu * mu;
    float inv = rsqrtf(var + 1e-5f);
    float4 gv = ((const float4*)g)[t];
    float4 bv = ((const float4*)b)[t];
    __nv_bfloat162* op = (__nv_bfloat162*)(o + (size_t)row * DM + t * 4);
    op[0] = __floats2bfloat162_rn((v.x - mu)*inv*gv.x + bv.x, (v.y - mu)*inv*gv.y + bv.y);
    op[1] = __floats2bfloat162_rn((v.z - mu)*inv*gv.z + bv.z, (v.w - mu)*inv*gv.w + bv.w);
}

// ---------------- bf16 wmma GEMM (W_xp, split-K via blockIdx.z) ------------
#define STAGES 3
#define SPAD   40

template<int BM, int BN, int WGM, int WGN>
__global__ __launch_bounds__(WGM*WGN*32)
void hgemm_kernel(const bf16* __restrict__ A, int lda,
                  const bf16* __restrict__ W, int ldb,
                  float* __restrict__ C, int ldc,
                  int N, int K,
                  int zk_off, size_t zc_off)
{
    constexpr int TM = BM / WGM;
    constexpr int TN = BN / WGN;
    constexpr int MF = TM / 16;
    constexpr int NF = TN / 16;
    constexpr int NT = WGM * WGN * 32;
    constexpr int SSZ = (BM + BN) * SPAD;

    extern __shared__ bf16 smh[];

    A += (size_t)blockIdx.z * zk_off;
    W += (size_t)blockIdx.z * zk_off;
    C += (size_t)blockIdx.z * zc_off;

    int tid = threadIdx.x;
    int wid = tid >> 5;
    int wm  = wid / WGN;
    int wn  = wid % WGN;
    int bm  = blockIdx.y * BM;
    int bn  = blockIdx.x * BN;

    auto prefetch = [&](int p, int k0) {
        uint32_t sbase = (uint32_t)__cvta_generic_to_shared(smh + p * SSZ);
        #pragma unroll
        for (int i = 0; i < (BM * 4) / NT; i++) {
            int e = i * NT + tid;
            int row = e >> 2, c8 = (e & 3) * 8;
            cp_async16(sbase + (row * SPAD + c8) * 2,
                       A + (size_t)(bm + row) * lda + k0 + c8);
        }
        uint32_t sbase2 = sbase + BM * SPAD * 2;
        #pragma unroll
        for (int i = 0; i < (BN * 4) / NT; i++) {
            int e = i * NT + tid;
            int row = e >> 2, c8 = (e & 3) * 8;
            int n = bn + row; if (n >= N) n = N - 1;
            cp_async16(sbase2 + (row * SPAD + c8) * 2,
                       W + (size_t)n * ldb + k0 + c8);
        }
    };

    wmma::fragment<wmma::accumulator, 16, 16, 16, float> acc[MF][NF];
    #pragma unroll
    for (int i = 0; i < MF; i++)
        #pragma unroll
        for (int j = 0; j < NF; j++) wmma::fill_fragment(acc[i][j], 0.f);

    int T = K / 32;
    #pragma unroll
    for (int s = 0; s < STAGES - 1; s++) {
        if (s < T) prefetch(s, s * 32);
        asm volatile("cp.async.commit_group;\n");
    }

    for (int t = 0; t < T; t++) {
        asm volatile("cp.async.wait_group %0;\n" :: "n"(STAGES - 2));
        __syncthreads();

        int pn = t + STAGES - 1;
        if (pn < T) prefetch(pn % STAGES, pn * 32);
        asm volatile("cp.async.commit_group;\n");

        const bf16* As = smh + (t % STAGES) * SSZ;
        const bf16* Ws = As + BM * SPAD;
        #pragma unroll
        for (int ks = 0; ks < 32; ks += 16) {
            wmma::fragment<wmma::matrix_a, 16, 16, 16, bf16, wmma::row_major> af[MF];
            wmma::fragment<wmma::matrix_b, 16, 16, 16, bf16, wmma::col_major> bff[NF];
            #pragma unroll
            for (int i = 0; i < MF; i++)
                wmma::load_matrix_sync(af[i], As + (wm * TM + i * 16) * SPAD + ks, SPAD);
            #pragma unroll
            for (int j = 0; j < NF; j++)
                wmma::load_matrix_sync(bff[j], Ws + (wn * TN + j * 16) * SPAD + ks, SPAD);
            #pragma unroll
            for (int i = 0; i < MF; i++)
                #pragma unroll
                for (int j = 0; j < NF; j++)
                    wmma::mma_sync(acc[i][j], af[i], bff[j], acc[i][j]);
        }
        __syncthreads();
    }

    #pragma unroll
    for (int i = 0; i < MF; i++) {
        int r0 = bm + wm * TM + i * 16;
        #pragma unroll
        for (int j = 0; j < NF; j++) {
            int c0 = bn + wn * TN + j * 16;
            if (c0 < N) {
                wmma::store_matrix_sync(C + (size_t)r0 * ldc + c0, acc[i][j], ldc, wmma::mem_row_major);
            }
        }
    }
}

// ---------------- split-K reduce + dtlo extraction -------------------------
__global__ void dbl_reduce_kernel(const float* __restrict__ dblp,
                                  float* __restrict__ dbl,
                                  bf16* __restrict__ dtlo)
{
    int idx = blockIdx.x * 256 + threadIdx.x;   // over MM*96
    const size_t STR = (size_t)MM * 96;
    float v = dblp[idx] + dblp[idx + STR] + dblp[idx + 2*STR] + dblp[idx + 3*STR];
    dbl[idx] = v;
    int m = idx / 96, c = idx - m * 96;
    if (c < DTR) dtlo[m * DTR + c] = __float2bfloat16(v);
}

// ---------------- causal depthwise conv (DC=4) + silu, 4 channels/thread ---
__global__ void conv_silu_kernel(const float* __restrict__ xz,
                                 const float* __restrict__ cw,
                                 const float* __restrict__ cb,
                                 float* __restrict__ xc,
                                 bf16* __restrict__ xcb)
{
    int idx = blockIdx.x * 256 + threadIdx.x;      // over M*DI/4
    int dq = idx & (DI/4 - 1);
    int m  = idx >> 9;
    int l  = m & (LL - 1);
    int d  = dq * 4;
    const float* p = xz + (size_t)m * (2*DI) + d;
    float4 w0 = *(const float4*)(cw + (d+0) * 4);
    float4 w1 = *(const float4*)(cw + (d+1) * 4);
    float4 w2 = *(const float4*)(cw + (d+2) * 4);
    float4 w3 = *(const float4*)(cw + (d+3) * 4);
    float4 bias = *(const float4*)(cb + d);
    float4 v = *(const float4*)p;
    float a0 = fmaf(w0.w, v.x, bias.x);
    float a1 = fmaf(w1.w, v.y, bias.y);
    float a2 = fmaf(w2.w, v.z, bias.z);
    float a3 = fmaf(w3.w, v.w, bias.w);
    if (l >= 1) { float4 u = *(const float4*)(p - 2*DI);
        a0 = fmaf(w0.z, u.x, a0); a1 = fmaf(w1.z, u.y, a1);
        a2 = fmaf(w2.z, u.z, a2); a3 = fmaf(w3.z, u.w, a3); }
    if (l >= 2) { float4 u = *(const float4*)(p - 4*DI);
        a0 = fmaf(w0.y, u.x, a0); a1 = fmaf(w1.y, u.y, a1);
        a2 = fmaf(w2.y, u.z, a2); a3 = fmaf(w3.y, u.w, a3); }
    if (l >= 3) { float4 u = *(const float4*)(p - 6*DI);
        a0 = fmaf(w0.x, u.x, a0); a1 = fmaf(w1.x, u.y, a1);
        a2 = fmaf(w2.x, u.z, a2); a3 = fmaf(w3.x, u.w, a3); }
    float r0 = a0 / (1.f + __expf(-a0));
    float r1 = a1 / (1.f + __expf(-a1));
    float r2 = a2 / (1.f + __expf(-a2));
    float r3 = a3 / (1.f + __expf(-a3));
    *(float4*)(xc + (size_t)m * DI + d) = make_float4(r0, r1, r2, r3);
    __nv_bfloat162* ob = (__nv_bfloat162*)(xcb + (size_t)m * DI + d);
    ob[0] = __floats2bfloat162_rn(r0, r1);
    ob[1] = __floats2bfloat162_rn(r2, r3);
}

// =============== chunked selective scan (16 states per thread) ==============
__global__ __launch_bounds__(256)
void scan_p1_kernel(const float* __restrict__ dt,
                    const float* __restrict__ xc,
                    const float* __restrict__ dbl,
                    const float* __restrict__ A_log,
                    float* __restrict__ P, float* __restrict__ U)
{
    int gid = blockIdx.x * 256 + threadIdx.x;   // BB*NCH*DI = 131072
    int d  = gid & (DI - 1);
    int ch = (gid >> 11) & (NCH - 1);
    int b  = gid >> 16;

    float A2[DS], Pv[DS], Uv[DS];
    #pragma unroll
    for (int s = 0; s < DS; s++) {
        A2[s] = -__expf(A_log[d * DS + s]) * LOG2E;
        Pv[s] = 1.f; Uv[s] = 0.f;
    }
    size_t mbase = (size_t)b * LL + ch * CH;
    for (int l = 0; l < CH; l++) {
        size_t m = mbase + l;
        float dtv = dt[m * DI + d];
        float xv  = xc[m * DI + d];
        float dx  = dtv * xv;
        const float4* Bp = (const float4*)(dbl + m * 96 + DTR);
        float4 B0 = Bp[0], B1 = Bp[1], B2 = Bp[2], B3 = Bp[3];
        float Bv[DS] = {B0.x,B0.y,B0.z,B0.w, B1.x,B1.y,B1.z,B1.w,
                        B2.x,B2.y,B2.z,B2.w, B3.x,B3.y,B3.z,B3.w};
        #pragma unroll
        for (int s = 0; s < DS; s++) {
            float a = exp2f(dtv * A2[s]);
            Pv[s] *= a;
            Uv[s] = fmaf(a, Uv[s], dx * Bv[s]);
        }
    }
    size_t base = ((size_t)(b * NCH + ch) * DS) * DI + d;
    #pragma unroll
    for (int s = 0; s < DS; s++) {
        P[base + (size_t)s * DI] = Pv[s];
        U[base + (size_t)s * DI] = Uv[s];
    }
}

__global__ void scan_p2_kernel(const float* __restrict__ P,
                               const float* __restrict__ U,
                               float* __restrict__ H)
{
    int gid = blockIdx.x * 256 + threadIdx.x;   // BB*DS*DI = 65536
    int d = gid & (DI - 1);
    int s = (gid >> 11) & (DS - 1);
    int b = gid >> 15;
    float h = 0.f;
    #pragma unroll
    for (int ch = 0; ch < NCH; ch++) {
        size_t idx = ((size_t)((b * NCH + ch) * DS + s)) * DI + d;
        H[idx] = h;
        h = fmaf(P[idx], h, U[idx]);
    }
}

__global__ __launch_bounds__(256)
void scan_p3_kernel(const float* __restrict__ dt,
                    const float* __restrict__ xc,
                    const float* __restrict__ dbl,
                    const float* __restrict__ xz,
                    const float* __restrict__ A_log,
                    const float* __restrict__ Dp,
                    const float* __restrict__ H,
                    bf16* __restrict__ y)
{
    int gid = blockIdx.x * 256 + threadIdx.x;   // 131072
    int d  = gid & (DI - 1);
    int ch = (gid >> 11) & (NCH - 1);
    int b  = gid >> 16;

    float A2[DS], h[DS];
    size_t hbase = ((size_t)(b * NCH + ch) * DS) * DI + d;
    #pragma unroll
    for (int s = 0; s < DS; s++) {
        A2[s] = -__expf(A_log[d * DS + s]) * LOG2E;
        h[s] = H[hbase + (size_t)s * DI];
    }
    float D_d = Dp[d];
    size_t mbase = (size_t)b * LL + ch * CH;
    for (int l = 0; l < CH; l++) {
        size_t m = mbase + l;
        float dtv = dt[m * DI + d];
        float xv  = xc[m * DI + d];
        float dx  = dtv * xv;
        const float4* Bp = (const float4*)(dbl + m * 96 + DTR);
        float4 B0 = Bp[0], B1 = Bp[1], B2 = Bp[2], B3 = Bp[3];
        const float4* Cp = (const float4*)(dbl + m * 96 + DTR + DS);
        float4 C0 = Cp[0], C1 = Cp[1], C2 = Cp[2], C3 = Cp[3];
        float Bv[DS] = {B0.x,B0.y,B0.z,B0.w, B1.x,B1.y,B1.z,B1.w,
                        B2.x,B2.y,B2.z,B2.w, B3.x,B3.y,B3.z,B3.w};
        float Cv[DS] = {C0.x,C0.y,C0.z,C0.w, C1.x,C1.y,C1.z,C1.w,
                        C2.x,C2.y,C2.z,C2.w, C3.x,C3.y,C3.z,C3.w};
        float acc = 0.f;
        #pragma unroll
        for (int s = 0; s < DS; s++) {
            float a = exp2f(dtv * A2[s]);
            h[s] = fmaf(a, h[s], dx * Bv[s]);
            acc = fmaf(h[s], Cv[s], acc);
        }
        float zv = xz[m * (2*DI) + DI + d];
        float yy = fmaf(xv, D_d, acc);
        y[m * DI + d] = __float2bfloat16(yy * (zv / (1.f + __expf(-zv))));
    }
}

// ---------------- launcher -------------------------------------------------
extern "C" void kernel_launch(void* const* d_in, const int* in_sizes, int n_in,
                              void* d_out, int out_size)
{
    const float* x      = (const float*)d_in[0];
    const float* ln_g   = (const float*)d_in[1];
    const float* ln_b   = (const float*)d_in[2];
    const float* W_in   = (const float*)d_in[3];
    const float* conv_w = (const float*)d_in[4];
    const float* conv_b = (const float*)d_in[5];
    const float* W_xp   = (const float*)d_in[6];
    const float* W_dt   = (const float*)d_in[7];
    const float* b_dt   = (const float*)d_in[8];
    const float* A_log  = (const float*)d_in[9];
    const float* Dp     = (const float*)d_in[10];
    const float* W_out  = (const float*)d_in[11];
    float* out = (float*)d_out;

    float *xz, *xc, *dbl, *dblp, *dtb, *Pb, *Ub, *Hb;
    bf16 *xnb, *xcb, *dtlo, *yb, *Winb, *Wxpb, *Wdtb, *Woutb;
    cudaGetSymbolAddress((void**)&xz,   g_xz);
    cudaGetSymbolAddress((void**)&xc,   g_xc);
    cudaGetSymbolAddress((void**)&dbl,  g_dbl);
    cudaGetSymbolAddress((void**)&dblp, g_dblp);
    cudaGetSymbolAddress((void**)&dtb,  g_dt);
    cudaGetSymbolAddress((void**)&xnb,  g_xnb);
    cudaGetSymbolAddress((void**)&xcb,  g_xcb);
    cudaGetSymbolAddress((void**)&dtlo, g_dtlo);
    cudaGetSymbolAddress((void**)&yb,   g_yb);
    cudaGetSymbolAddress((void**)&Winb, g_Winb);
    cudaGetSymbolAddress((void**)&Wxpb, g_Wxpb);
    cudaGetSymbolAddress((void**)&Wdtb, g_Wdtb);
    cudaGetSymbolAddress((void**)&Woutb,g_Woutb);
    cudaGetSymbolAddress((void**)&Pb,   g_P);
    cudaGetSymbolAddress((void**)&Ub,   g_U);
    cudaGetSymbolAddress((void**)&Hb,   g_H);

    constexpr int SM_MMA = 2 * (128 + 128) * 72 * 2;          // 73728
    constexpr int SM_64  = (64 + 128) * SPAD * 2 * STAGES;    // 46080
    cudaFuncSetAttribute(mma_gemm_kernel<0>, cudaFuncAttributeMaxDynamicSharedMemorySize, SM_MMA);
    cudaFuncSetAttribute(mma_gemm_kernel<1>, cudaFuncAttributeMaxDynamicSharedMemorySize, SM_MMA);
    cudaFuncSetAttribute(mma_gemm_kernel<2>, cudaFuncAttributeMaxDynamicSharedMemorySize, SM_MMA);
    cudaFuncSetAttribute(hgemm_kernel<64,128,2,4>, cudaFuncAttributeMaxDynamicSharedMemorySize, SM_64);

    // 1. W_in -> bf16
    f2bf_kernel<<<((2*DI*DM)/4 + 255)/256, 256>>>(W_in,  Winb, 2*DI*DM);
    // 2. LayerNorm -> bf16
    layernorm_kernel<<<MM, 256>>>(x, ln_g, ln_b, xnb);
    // 3. W_xp -> bf16
    f2bf_kernel<<<((96*DI)/4 + 255)/256, 256>>>(W_xp,  Wxpb, 96*DI);
    // 4. xz = xn @ W_in^T   [8192 x 4096], K=1024   <-- PROFILED (launch #4)
    mma_gemm_kernel<0><<<dim3(4096/128, MM/128), 256, SM_MMA>>>(
        xnb, DM, Winb, DM, xz, 2*DI, DM, nullptr);
    // 5. causal conv + silu -> xc (4 ch/thread)
    conv_silu_kernel<<<(MM*DI/4)/256, 256>>>(xz, conv_w, conv_b, xc, xcb);
    // 6. W_dt -> bf16
    f2bf_kernel<<<((DI*DTR)/4 + 255)/256, 256>>>(W_dt,  Wdtb, DI*DTR);
    // 7. dbl partials = xc @ W_xp^T, split-K x4  [8192 x 96], K slices of 512
    hgemm_kernel<64,128,2,4><<<dim3(1, MM/64, 4), 256, SM_64>>>(
        xcb, DI, Wxpb, DI, dblp, 96, 96, DI/4, DI/4, (size_t)MM*96);
    // 8. reduce partials -> dbl fp32 + dtlo bf16
    dbl_reduce_kernel<<<(MM*96)/256, 256>>>(dblp, dbl, dtlo);
    // 9. W_out -> bf16
    f2bf_kernel<<<((DM*DI)/4 + 255)/256, 256>>>(W_out, Woutb, DM*DI);
    // 10. dt = softplus(dt_lo @ W_dt^T + b_dt)
    mma_gemm_kernel<2><<<dim3(DI/128, MM/128), 256, SM_MMA>>>(
        dtlo, DTR, Wdtb, DTR, dtb, DI, DTR, b_dt);
    // 11-13. chunked selective scan (16 states/thread)
    scan_p1_kernel<<<(BB*NCH*DI)/256, 256>>>(dtb, xc, dbl, A_log, Pb, Ub);
    scan_p2_kernel<<<(BB*DS*DI)/256, 256>>>(Pb, Ub, Hb);
    scan_p3_kernel<<<(BB*NCH*DI)/256, 256>>>(dtb, xc, dbl, xz, A_log, Dp, Hb, yb);
    // 14. out = x + y @ W_out^T  [8192 x 1024], K=2048
    mma_gemm_kernel<1><<<dim3(DM/128, MM/128), 256, SM_MMA>>>(
        yb, DI, Woutb, DI, out, DM, DI, x);
}

// round 11
// speedup vs baseline: 8.4237x; 1.1487x over previous
#include <cuda_runtime.h>
#include <cuda_bf16.h>
#include <mma.h>
#include <cstdint>

using namespace nvcuda;
typedef __nv_bfloat16 bf16;

#define BB    2
#define LL    4096
#define DM    1024
#define DS    16
#define DI    2048
#define DTR   64
#define MM    (BB*LL)          // 8192
#define CH    128
#define NCH   (LL/CH)          // 32

// ---------------- scratch (device globals) ---------------------------------
__device__ float g_xz [ (size_t)MM * (2*DI) ];    // 8192x4096 (xs | z) fp32
__device__ float g_dbl[ (size_t)MM * 96 ];        // dt_lo64 | B16 | C16  fp32
__device__ float g_dblp[ (size_t)4 * MM * 96 ];   // split-K partials
__device__ float g_dt [ (size_t)MM * DI ];        // fp32
__device__ bf16  g_xnb [ (size_t)MM * DM ];
__device__ bf16  g_xcb [ (size_t)MM * DI ];       // conv out (bf16 only now)
__device__ bf16  g_dtlo[ (size_t)MM * DTR ];
__device__ bf16  g_yb  [ (size_t)MM * DI ];
__device__ bf16  g_Winb [ (size_t)(2*DI) * DM ];
__device__ bf16  g_Wxpb [ (size_t)96 * DI ];
__device__ bf16  g_Wdtb [ (size_t)DI * DTR ];
__device__ bf16  g_Woutb[ (size_t)DM * DI ];
// scan chunk buffers, layout idx(b,ch,s,d) = ((b*NCH+ch)*DS+s)*DI + d
__device__ float g_P [ (size_t)BB * NCH * DS * DI ];
__device__ float g_U [ (size_t)BB * NCH * DS * DI ];
__device__ float g_H [ (size_t)BB * NCH * DS * DI ];

#define LOG2E 1.4426950408889634f

// ======================= helpers ============================================
__device__ __forceinline__ void cp_async16(uint32_t saddr, const void* gptr) {
    asm volatile("cp.async.cg.shared.global [%0], [%1], 16;\n" :: "r"(saddr), "l"(gptr));
}
__device__ __forceinline__ void ldsm_x4(uint32_t* r, uint32_t addr) {
    asm volatile("ldmatrix.sync.aligned.m8n8.x4.shared.b16 {%0,%1,%2,%3}, [%4];"
        : "=r"(r[0]), "=r"(r[1]), "=r"(r[2]), "=r"(r[3]) : "r"(addr));
}
__device__ __forceinline__ void mma16816(float* d, const uint32_t* a, uint32_t b0, uint32_t b1) {
    asm volatile("mma.sync.aligned.m16n8k16.row.col.f32.bf16.bf16.f32 "
        "{%0,%1,%2,%3}, {%4,%5,%6,%7}, {%8,%9}, {%0,%1,%2,%3};"
        : "+f"(d[0]), "+f"(d[1]), "+f"(d[2]), "+f"(d[3])
        : "r"(a[0]), "r"(a[1]), "r"(a[2]), "r"(a[3]), "r"(b0), "r"(b1));
}
__device__ __forceinline__ float fast_softplus(float v) {
    return (v > 15.f) ? v : __logf(1.f + __expf(v));
}

// ======================= mma.sync GEMM (BK=64, 2-stage, 2 CTAs/SM) =========
template<int EPI>
__global__ __launch_bounds__(256, 2)
void mma_gemm_kernel(const bf16* __restrict__ A, int lda,
                     const bf16* __restrict__ W, int ldb,
                     float* __restrict__ C, int ldc,
                     int K, const float* __restrict__ aux)
{
    constexpr int BM = 128, BN = 128, BK = 64, SP = 72;
    constexpr int ASZ = BM * SP;
    constexpr int SSZ = (BM + BN) * SP;

    extern __shared__ bf16 sm2[];
    const int tid  = threadIdx.x;
    const int lane = tid & 31;
    const int wid  = tid >> 5;
    const int wm   = wid >> 2;
    const int wn   = wid & 3;
    const int bm   = blockIdx.y * BM;
    const int bn   = blockIdx.x * BN;

    auto prefetch = [&](int s, int kt) {
        const int k0 = kt * BK;
        uint32_t base = (uint32_t)__cvta_generic_to_shared(sm2 + s * SSZ);
        #pragma unroll
        for (int i = 0; i < 4; i++) {
            int e = i * 256 + tid;
            int r = e >> 3, c = e & 7;
            cp_async16(base + (r * SP + c * 8) * 2,
                       A + (size_t)(bm + r) * lda + k0 + c * 8);
        }
        uint32_t baseB = base + ASZ * 2;
        #pragma unroll
        for (int i = 0; i < 4; i++) {
            int e = i * 256 + tid;
            int r = e >> 3, c = e & 7;
            cp_async16(baseB + (r * SP + c * 8) * 2,
                       W + (size_t)(bn + r) * ldb + k0 + c * 8);
        }
    };

    float acc[4][4][4];
    #pragma unroll
    for (int i = 0; i < 4; i++)
        #pragma unroll
        for (int j = 0; j < 4; j++)
            #pragma unroll
            for (int e = 0; e < 4; e++) acc[i][j][e] = 0.f;

    const int T = K / BK;
    prefetch(0, 0);
    asm volatile("cp.async.commit_group;\n");

    for (int t = 0; t < T; t++) {
        if (t + 1 < T) {
            prefetch((t + 1) & 1, t + 1);
            asm volatile("cp.async.commit_group;\n");
            asm volatile("cp.async.wait_group 1;\n");
        } else {
            asm volatile("cp.async.wait_group 0;\n");
        }
        __syncthreads();

        uint32_t abase = (uint32_t)__cvta_generic_to_shared(sm2 + (t & 1) * SSZ);
        uint32_t bbase = abase + ASZ * 2;
        const int half = lane >> 4;
        #pragma unroll
        for (int k16 = 0; k16 < 4; k16++) {
            uint32_t af[4][4], bfr[2][4];
            #pragma unroll
            for (int i = 0; i < 4; i++) {
                int row = wm * 64 + i * 16 + (lane & 15);
                ldsm_x4(af[i], abase + (row * SP + (k16 * 2 + half) * 8) * 2);
            }
            #pragma unroll
            for (int jp = 0; jp < 2; jp++) {
                int row = wn * 32 + jp * 16 + (lane & 15);
                ldsm_x4(bfr[jp], bbase + (row * SP + (k16 * 2 + half) * 8) * 2);
            }
            #pragma unroll
            for (int i = 0; i < 4; i++)
                #pragma unroll
                for (int jp = 0; jp < 2; jp++) {
                    mma16816(acc[i][2*jp],   af[i], bfr[jp][0], bfr[jp][2]);
                    mma16816(acc[i][2*jp+1], af[i], bfr[jp][1], bfr[jp][3]);
                }
        }
        __syncthreads();
    }

    const int r0 = bm + wm * 64 + (lane >> 2);
    const int c0 = bn + wn * 32 + (lane & 3) * 2;
    #pragma unroll
    for (int i = 0; i < 4; i++) {
        #pragma unroll
        for (int j = 0; j < 4; j++) {
            int r = r0 + i * 16;
            int c = c0 + j * 8;
            float v0 = acc[i][j][0], v1 = acc[i][j][1];
            float v2 = acc[i][j][2], v3 = acc[i][j][3];
            if (EPI == 1) {
                const float2 a0 = *(const float2*)(aux + (size_t)r * ldc + c);
                const float2 a1 = *(const float2*)(aux + (size_t)(r+8) * ldc + c);
                v0 += a0.x; v1 += a0.y; v2 += a1.x; v3 += a1.y;
            } else if (EPI == 2) {
                float b0 = aux[c], b1 = aux[c+1];
                v0 = fast_softplus(v0 + b0);
                v1 = fast_softplus(v1 + b1);
                v2 = fast_softplus(v2 + b0);
                v3 = fast_softplus(v3 + b1);
            }
            *(float2*)(C + (size_t)r * ldc + c)     = make_float2(v0, v1);
            *(float2*)(C + (size_t)(r+8) * ldc + c) = make_float2(v2, v3);
        }
    }
}

// ---------------- fp32 -> bf16 converts ------------------------------------
__global__ void f2bf_kernel(const float* __restrict__ src, bf16* __restrict__ dst, int n)
{
    int i = (blockIdx.x * 256 + threadIdx.x) * 4;
    if (i < n) {
        float4 v = *(const float4*)(src + i);
        __nv_bfloat162* d = (__nv_bfloat162*)(dst + i);
        d[0] = __floats2bfloat162_rn(v.x, v.y);
        d[1] = __floats2bfloat162_rn(v.z, v.w);
    }
}

// three tensors in one launch
__global__ void f2bf3_kernel(const float* __restrict__ s0, bf16* __restrict__ d0, int n0,
                             const float* __restrict__ s1, bf16* __restrict__ d1, int n1,
                             const float* __restrict__ s2, bf16* __restrict__ d2, int n2)
{
    int i = (blockIdx.x * 256 + threadIdx.x) * 4;
    const float* s; bf16* d; int off;
    if (i < n0)                { s = s0; d = d0; off = i; }
    else if (i < n0 + n1)      { s = s1; d = d1; off = i - n0; }
    else if (i < n0 + n1 + n2) { s = s2; d = d2; off = i - n0 - n1; }
    else return;
    float4 v = *(const float4*)(s + off);
    __nv_bfloat162* dd = (__nv_bfloat162*)(d + off);
    dd[0] = __floats2bfloat162_rn(v.x, v.y);
    dd[1] = __floats2bfloat162_rn(v.z, v.w);
}

// ---------------- layernorm -> bf16 ----------------------------------------
__global__ void layernorm_kernel(const float* __restrict__ x,
                                 const float* __restrict__ g,
                                 const float* __restrict__ b,
                                 bf16* __restrict__ o)
{
    __shared__ float red[64];
    int row = blockIdx.x;
    int t = threadIdx.x;
    const float4* xr = (const float4*)(x + (size_t)row * DM);
    float4 v = xr[t];
    float s = v.x + v.y + v.z + v.w;
    float q = v.x*v.x + v.y*v.y + v.z*v.z + v.w*v.w;
    #pragma unroll
    for (int off = 16; off; off >>= 1) {
        s += __shfl_xor_sync(0xffffffffu, s, off);
        q += __shfl_xor_sync(0xffffffffu, q, off);
    }
    if ((t & 31) == 0) { red[t >> 5] = s; red[32 + (t >> 5)] = q; }
    __syncthreads();
    if (t < 32) {
        float s2 = (t < 8) ? red[t]      : 0.f;
        float q2 = (t < 8) ? red[32 + t] : 0.f;
        #pragma unroll
        for (int off = 4; off; off >>= 1) {
            s2 += __shfl_xor_sync(0xffffffffu, s2, off);
            q2 += __shfl_xor_sync(0xffffffffu, q2, off);
        }
        if (t == 0) { red[0] = s2; red[1] = q2; }
    }
    __syncthreads();
    float mu  = red[0] * (1.f / DM);
    float var = red[1] * (1.f / DM) - mu * mu;
    float inv = rsqrtf(var + 1e-5f);
    float4 gv = ((const float4*)g)[t];
    float4 bv = ((const float4*)b)[t];
    __nv_bfloat162* op = (__nv_bfloat162*)(o + (size_t)row * DM + t * 4);
    op[0] = __floats2bfloat162_rn((v.x - mu)*inv*gv.x + bv.x, (v.y - mu)*inv*gv.y + bv.y);
    op[1] = __floats2bfloat162_rn((v.z - mu)*inv*gv.z + bv.z, (v.w - mu)*inv*gv.w + bv.w);
}

// ---------------- bf16 wmma GEMM (W_xp, split-K via blockIdx.z) ------------
#define STAGES 3
#define SPAD   40

template<int BM, int BN, int WGM, int WGN>
__global__ __launch_bounds__(WGM*WGN*32)
void hgemm_kernel(const bf16* __restrict__ A, int lda,
                  const bf16* __restrict__ W, int ldb,
                  float* __restrict__ C, int ldc,
                  int N, int K,
                  int zk_off, size_t zc_off)
{
    constexpr int TM = BM / WGM;
    constexpr int TN = BN / WGN;
    constexpr int MF = TM / 16;
    constexpr int NF = TN / 16;
    constexpr int NT = WGM * WGN * 32;
    constexpr int SSZ = (BM + BN) * SPAD;

    extern __shared__ bf16 smh[];

    A += (size_t)blockIdx.z * zk_off;
    W += (size_t)blockIdx.z * zk_off;
    C += (size_t)blockIdx.z * zc_off;

    int tid = threadIdx.x;
    int wid = tid >> 5;
    int wm  = wid / WGN;
    int wn  = wid % WGN;
    int bm  = blockIdx.y * BM;
    int bn  = blockIdx.x * BN;

    auto prefetch = [&](int p, int k0) {
        uint32_t sbase = (uint32_t)__cvta_generic_to_shared(smh + p * SSZ);
        #pragma unroll
        for (int i = 0; i < (BM * 4) / NT; i++) {
            int e = i * NT + tid;
            int row = e >> 2, c8 = (e & 3) * 8;
            cp_async16(sbase + (row * SPAD + c8) * 2,
                       A + (size_t)(bm + row) * lda + k0 + c8);
        }
        uint32_t sbase2 = sbase + BM * SPAD * 2;
        #pragma unroll
        for (int i = 0; i < (BN * 4) / NT; i++) {
            int e = i * NT + tid;
            int row = e >> 2, c8 = (e & 3) * 8;
            int n = bn + row; if (n >= N) n = N - 1;
            cp_async16(sbase2 + (row * SPAD + c8) * 2,
                       W + (size_t)n * ldb + k0 + c8);
        }
    };

    wmma::fragment<wmma::accumulator, 16, 16, 16, float> acc[MF][NF];
    #pragma unroll
    for (int i = 0; i < MF; i++)
        #pragma unroll
        for (int j = 0; j < NF; j++) wmma::fill_fragment(acc[i][j], 0.f);

    int T = K / 32;
    #pragma unroll
    for (int s = 0; s < STAGES - 1; s++) {
        if (s < T) prefetch(s, s * 32);
        asm volatile("cp.async.commit_group;\n");
    }

    for (int t = 0; t < T; t++) {
        asm volatile("cp.async.wait_group %0;\n" :: "n"(STAGES - 2));
        __syncthreads();

        int pn = t + STAGES - 1;
        if (pn < T) prefetch(pn % STAGES, pn * 32);
        asm volatile("cp.async.commit_group;\n");

        const bf16* As = smh + (t % STAGES) * SSZ;
        const bf16* Ws = As + BM * SPAD;
        #pragma unroll
        for (int ks = 0; ks < 32; ks += 16) {
            wmma::fragment<wmma::matrix_a, 16, 16, 16, bf16, wmma::row_major> af[MF];
            wmma::fragment<wmma::matrix_b, 16, 16, 16, bf16, wmma::col_major> bff[NF];
            #pragma unroll
            for (int i = 0; i < MF; i++)
                wmma::load_matrix_sync(af[i], As + (wm * TM + i * 16) * SPAD + ks, SPAD);
            #pragma unroll
            for (int j = 0; j < NF; j++)
                wmma::load_matrix_sync(bff[j], Ws + (wn * TN + j * 16) * SPAD + ks, SPAD);
            #pragma unroll
            for (int i = 0; i < MF; i++)
                #pragma unroll
                for (int j = 0; j < NF; j++)
                    wmma::mma_sync(acc[i][j], af[i], bff[j], acc[i][j]);
        }
        __syncthreads();
    }

    #pragma unroll
    for (int i = 0; i < MF; i++) {
        int r0 = bm + wm * TM + i * 16;
        #pragma unroll
        for (int j = 0; j < NF; j++) {
            int c0 = bn + wn * TN + j * 16;
            if (c0 < N) {
                wmma::store_matrix_sync(C + (size_t)r0 * ldc + c0, acc[i][j], ldc, wmma::mem_row_major);
            }
        }
    }
}

// ---------------- split-K reduce + dtlo extraction -------------------------
__global__ void dbl_reduce_kernel(const float* __restrict__ dblp,
                                  float* __restrict__ dbl,
                                  bf16* __restrict__ dtlo)
{
    int idx = blockIdx.x * 256 + threadIdx.x;   // over MM*96
    const size_t STR = (size_t)MM * 96;
    float v = dblp[idx] + dblp[idx + STR] + dblp[idx + 2*STR] + dblp[idx + 3*STR];
    dbl[idx] = v;
    int m = idx / 96, c = idx - m * 96;
    if (c < DTR) dtlo[m * DTR + c] = __float2bfloat16(v);
}

// ---------------- causal depthwise conv (DC=4) + silu, 4 channels/thread ---
__global__ void conv_silu_kernel(const float* __restrict__ xz,
                                 const float* __restrict__ cw,
                                 const float* __restrict__ cb,
                                 bf16* __restrict__ xcb)
{
    int idx = blockIdx.x * 256 + threadIdx.x;      // over M*DI/4
    int dq = idx & (DI/4 - 1);
    int m  = idx >> 9;
    int l  = m & (LL - 1);
    int d  = dq * 4;
    const float* p = xz + (size_t)m * (2*DI) + d;
    float4 w0 = *(const float4*)(cw + (d+0) * 4);
    float4 w1 = *(const float4*)(cw + (d+1) * 4);
    float4 w2 = *(const float4*)(cw + (d+2) * 4);
    float4 w3 = *(const float4*)(cw + (d+3) * 4);
    float4 bias = *(const float4*)(cb + d);
    float4 v = *(const float4*)p;
    float a0 = fmaf(w0.w, v.x, bias.x);
    float a1 = fmaf(w1.w, v.y, bias.y);
    float a2 = fmaf(w2.w, v.z, bias.z);
    float a3 = fmaf(w3.w, v.w, bias.w);
    if (l >= 1) { float4 u = *(const float4*)(p - 2*DI);
        a0 = fmaf(w0.z, u.x, a0); a1 = fmaf(w1.z, u.y, a1);
        a2 = fmaf(w2.z, u.z, a2); a3 = fmaf(w3.z, u.w, a3); }
    if (l >= 2) { float4 u = *(const float4*)(p - 4*DI);
        a0 = fmaf(w0.y, u.x, a0); a1 = fmaf(w1.y, u.y, a1);
        a2 = fmaf(w2.y, u.z, a2); a3 = fmaf(w3.y, u.w, a3); }
    if (l >= 3) { float4 u = *(const float4*)(p - 6*DI);
        a0 = fmaf(w0.x, u.x, a0); a1 = fmaf(w1.x, u.y, a1);
        a2 = fmaf(w2.x, u.z, a2); a3 = fmaf(w3.x, u.w, a3); }
    float r0 = a0 / (1.f + __expf(-a0));
    float r1 = a1 / (1.f + __expf(-a1));
    float r2 = a2 / (1.f + __expf(-a2));
    float r3 = a3 / (1.f + __expf(-a3));
    __nv_bfloat162* ob = (__nv_bfloat162*)(xcb + (size_t)m * DI + d);
    ob[0] = __floats2bfloat162_rn(r0, r1);
    ob[1] = __floats2bfloat162_rn(r2, r3);
}

// =============== chunked selective scan (16 states per thread) ==============
// Adaptive fast path: if A2[s] == (s+1)*A2[0] (true for A_log = log(1..16)),
// all 16 exponentials are powers of one exp2 -> 1 MUFU + 15 FMULs per step.
// Generic fallback otherwise.

__global__ __launch_bounds__(256)
void scan_p1_kernel(const float* __restrict__ dt,
                    const bf16* __restrict__ xc,
                    const float* __restrict__ dbl,
                    const float* __restrict__ A_log,
                    float* __restrict__ P, float* __restrict__ U)
{
    int gid = blockIdx.x * 256 + threadIdx.x;   // BB*NCH*DI = 131072
    int d  = gid & (DI - 1);
    int ch = (gid >> 11) & (NCH - 1);
    int b  = gid >> 16;

    float A2[DS], Pv[DS], Uv[DS];
    #pragma unroll
    for (int s = 0; s < DS; s++) {
        A2[s] = -__expf(A_log[d * DS + s]) * LOG2E;
        Pv[s] = 1.f; Uv[s] = 0.f;
    }
    bool fastp = true;
    #pragma unroll
    for (int s = 0; s < DS; s++)
        fastp = fastp && (fabsf(A2[s] - (float)(s + 1) * A2[0]) <= 1e-4f * fabsf(A2[s]));

    size_t mbase = (size_t)b * LL + ch * CH;
    if (fastp) {
        float A20 = A2[0];
        for (int l = 0; l < CH; l++) {
            size_t m = mbase + l;
            float dtv = dt[m * DI + d];
            float xv  = __bfloat162float(xc[m * DI + d]);
            float dx  = dtv * xv;
            const float4* Bp = (const float4*)(dbl + m * 96 + DTR);
            float4 B0 = Bp[0], B1 = Bp[1], B2 = Bp[2], B3 = Bp[3];
            float Bv[DS] = {B0.x,B0.y,B0.z,B0.w, B1.x,B1.y,B1.z,B1.w,
                            B2.x,B2.y,B2.z,B2.w, B3.x,B3.y,B3.z,B3.w};
            float a1 = exp2f(dtv * A20);
            float as = a1;
            #pragma unroll
            for (int s = 0; s < DS; s++) {
                Pv[s] *= as;
                Uv[s] = fmaf(as, Uv[s], dx * Bv[s]);
                as *= a1;
            }
        }
    } else {
        for (int l = 0; l < CH; l++) {
            size_t m = mbase + l;
            float dtv = dt[m * DI + d];
            float xv  = __bfloat162float(xc[m * DI + d]);
            float dx  = dtv * xv;
            const float4* Bp = (const float4*)(dbl + m * 96 + DTR);
            float4 B0 = Bp[0], B1 = Bp[1], B2 = Bp[2], B3 = Bp[3];
            float Bv[DS] = {B0.x,B0.y,B0.z,B0.w, B1.x,B1.y,B1.z,B1.w,
                            B2.x,B2.y,B2.z,B2.w, B3.x,B3.y,B3.z,B3.w};
            #pragma unroll
            for (int s = 0; s < DS; s++) {
                float a = exp2f(dtv * A2[s]);
                Pv[s] *= a;
                Uv[s] = fmaf(a, Uv[s], dx * Bv[s]);
            }
        }
    }
    size_t base = ((size_t)(b * NCH + ch) * DS) * DI + d;
    #pragma unroll
    for (int s = 0; s < DS; s++) {
        P[base + (size_t)s * DI] = Pv[s];
        U[base + (size_t)s * DI] = Uv[s];
    }
}

__global__ void scan_p2_kernel(const float* __restrict__ P,
                               const float* __restrict__ U,
                               float* __restrict__ H)
{
    int gid = blockIdx.x * 256 + threadIdx.x;   // BB*DS*DI = 65536
    int d = gid & (DI - 1);
    int s = (gid >> 11) & (DS - 1);
    int b = gid >> 15;
    float h = 0.f;
    #pragma unroll
    for (int ch = 0; ch < NCH; ch++) {
        size_t idx = ((size_t)((b * NCH + ch) * DS + s)) * DI + d;
        H[idx] = h;
        h = fmaf(P[idx], h, U[idx]);
    }
}

__global__ __launch_bounds__(256)
void scan_p3_kernel(const float* __restrict__ dt,
                    const bf16* __restrict__ xc,
                    const float* __restrict__ dbl,
                    const float* __restrict__ xz,
                    const float* __restrict__ A_log,
                    const float* __restrict__ Dp,
                    const float* __restrict__ H,
                    bf16* __restrict__ y)
{
    int gid = blockIdx.x * 256 + threadIdx.x;   // 131072
    int d  = gid & (DI - 1);
    int ch = (gid >> 11) & (NCH - 1);
    int b  = gid >> 16;

    float A2[DS], h[DS];
    size_t hbase = ((size_t)(b * NCH + ch) * DS) * DI + d;
    #pragma unroll
    for (int s = 0; s < DS; s++) {
        A2[s] = -__expf(A_log[d * DS + s]) * LOG2E;
        h[s] = H[hbase + (size_t)s * DI];
    }
    bool fastp = true;
    #pragma unroll
    for (int s = 0; s < DS; s++)
        fastp = fastp && (fabsf(A2[s] - (float)(s + 1) * A2[0]) <= 1e-4f * fabsf(A2[s]));

    float D_d = Dp[d];
    size_t mbase = (size_t)b * LL + ch * CH;
    if (fastp) {
        float A20 = A2[0];
        for (int l = 0; l < CH; l++) {
            size_t m = mbase + l;
            float dtv = dt[m * DI + d];
            float xv  = __bfloat162float(xc[m * DI + d]);
            float dx  = dtv * xv;
            const float4* Bp = (const float4*)(dbl + m * 96 + DTR);
            float4 B0 = Bp[0], B1 = Bp[1], B2 = Bp[2], B3 = Bp[3];
            const float4* Cp = (const float4*)(dbl + m * 96 + DTR + DS);
            float4 C0 = Cp[0], C1 = Cp[1], C2 = Cp[2], C3 = Cp[3];
            float Bv[DS] = {B0.x,B0.y,B0.z,B0.w, B1.x,B1.y,B1.z,B1.w,
                            B2.x,B2.y,B2.z,B2.w, B3.x,B3.y,B3.z,B3.w};
            float Cv[DS] = {C0.x,C0.y,C0.z,C0.w, C1.x,C1.y,C1.z,C1.w,
                            C2.x,C2.y,C2.z,C2.w, C3.x,C3.y,C3.z,C3.w};
            float a1 = exp2f(dtv * A20);
            float as = a1;
            float acc = 0.f;
            #pragma unroll
            for (int s = 0; s < DS; s++) {
                h[s] = fmaf(as, h[s], dx * Bv[s]);
                acc = fmaf(h[s], Cv[s], acc);
                as *= a1;
            }
            float zv = xz[m * (2*DI) + DI + d];
            float yy = fmaf(xv, D_d, acc);
            y[m * DI + d] = __float2bfloat16(yy * (zv / (1.f + __expf(-zv))));
        }
    } else {
        for (int l = 0; l < CH; l++) {
            size_t m = mbase + l;
            float dtv = dt[m * DI + d];
            float xv  = __bfloat162float(xc[m * DI + d]);
            float dx  = dtv * xv;
            const float4* Bp = (const float4*)(dbl + m * 96 + DTR);
            float4 B0 = Bp[0], B1 = Bp[1], B2 = Bp[2], B3 = Bp[3];
            const float4* Cp = (const float4*)(dbl + m * 96 + DTR + DS);
            float4 C0 = Cp[0], C1 = Cp[1], C2 = Cp[2], C3 = Cp[3];
            float Bv[DS] = {B0.x,B0.y,B0.z,B0.w, B1.x,B1.y,B1.z,B1.w,
                            B2.x,B2.y,B2.z,B2.w, B3.x,B3.y,B3.z,B3.w};
            float Cv[DS] = {C0.x,C0.y,C0.z,C0.w, C1.x,C1.y,C1.z,C1.w,
                            C2.x,C2.y,C2.z,C2.w, C3.x,C3.y,C3.z,C3.w};
            float acc = 0.f;
            #pragma unroll
            for (int s = 0; s < DS; s++) {
                float a = exp2f(dtv * A2[s]);
                h[s] = fmaf(a, h[s], dx * Bv[s]);
                acc = fmaf(h[s], Cv[s], acc);
            }
            float zv = xz[m * (2*DI) + DI + d];
            float yy = fmaf(xv, D_d, acc);
            y[m * DI + d] = __float2bfloat16(yy * (zv / (1.f + __expf(-zv))));
        }
    }
}

// ---------------- launcher -------------------------------------------------
extern "C" void kernel_launch(void* const* d_in, const int* in_sizes, int n_in,
                              void* d_out, int out_size)
{
    const float* x      = (const float*)d_in[0];
    const float* ln_g   = (const float*)d_in[1];
    const float* ln_b   = (const float*)d_in[2];
    const float* W_in   = (const float*)d_in[3];
    const float* conv_w = (const float*)d_in[4];
    const float* conv_b = (const float*)d_in[5];
    const float* W_xp   = (const float*)d_in[6];
    const float* W_dt   = (const float*)d_in[7];
    const float* b_dt   = (const float*)d_in[8];
    const float* A_log  = (const float*)d_in[9];
    const float* Dp     = (const float*)d_in[10];
    const float* W_out  = (const float*)d_in[11];
    float* out = (float*)d_out;

    float *xz, *dbl, *dblp, *dtb, *Pb, *Ub, *Hb;
    bf16 *xnb, *xcb, *dtlo, *yb, *Winb, *Wxpb, *Wdtb, *Woutb;
    cudaGetSymbolAddress((void**)&xz,   g_xz);
    cudaGetSymbolAddress((void**)&dbl,  g_dbl);
    cudaGetSymbolAddress((void**)&dblp, g_dblp);
    cudaGetSymbolAddress((void**)&dtb,  g_dt);
    cudaGetSymbolAddress((void**)&xnb,  g_xnb);
    cudaGetSymbolAddress((void**)&xcb,  g_xcb);
    cudaGetSymbolAddress((void**)&dtlo, g_dtlo);
    cudaGetSymbolAddress((void**)&yb,   g_yb);
    cudaGetSymbolAddress((void**)&Winb, g_Winb);
    cudaGetSymbolAddress((void**)&Wxpb, g_Wxpb);
    cudaGetSymbolAddress((void**)&Wdtb, g_Wdtb);
    cudaGetSymbolAddress((void**)&Woutb,g_Woutb);
    cudaGetSymbolAddress((void**)&Pb,   g_P);
    cudaGetSymbolAddress((void**)&Ub,   g_U);
    cudaGetSymbolAddress((void**)&Hb,   g_H);

    constexpr int SM_MMA = 2 * (128 + 128) * 72 * 2;          // 73728
    constexpr int SM_64  = (64 + 128) * SPAD * 2 * STAGES;    // 46080
    cudaFuncSetAttribute(mma_gemm_kernel<0>, cudaFuncAttributeMaxDynamicSharedMemorySize, SM_MMA);
    cudaFuncSetAttribute(mma_gemm_kernel<1>, cudaFuncAttributeMaxDynamicSharedMemorySize, SM_MMA);
    cudaFuncSetAttribute(mma_gemm_kernel<2>, cudaFuncAttributeMaxDynamicSharedMemorySize, SM_MMA);
    cudaFuncSetAttribute(hgemm_kernel<64,128,2,4>, cudaFuncAttributeMaxDynamicSharedMemorySize, SM_64);

    const int nWxp = 96*DI, nWdt = DI*DTR, nWout = DM*DI;

    // 1. W_in -> bf16
    f2bf_kernel<<<((2*DI*DM)/4 + 255)/256, 256>>>(W_in,  Winb, 2*DI*DM);
    // 2. LayerNorm -> bf16
    layernorm_kernel<<<MM, 256>>>(x, ln_g, ln_b, xnb);
    // 3. W_xp + W_dt + W_out -> bf16 (one launch)
    f2bf3_kernel<<<(((nWxp+nWdt+nWout)/4) + 255)/256, 256>>>(
        W_xp, Wxpb, nWxp, W_dt, Wdtb, nWdt, W_out, Woutb, nWout);
    // 4. xz = xn @ W_in^T   [8192 x 4096], K=1024   <-- PROFILED (launch #4)
    mma_gemm_kernel<0><<<dim3(4096/128, MM/128), 256, SM_MMA>>>(
        xnb, DM, Winb, DM, xz, 2*DI, DM, nullptr);
    // 5. causal conv + silu -> xcb (bf16 only)
    conv_silu_kernel<<<(MM*DI/4)/256, 256>>>(xz, conv_w, conv_b, xcb);
    // 6. dbl partials = xc @ W_xp^T, split-K x4
    hgemm_kernel<64,128,2,4><<<dim3(1, MM/64, 4), 256, SM_64>>>(
        xcb, DI, Wxpb, DI, dblp, 96, 96, DI/4, DI/4, (size_t)MM*96);
    // 7. reduce partials -> dbl fp32 + dtlo bf16
    dbl_reduce_kernel<<<(MM*96)/256, 256>>>(dblp, dbl, dtlo);
    // 8. dt = softplus(dt_lo @ W_dt^T + b_dt)
    mma_gemm_kernel<2><<<dim3(DI/128, MM/128), 256, SM_MMA>>>(
        dtlo, DTR, Wdtb, DTR, dtb, DI, DTR, b_dt);
    // 9-11. chunked selective scan (16 states/thread, 1-MUFU fast path)
    scan_p1_kernel<<<(BB*NCH*DI)/256, 256>>>(dtb, xcb, dbl, A_log, Pb, Ub);
    scan_p2_kernel<<<(BB*DS*DI)/256, 256>>>(Pb, Ub, Hb);
    scan_p3_kernel<<<(BB*NCH*DI)/256, 256>>>(dtb, xcb, dbl, xz, A_log, Dp, Hb, yb);
    // 12. out = x + y @ W_out^T  [8192 x 1024], K=2048
    mma_gemm_kernel<1><<<dim3(DM/128, MM/128), 256, SM_MMA>>>(
        yb, DI, Woutb, DI, out, DM, DI, x);
}

// round 12
// speedup vs baseline: 8.6884x; 1.0314x over previous
#include <cuda_runtime.h>
#include <cuda_bf16.h>
#include <mma.h>
#include <cstdint>

using namespace nvcuda;
typedef __nv_bfloat16 bf16;

#define BB    2
#define LL    4096
#define DM    1024
#define DS    16
#define DI    2048
#define DTR   64
#define MM    (BB*LL)          // 8192
#define CH    128
#define NCH   (LL/CH)          // 32

// ---------------- scratch (device globals) ---------------------------------
__device__ bf16  g_xz [ (size_t)MM * (2*DI) ];    // 8192x4096 (xs | z) bf16
__device__ float g_dbl[ (size_t)MM * 96 ];        // dt_lo64 | B16 | C16  fp32
__device__ float g_dblp[ (size_t)4 * MM * 96 ];   // split-K partials
__device__ bf16  g_dt [ (size_t)MM * DI ];        // bf16 now
__device__ bf16  g_xnb [ (size_t)MM * DM ];
__device__ bf16  g_xcb [ (size_t)MM * DI ];
__device__ bf16  g_dtlo[ (size_t)MM * DTR ];
__device__ bf16  g_yb  [ (size_t)MM * DI ];
__device__ bf16  g_Winb [ (size_t)(2*DI) * DM ];
__device__ bf16  g_Wxpb [ (size_t)96 * DI ];
__device__ bf16  g_Wdtb [ (size_t)DI * DTR ];
__device__ bf16  g_Woutb[ (size_t)DM * DI ];
// scan chunk buffers, layout idx(b,ch,s,d) = ((b*NCH+ch)*DS+s)*DI + d
__device__ float g_P [ (size_t)BB * NCH * DS * DI ];
__device__ float g_U [ (size_t)BB * NCH * DS * DI ];
__device__ float g_H [ (size_t)BB * NCH * DS * DI ];

#define LOG2E 1.4426950408889634f

// ======================= helpers ============================================
__device__ __forceinline__ void cp_async16(uint32_t saddr, const void* gptr) {
    asm volatile("cp.async.cg.shared.global [%0], [%1], 16;\n" :: "r"(saddr), "l"(gptr));
}
__device__ __forceinline__ void ldsm_x4(uint32_t* r, uint32_t addr) {
    asm volatile("ldmatrix.sync.aligned.m8n8.x4.shared.b16 {%0,%1,%2,%3}, [%4];"
        : "=r"(r[0]), "=r"(r[1]), "=r"(r[2]), "=r"(r[3]) : "r"(addr));
}
__device__ __forceinline__ void mma16816(float* d, const uint32_t* a, uint32_t b0, uint32_t b1) {
    asm volatile("mma.sync.aligned.m16n8k16.row.col.f32.bf16.bf16.f32 "
        "{%0,%1,%2,%3}, {%4,%5,%6,%7}, {%8,%9}, {%0,%1,%2,%3};"
        : "+f"(d[0]), "+f"(d[1]), "+f"(d[2]), "+f"(d[3])
        : "r"(a[0]), "r"(a[1]), "r"(a[2]), "r"(a[3]), "r"(b0), "r"(b1));
}
__device__ __forceinline__ float fast_softplus(float v) {
    return (v > 15.f) ? v : __logf(1.f + __expf(v));
}
// load 4 consecutive bf16 -> float4 (8B aligned)
__device__ __forceinline__ float4 ld_bf16x4(const bf16* p) {
    __nv_bfloat162 a = ((const __nv_bfloat162*)p)[0];
    __nv_bfloat162 b = ((const __nv_bfloat162*)p)[1];
    return make_float4(__low2float(a), __high2float(a), __low2float(b), __high2float(b));
}

// ======================= mma.sync GEMM (BK=64, 3-stage, 2 CTAs/SM) =========
//  C[M,N] = A[M,K] * W[N,K]^T   (bf16 in)
//  EPI: 1 fp32 out + residual aux[MxN];  2 bf16 out softplus(v+aux[col]);
//  EPI: 3 bf16 out plain.
template<int EPI>
__global__ __launch_bounds__(256, 2)
void mma_gemm_kernel(const bf16* __restrict__ A, int lda,
                     const bf16* __restrict__ W, int ldb,
                     void* __restrict__ Cv, int ldc,
                     int K, const float* __restrict__ aux)
{
    constexpr int BM = 128, BN = 128, BK = 64, SP = 72, NS = 3;
    constexpr int ASZ = BM * SP;
    constexpr int SSZ = (BM + BN) * SP;         // 18432 elems = 36864 B/stage

    extern __shared__ bf16 sm2[];
    const int tid  = threadIdx.x;
    const int lane = tid & 31;
    const int wid  = tid >> 5;
    const int wm   = wid >> 2;
    const int wn   = wid & 3;
    const int bm   = blockIdx.y * BM;
    const int bn   = blockIdx.x * BN;

    auto prefetch = [&](int s, int kt) {
        const int k0 = kt * BK;
        uint32_t base = (uint32_t)__cvta_generic_to_shared(sm2 + s * SSZ);
        #pragma unroll
        for (int i = 0; i < 4; i++) {
            int e = i * 256 + tid;
            int r = e >> 3, c = e & 7;
            cp_async16(base + (r * SP + c * 8) * 2,
                       A + (size_t)(bm + r) * lda + k0 + c * 8);
        }
        uint32_t baseB = base + ASZ * 2;
        #pragma unroll
        for (int i = 0; i < 4; i++) {
            int e = i * 256 + tid;
            int r = e >> 3, c = e & 7;
            cp_async16(baseB + (r * SP + c * 8) * 2,
                       W + (size_t)(bn + r) * ldb + k0 + c * 8);
        }
    };

    float acc[4][4][4];
    #pragma unroll
    for (int i = 0; i < 4; i++)
        #pragma unroll
        for (int j = 0; j < 4; j++)
            #pragma unroll
            for (int e = 0; e < 4; e++) acc[i][j][e] = 0.f;

    const int T = K / BK;
    #pragma unroll
    for (int s = 0; s < NS - 1; s++) {
        if (s < T) prefetch(s, s);
        asm volatile("cp.async.commit_group;\n");
    }

    for (int t = 0; t < T; t++) {
        int tn = t + NS - 1;
        if (tn < T) prefetch(tn % NS, tn);
        asm volatile("cp.async.commit_group;\n");
        asm volatile("cp.async.wait_group %0;\n" :: "n"(NS - 1));
        __syncthreads();

        uint32_t abase = (uint32_t)__cvta_generic_to_shared(sm2 + (t % NS) * SSZ);
        uint32_t bbase = abase + ASZ * 2;
        const int half = lane >> 4;
        #pragma unroll
        for (int k16 = 0; k16 < 4; k16++) {
            uint32_t af[4][4], bfr[2][4];
            #pragma unroll
            for (int i = 0; i < 4; i++) {
                int row = wm * 64 + i * 16 + (lane & 15);
                ldsm_x4(af[i], abase + (row * SP + (k16 * 2 + half) * 8) * 2);
            }
            #pragma unroll
            for (int jp = 0; jp < 2; jp++) {
                int row = wn * 32 + jp * 16 + (lane & 15);
                ldsm_x4(bfr[jp], bbase + (row * SP + (k16 * 2 + half) * 8) * 2);
            }
            #pragma unroll
            for (int i = 0; i < 4; i++)
                #pragma unroll
                for (int jp = 0; jp < 2; jp++) {
                    mma16816(acc[i][2*jp],   af[i], bfr[jp][0], bfr[jp][2]);
                    mma16816(acc[i][2*jp+1], af[i], bfr[jp][1], bfr[jp][3]);
                }
        }
        __syncthreads();
    }

    const int r0 = bm + wm * 64 + (lane >> 2);
    const int c0 = bn + wn * 32 + (lane & 3) * 2;
    #pragma unroll
    for (int i = 0; i < 4; i++) {
        #pragma unroll
        for (int j = 0; j < 4; j++) {
            int r = r0 + i * 16;
            int c = c0 + j * 8;
            float v0 = acc[i][j][0], v1 = acc[i][j][1];
            float v2 = acc[i][j][2], v3 = acc[i][j][3];
            if (EPI == 1) {
                float* C = (float*)Cv;
                const float2 a0 = *(const float2*)(aux + (size_t)r * ldc + c);
                const float2 a1 = *(const float2*)(aux + (size_t)(r+8) * ldc + c);
                v0 += a0.x; v1 += a0.y; v2 += a1.x; v3 += a1.y;
                *(float2*)(C + (size_t)r * ldc + c)     = make_float2(v0, v1);
                *(float2*)(C + (size_t)(r+8) * ldc + c) = make_float2(v2, v3);
            } else if (EPI == 2) {
                bf16* C = (bf16*)Cv;
                float b0 = aux[c], b1 = aux[c+1];
                v0 = fast_softplus(v0 + b0);
                v1 = fast_softplus(v1 + b1);
                v2 = fast_softplus(v2 + b0);
                v3 = fast_softplus(v3 + b1);
                *(__nv_bfloat162*)(C + (size_t)r * ldc + c)     = __floats2bfloat162_rn(v0, v1);
                *(__nv_bfloat162*)(C + (size_t)(r+8) * ldc + c) = __floats2bfloat162_rn(v2, v3);
            } else {
                bf16* C = (bf16*)Cv;
                *(__nv_bfloat162*)(C + (size_t)r * ldc + c)     = __floats2bfloat162_rn(v0, v1);
                *(__nv_bfloat162*)(C + (size_t)(r+8) * ldc + c) = __floats2bfloat162_rn(v2, v3);
            }
        }
    }
}

// ---------------- fp32 -> bf16 converts ------------------------------------
__global__ void f2bf_kernel(const float* __restrict__ src, bf16* __restrict__ dst, int n)
{
    int i = (blockIdx.x * 256 + threadIdx.x) * 4;
    if (i < n) {
        float4 v = *(const float4*)(src + i);
        __nv_bfloat162* d = (__nv_bfloat162*)(dst + i);
        d[0] = __floats2bfloat162_rn(v.x, v.y);
        d[1] = __floats2bfloat162_rn(v.z, v.w);
    }
}

__global__ void f2bf3_kernel(const float* __restrict__ s0, bf16* __restrict__ d0, int n0,
                             const float* __restrict__ s1, bf16* __restrict__ d1, int n1,
                             const float* __restrict__ s2, bf16* __restrict__ d2, int n2)
{
    int i = (blockIdx.x * 256 + threadIdx.x) * 4;
    const float* s; bf16* d; int off;
    if (i < n0)                { s = s0; d = d0; off = i; }
    else if (i < n0 + n1)      { s = s1; d = d1; off = i - n0; }
    else if (i < n0 + n1 + n2) { s = s2; d = d2; off = i - n0 - n1; }
    else return;
    float4 v = *(const float4*)(s + off);
    __nv_bfloat162* dd = (__nv_bfloat162*)(d + off);
    dd[0] = __floats2bfloat162_rn(v.x, v.y);
    dd[1] = __floats2bfloat162_rn(v.z, v.w);
}

// ---------------- layernorm -> bf16 ----------------------------------------
__global__ void layernorm_kernel(const float* __restrict__ x,
                                 const float* __restrict__ g,
                                 const float* __restrict__ b,
                                 bf16* __restrict__ o)
{
    __shared__ float red[64];
    int row = blockIdx.x;
    int t = threadIdx.x;
    const float4* xr = (const float4*)(x + (size_t)row * DM);
    float4 v = xr[t];
    float s = v.x + v.y + v.z + v.w;
    float q = v.x*v.x + v.y*v.y + v.z*v.z + v.w*v.w;
    #pragma unroll
    for (int off = 16; off; off >>= 1) {
        s += __shfl_xor_sync(0xffffffffu, s, off);
        q += __shfl_xor_sync(0xffffffffu, q, off);
    }
    if ((t & 31) == 0) { red[t >> 5] = s; red[32 + (t >> 5)] = q; }
    __syncthreads();
    if (t < 32) {
        float s2 = (t < 8) ? red[t]      : 0.f;
        float q2 = (t < 8) ? red[32 + t] : 0.f;
        #pragma unroll
        for (int off = 4; off; off >>= 1) {
            s2 += __shfl_xor_sync(0xffffffffu, s2, off);
            q2 += __shfl_xor_sync(0xffffffffu, q2, off);
        }
        if (t == 0) { red[0] = s2; red[1] = q2; }
    }
    __syncthreads();
    float mu  = red[0] * (1.f / DM);
    float var = red[1] * (1.f / DM) - mu * mu;
    float inv = rsqrtf(var + 1e-5f);
    float4 gv = ((const float4*)g)[t];
    float4 bv = ((const float4*)b)[t];
    __nv_bfloat162* op = (__nv_bfloat162*)(o + (size_t)row * DM + t * 4);
    op[0] = __floats2bfloat162_rn((v.x - mu)*inv*gv.x + bv.x, (v.y - mu)*inv*gv.y + bv.y);
    op[1] = __floats2bfloat162_rn((v.z - mu)*inv*gv.z + bv.z, (v.w - mu)*inv*gv.w + bv.w);
}

// ---------------- bf16 wmma GEMM (W_xp, split-K via blockIdx.z) ------------
#define STAGES 3
#define SPAD   40

template<int BM, int BN, int WGM, int WGN>
__global__ __launch_bounds__(WGM*WGN*32)
void hgemm_kernel(const bf16* __restrict__ A, int lda,
                  const bf16* __restrict__ W, int ldb,
                  float* __restrict__ C, int ldc,
                  int N, int K,
                  int zk_off, size_t zc_off)
{
    constexpr int TM = BM / WGM;
    constexpr int TN = BN / WGN;
    constexpr int MF = TM / 16;
    constexpr int NF = TN / 16;
    constexpr int NT = WGM * WGN * 32;
    constexpr int SSZ = (BM + BN) * SPAD;

    extern __shared__ bf16 smh[];

    A += (size_t)blockIdx.z * zk_off;
    W += (size_t)blockIdx.z * zk_off;
    C += (size_t)blockIdx.z * zc_off;

    int tid = threadIdx.x;
    int wid = tid >> 5;
    int wm  = wid / WGN;
    int wn  = wid % WGN;
    int bm  = blockIdx.y * BM;
    int bn  = blockIdx.x * BN;

    auto prefetch = [&](int p, int k0) {
        uint32_t sbase = (uint32_t)__cvta_generic_to_shared(smh + p * SSZ);
        #pragma unroll
        for (int i = 0; i < (BM * 4) / NT; i++) {
            int e = i * NT + tid;
            int row = e >> 2, c8 = (e & 3) * 8;
            cp_async16(sbase + (row * SPAD + c8) * 2,
                       A + (size_t)(bm + row) * lda + k0 + c8);
        }
        uint32_t sbase2 = sbase + BM * SPAD * 2;
        #pragma unroll
        for (int i = 0; i < (BN * 4) / NT; i++) {
            int e = i * NT + tid;
            int row = e >> 2, c8 = (e & 3) * 8;
            int n = bn + row; if (n >= N) n = N - 1;
            cp_async16(sbase2 + (row * SPAD + c8) * 2,
                       W + (size_t)n * ldb + k0 + c8);
        }
    };

    wmma::fragment<wmma::accumulator, 16, 16, 16, float> acc[MF][NF];
    #pragma unroll
    for (int i = 0; i < MF; i++)
        #pragma unroll
        for (int j = 0; j < NF; j++) wmma::fill_fragment(acc[i][j], 0.f);

    int T = K / 32;
    #pragma unroll
    for (int s = 0; s < STAGES - 1; s++) {
        if (s < T) prefetch(s, s * 32);
        asm volatile("cp.async.commit_group;\n");
    }

    for (int t = 0; t < T; t++) {
        asm volatile("cp.async.wait_group %0;\n" :: "n"(STAGES - 2));
        __syncthreads();

        int pn = t + STAGES - 1;
        if (pn < T) prefetch(pn % STAGES, pn * 32);
        asm volatile("cp.async.commit_group;\n");

        const bf16* As = smh + (t % STAGES) * SSZ;
        const bf16* Ws = As + BM * SPAD;
        #pragma unroll
        for (int ks = 0; ks < 32; ks += 16) {
            wmma::fragment<wmma::matrix_a, 16, 16, 16, bf16, wmma::row_major> af[MF];
            wmma::fragment<wmma::matrix_b, 16, 16, 16, bf16, wmma::col_major> bff[NF];
            #pragma unroll
            for (int i = 0; i < MF; i++)
                wmma::load_matrix_sync(af[i], As + (wm * TM + i * 16) * SPAD + ks, SPAD);
            #pragma unroll
            for (int j = 0; j < NF; j++)
                wmma::load_matrix_sync(bff[j], Ws + (wn * TN + j * 16) * SPAD + ks, SPAD);
            #pragma unroll
            for (int i = 0; i < MF; i++)
                #pragma unroll
                for (int j = 0; j < NF; j++)
                    wmma::mma_sync(acc[i][j], af[i], bff[j], acc[i][j]);
        }
        __syncthreads();
    }

    #pragma unroll
    for (int i = 0; i < MF; i++) {
        int r0 = bm + wm * TM + i * 16;
        #pragma unroll
        for (int j = 0; j < NF; j++) {
            int c0 = bn + wn * TN + j * 16;
            if (c0 < N) {
                wmma::store_matrix_sync(C + (size_t)r0 * ldc + c0, acc[i][j], ldc, wmma::mem_row_major);
            }
        }
    }
}

// ---------------- split-K reduce + dtlo extraction -------------------------
__global__ void dbl_reduce_kernel(const float* __restrict__ dblp,
                                  float* __restrict__ dbl,
                                  bf16* __restrict__ dtlo)
{
    int idx = blockIdx.x * 256 + threadIdx.x;   // over MM*96
    const size_t STR = (size_t)MM * 96;
    float v = dblp[idx] + dblp[idx + STR] + dblp[idx + 2*STR] + dblp[idx + 3*STR];
    dbl[idx] = v;
    int m = idx / 96, c = idx - m * 96;
    if (c < DTR) dtlo[m * DTR + c] = __float2bfloat16(v);
}

// ---------------- causal depthwise conv (DC=4) + silu, 4 channels/thread ---
__global__ void conv_silu_kernel(const bf16* __restrict__ xz,
                                 const float* __restrict__ cw,
                                 const float* __restrict__ cb,
                                 bf16* __restrict__ xcb)
{
    int idx = blockIdx.x * 256 + threadIdx.x;      // over M*DI/4
    int dq = idx & (DI/4 - 1);
    int m  = idx >> 9;
    int l  = m & (LL - 1);
    int d  = dq * 4;
    const bf16* p = xz + (size_t)m * (2*DI) + d;
    float4 w0 = *(const float4*)(cw + (d+0) * 4);
    float4 w1 = *(const float4*)(cw + (d+1) * 4);
    float4 w2 = *(const float4*)(cw + (d+2) * 4);
    float4 w3 = *(const float4*)(cw + (d+3) * 4);
    float4 bias = *(const float4*)(cb + d);
    float4 v = ld_bf16x4(p);
    float a0 = fmaf(w0.w, v.x, bias.x);
    float a1 = fmaf(w1.w, v.y, bias.y);
    float a2 = fmaf(w2.w, v.z, bias.z);
    float a3 = fmaf(w3.w, v.w, bias.w);
    if (l >= 1) { float4 u = ld_bf16x4(p - 2*DI);
        a0 = fmaf(w0.z, u.x, a0); a1 = fmaf(w1.z, u.y, a1);
        a2 = fmaf(w2.z, u.z, a2); a3 = fmaf(w3.z, u.w, a3); }
    if (l >= 2) { float4 u = ld_bf16x4(p - 4*DI);
        a0 = fmaf(w0.y, u.x, a0); a1 = fmaf(w1.y, u.y, a1);
        a2 = fmaf(w2.y, u.z, a2); a3 = fmaf(w3.y, u.w, a3); }
    if (l >= 3) { float4 u = ld_bf16x4(p - 6*DI);
        a0 = fmaf(w0.x, u.x, a0); a1 = fmaf(w1.x, u.y, a1);
        a2 = fmaf(w2.x, u.z, a2); a3 = fmaf(w3.x, u.w, a3); }
    float r0 = a0 / (1.f + __expf(-a0));
    float r1 = a1 / (1.f + __expf(-a1));
    float r2 = a2 / (1.f + __expf(-a2));
    float r3 = a3 / (1.f + __expf(-a3));
    __nv_bfloat162* ob = (__nv_bfloat162*)(xcb + (size_t)m * DI + d);
    ob[0] = __floats2bfloat162_rn(r0, r1);
    ob[1] = __floats2bfloat162_rn(r2, r3);
}

// =============== chunked selective scan (16 states per thread) ==============
__global__ __launch_bounds__(256)
void scan_p1_kernel(const bf16* __restrict__ dt,
                    const bf16* __restrict__ xc,
                    const float* __restrict__ dbl,
                    const float* __restrict__ A_log,
                    float* __restrict__ P, float* __restrict__ U)
{
    int gid = blockIdx.x * 256 + threadIdx.x;   // BB*NCH*DI = 131072
    int d  = gid & (DI - 1);
    int ch = (gid >> 11) & (NCH - 1);
    int b  = gid >> 16;

    float A2[DS], Pv[DS], Uv[DS];
    #pragma unroll
    for (int s = 0; s < DS; s++) {
        A2[s] = -__expf(A_log[d * DS + s]) * LOG2E;
        Pv[s] = 1.f; Uv[s] = 0.f;
    }
    bool fastp = true;
    #pragma unroll
    for (int s = 0; s < DS; s++)
        fastp = fastp && (fabsf(A2[s] - (float)(s + 1) * A2[0]) <= 1e-4f * fabsf(A2[s]));

    size_t mbase = (size_t)b * LL + ch * CH;
    if (fastp) {
        float A20 = A2[0];
        for (int l = 0; l < CH; l++) {
            size_t m = mbase + l;
            float dtv = __bfloat162float(dt[m * DI + d]);
            float xv  = __bfloat162float(xc[m * DI + d]);
            float dx  = dtv * xv;
            const float4* Bp = (const float4*)(dbl + m * 96 + DTR);
            float4 B0 = Bp[0], B1 = Bp[1], B2 = Bp[2], B3 = Bp[3];
            float Bv[DS] = {B0.x,B0.y,B0.z,B0.w, B1.x,B1.y,B1.z,B1.w,
                            B2.x,B2.y,B2.z,B2.w, B3.x,B3.y,B3.z,B3.w};
            float a1 = exp2f(dtv * A20);
            float as = a1;
            #pragma unroll
            for (int s = 0; s < DS; s++) {
                Pv[s] *= as;
                Uv[s] = fmaf(as, Uv[s], dx * Bv[s]);
                as *= a1;
            }
        }
    } else {
        for (int l = 0; l < CH; l++) {
            size_t m = mbase + l;
            float dtv = __bfloat162float(dt[m * DI + d]);
            float xv  = __bfloat162float(xc[m * DI + d]);
            float dx  = dtv * xv;
            const float4* Bp = (const float4*)(dbl + m * 96 + DTR);
            float4 B0 = Bp[0], B1 = Bp[1], B2 = Bp[2], B3 = Bp[3];
            float Bv[DS] = {B0.x,B0.y,B0.z,B0.w, B1.x,B1.y,B1.z,B1.w,
                            B2.x,B2.y,B2.z,B2.w, B3.x,B3.y,B3.z,B3.w};
            #pragma unroll
            for (int s = 0; s < DS; s++) {
                float a = exp2f(dtv * A2[s]);
                Pv[s] *= a;
                Uv[s] = fmaf(a, Uv[s], dx * Bv[s]);
            }
        }
    }
    size_t base = ((size_t)(b * NCH + ch) * DS) * DI + d;
    #pragma unroll
    for (int s = 0; s < DS; s++) {
        P[base + (size_t)s * DI] = Pv[s];
        U[base + (size_t)s * DI] = Uv[s];
    }
}

__global__ void scan_p2_kernel(const float* __restrict__ P,
                               const float* __restrict__ U,
                               float* __restrict__ H)
{
    int gid = blockIdx.x * 256 + threadIdx.x;   // BB*DS*DI = 65536
    int d = gid & (DI - 1);
    int s = (gid >> 11) & (DS - 1);
    int b = gid >> 15;
    float h = 0.f;
    #pragma unroll
    for (int ch = 0; ch < NCH; ch++) {
        size_t idx = ((size_t)((b * NCH + ch) * DS + s)) * DI + d;
        H[idx] = h;
        h = fmaf(P[idx], h, U[idx]);
    }
}

__global__ __launch_bounds__(256)
void scan_p3_kernel(const bf16* __restrict__ dt,
                    const bf16* __restrict__ xc,
                    const float* __restrict__ dbl,
                    const bf16* __restrict__ xz,
                    const float* __restrict__ A_log,
                    const float* __restrict__ Dp,
                    const float* __restrict__ H,
                    bf16* __restrict__ y)
{
    int gid = blockIdx.x * 256 + threadIdx.x;   // 131072
    int d  = gid & (DI - 1);
    int ch = (gid >> 11) & (NCH - 1);
    int b  = gid >> 16;

    float A2[DS], h[DS];
    size_t hbase = ((size_t)(b * NCH + ch) * DS) * DI + d;
    #pragma unroll
    for (int s = 0; s < DS; s++) {
        A2[s] = -__expf(A_log[d * DS + s]) * LOG2E;
        h[s] = H[hbase + (size_t)s * DI];
    }
    bool fastp = true;
    #pragma unroll
    for (int s = 0; s < DS; s++)
        fastp = fastp && (fabsf(A2[s] - (float)(s + 1) * A2[0]) <= 1e-4f * fabsf(A2[s]));

    float D_d = Dp[d];
    size_t mbase = (size_t)b * LL + ch * CH;
    if (fastp) {
        float A20 = A2[0];
        for (int l = 0; l < CH; l++) {
            size_t m = mbase + l;
            float dtv = __bfloat162float(dt[m * DI + d]);
            float xv  = __bfloat162float(xc[m * DI + d]);
            float dx  = dtv * xv;
            const float4* Bp = (const float4*)(dbl + m * 96 + DTR);
            float4 B0 = Bp[0], B1 = Bp[1], B2 = Bp[2], B3 = Bp[3];
            const float4* Cp = (const float4*)(dbl + m * 96 + DTR + DS);
            float4 C0 = Cp[0], C1 = Cp[1], C2 = Cp[2], C3 = Cp[3];
            float Bv[DS] = {B0.x,B0.y,B0.z,B0.w, B1.x,B1.y,B1.z,B1.w,
                            B2.x,B2.y,B2.z,B2.w, B3.x,B3.y,B3.z,B3.w};
            float Cv[DS] = {C0.x,C0.y,C0.z,C0.w, C1.x,C1.y,C1.z,C1.w,
                            C2.x,C2.y,C2.z,C2.w, C3.x,C3.y,C3.z,C3.w};
            float a1 = exp2f(dtv * A20);
            float as = a1;
            float acc = 0.f;
            #pragma unroll
            for (int s = 0; s < DS; s++) {
                h[s] = fmaf(as, h[s], dx * Bv[s]);
                acc = fmaf(h[s], Cv[s], acc);
                as *= a1;
            }
            float zv = __bfloat162float(xz[m * (2*DI) + DI + d]);
            float yy = fmaf(xv, D_d, acc);
            y[m * DI + d] = __float2bfloat16(yy * (zv / (1.f + __expf(-zv))));
        }
    } else {
        for (int l = 0; l < CH; l++) {
            size_t m = mbase + l;
            float dtv = __bfloat162float(dt[m * DI + d]);
            float xv  = __bfloat162float(xc[m * DI + d]);
            float dx  = dtv * xv;
            const float4* Bp = (const float4*)(dbl + m * 96 + DTR);
            float4 B0 = Bp[0], B1 = Bp[1], B2 = Bp[2], B3 = Bp[3];
            const float4* Cp = (const float4*)(dbl + m * 96 + DTR + DS);
            float4 C0 = Cp[0], C1 = Cp[1], C2 = Cp[2], C3 = Cp[3];
            float Bv[DS] = {B0.x,B0.y,B0.z,B0.w, B1.x,B1.y,B1.z,B1.w,
                            B2.x,B2.y,B2.z,B2.w, B3.x,B3.y,B3.z,B3.w};
            float Cv[DS] = {C0.x,C0.y,C0.z,C0.w, C1.x,C1.y,C1.z,C1.w,
                            C2.x,C2.y,C2.z,C2.w, C3.x,C3.y,C3.z,C3.w};
            float acc = 0.f;
            #pragma unroll
            for (int s = 0; s < DS; s++) {
                float a = exp2f(dtv * A2[s]);
                h[s] = fmaf(a, h[s], dx * Bv[s]);
                acc = fmaf(h[s], Cv[s], acc);
            }
            float zv = __bfloat162float(xz[m * (2*DI) + DI + d]);
            float yy = fmaf(xv, D_d, acc);
            y[m * DI + d] = __float2bfloat16(yy * (zv / (1.f + __expf(-zv))));
        }
    }
}

// ---------------- launcher -------------------------------------------------
extern "C" void kernel_launch(void* const* d_in, const int* in_sizes, int n_in,
                              void* d_out, int out_size)
{
    const float* x      = (const float*)d_in[0];
    const float* ln_g   = (const float*)d_in[1];
    const float* ln_b   = (const float*)d_in[2];
    const float* W_in   = (const float*)d_in[3];
    const float* conv_w = (const float*)d_in[4];
    const float* conv_b = (const float*)d_in[5];
    const float* W_xp   = (const float*)d_in[6];
    const float* W_dt   = (const float*)d_in[7];
    const float* b_dt   = (const float*)d_in[8];
    const float* A_log  = (const float*)d_in[9];
    const float* Dp     = (const float*)d_in[10];
    const float* W_out  = (const float*)d_in[11];
    float* out = (float*)d_out;

    float *dbl, *dblp, *Pb, *Ub, *Hb;
    bf16 *xz, *dtb, *xnb, *xcb, *dtlo, *yb, *Winb, *Wxpb, *Wdtb, *Woutb;
    cudaGetSymbolAddress((void**)&xz,   g_xz);
    cudaGetSymbolAddress((void**)&dbl,  g_dbl);
    cudaGetSymbolAddress((void**)&dblp, g_dblp);
    cudaGetSymbolAddress((void**)&dtb,  g_dt);
    cudaGetSymbolAddress((void**)&xnb,  g_xnb);
    cudaGetSymbolAddress((void**)&xcb,  g_xcb);
    cudaGetSymbolAddress((void**)&dtlo, g_dtlo);
    cudaGetSymbolAddress((void**)&yb,   g_yb);
    cudaGetSymbolAddress((void**)&Winb, g_Winb);
    cudaGetSymbolAddress((void**)&Wxpb, g_Wxpb);
    cudaGetSymbolAddress((void**)&Wdtb, g_Wdtb);
    cudaGetSymbolAddress((void**)&Woutb,g_Woutb);
    cudaGetSymbolAddress((void**)&Pb,   g_P);
    cudaGetSymbolAddress((void**)&Ub,   g_U);
    cudaGetSymbolAddress((void**)&Hb,   g_H);

    constexpr int SM_MMA = 3 * (128 + 128) * 72 * 2;          // 110592 (108 KB)
    constexpr int SM_64  = (64 + 128) * SPAD * 2 * STAGES;    // 46080
    cudaFuncSetAttribute(mma_gemm_kernel<1>, cudaFuncAttributeMaxDynamicSharedMemorySize, SM_MMA);
    cudaFuncSetAttribute(mma_gemm_kernel<2>, cudaFuncAttributeMaxDynamicSharedMemorySize, SM_MMA);
    cudaFuncSetAttribute(mma_gemm_kernel<3>, cudaFuncAttributeMaxDynamicSharedMemorySize, SM_MMA);
    cudaFuncSetAttribute(hgemm_kernel<64,128,2,4>, cudaFuncAttributeMaxDynamicSharedMemorySize, SM_64);

    const int nWxp = 96*DI, nWdt = DI*DTR, nWout = DM*DI;

    // 1. W_in -> bf16
    f2bf_kernel<<<((2*DI*DM)/4 + 255)/256, 256>>>(W_in,  Winb, 2*DI*DM);
    // 2. LayerNorm -> bf16
    layernorm_kernel<<<MM, 256>>>(x, ln_g, ln_b, xnb);
    // 3. W_xp + W_dt + W_out -> bf16 (one launch)
    f2bf3_kernel<<<(((nWxp+nWdt+nWout)/4) + 255)/256, 256>>>(
        W_xp, Wxpb, nWxp, W_dt, Wdtb, nWdt, W_out, Woutb, nWout);
    // 4. xz = xn @ W_in^T -> bf16  [8192 x 4096], K=1024   <-- PROFILED (#4)
    mma_gemm_kernel<3><<<dim3(4096/128, MM/128), 256, SM_MMA>>>(
        xnb, DM, Winb, DM, xz, 2*DI, DM, nullptr);
    // 5. causal conv + silu -> xcb (bf16 in/out)
    conv_silu_kernel<<<(MM*DI/4)/256, 256>>>(xz, conv_w, conv_b, xcb);
    // 6. dbl partials = xc @ W_xp^T, split-K x4
    hgemm_kernel<64,128,2,4><<<dim3(1, MM/64, 4), 256, SM_64>>>(
        xcb, DI, Wxpb, DI, dblp, 96, 96, DI/4, DI/4, (size_t)MM*96);
    // 7. reduce partials -> dbl fp32 + dtlo bf16
    dbl_reduce_kernel<<<(MM*96)/256, 256>>>(dblp, dbl, dtlo);
    // 8. dt = softplus(dt_lo @ W_dt^T + b_dt) -> bf16
    mma_gemm_kernel<2><<<dim3(DI/128, MM/128), 256, SM_MMA>>>(
        dtlo, DTR, Wdtb, DTR, dtb, DI, DTR, b_dt);
    // 9-11. chunked selective scan
    scan_p1_kernel<<<(BB*NCH*DI)/256, 256>>>(dtb, xcb, dbl, A_log, Pb, Ub);
    scan_p2_kernel<<<(BB*DS*DI)/256, 256>>>(Pb, Ub, Hb);
    scan_p3_kernel<<<(BB*NCH*DI)/256, 256>>>(dtb, xcb, dbl, xz, A_log, Dp, Hb, yb);
    // 12. out = x + y @ W_out^T  [8192 x 1024], K=2048
    mma_gemm_kernel<1><<<dim3(DM/128, MM/128), 256, SM_MMA>>>(
        yb, DI, Woutb, DI, out, DM, DI, x);
}